// round 1
// baseline (speedup 1.0000x reference)
#include <cuda_runtime.h>
#include <math.h>

#define T_  64
#define B_  256
#define D_  512
#define H_  512
#define NQ_ 8
#define NS  256   // 2^NQ

// scratch (allocation-free rule: device globals)
__device__ float g_H1[B_ * 4 * H_];   // relu(z@pW1+pb1), row = b*4+gate
__device__ float g_h[B_ * H_];
__device__ float g_c[B_ * H_];

__global__ void zero_state_kernel() {
    int i = blockIdx.x * blockDim.x + threadIdx.x;
    if (i < B_ * H_) { g_h[i] = 0.f; g_c[i] = 0.f; }
}

// One block per (batch, gate): angles -> 8-qubit statevector sim -> measure -> pW1+relu
__global__ __launch_bounds__(256) void quantum_kernel(
    const float* __restrict__ xt,                                   // inputs + t*B*D
    const float* __restrict__ Wf, const float* __restrict__ Wi,
    const float* __restrict__ Wu, const float* __restrict__ Wo,
    const float* __restrict__ bf, const float* __restrict__ bi,
    const float* __restrict__ bu, const float* __restrict__ bo,
    const float* __restrict__ qpf, const float* __restrict__ qpi,
    const float* __restrict__ qpu, const float* __restrict__ qpo,
    const float* __restrict__ pW1, const float* __restrict__ pb1)
{
    int b = blockIdx.x, g = blockIdx.y;
    int tid = threadIdx.x, warp = tid >> 5, lane = tid & 31;

    const float* W  = (g == 0) ? Wf  : (g == 1) ? Wi  : (g == 2) ? Wu  : Wo;
    const float* bs = (g == 0) ? bf  : (g == 1) ? bi  : (g == 2) ? bu  : bo;
    const float* qp = (g == 0) ? qpf : (g == 1) ? qpi : (g == 2) ? qpu : qpo;

    __shared__ float sre[NS], sim_[NS];
    __shared__ float ang[8];
    __shared__ float csx[8], ssx[8];     // RX cos/sin (input angles)
    __shared__ float cqp[32], sqp[32];   // RY/RZ cos/sin per (layer,qubit,type)
    __shared__ float zsh[8];

    // ---- gate angles: warp w computes theta_w = comb . W[:,w] + b[w] ----
    {
        const float* xrow = xt + b * D_;
        const float* hrow = g_h + b * H_;
        float acc = 0.f;
        for (int k = lane; k < D_; k += 32) acc += xrow[k] * W[k * NQ_ + warp];
        for (int k = lane; k < H_; k += 32) acc += hrow[k] * W[(D_ + k) * NQ_ + warp];
        #pragma unroll
        for (int o = 16; o; o >>= 1) acc += __shfl_xor_sync(0xffffffffu, acc, o);
        if (lane == 0) ang[warp] = acc + bs[warp];
    }
    __syncthreads();

    if (tid < 8) {
        float a = ang[tid] * 0.5f;
        csx[tid] = cosf(a); ssx[tid] = sinf(a);
    } else if (tid < 40) {
        int ii = tid - 8;             // 0..31
        int l = ii >> 4, r = ii & 15, q = r >> 1, ty = r & 1;
        float a = qp[l * NQ_ * 3 + q * 3 + ty] * 0.5f;
        cqp[ii] = cosf(a); sqp[ii] = sinf(a);
    }

    // statevector: one amplitude per thread, |0...0> init
    float re = (tid == 0) ? 1.f : 0.f;
    float im = 0.f;
    __syncthreads();

    // ---- RX(theta_q, wire q), q=0..7.  wire q <-> bit (7-q), stride 1<<(7-q) ----
    // Both halves: s' = c*s_own + s*Im(partner) - i*s*Re(partner)
    #pragma unroll
    for (int q = 0; q < 8; q++) {
        int str = 1 << (7 - q);
        sre[tid] = re; sim_[tid] = im;
        __syncthreads();
        int j = tid ^ str;
        float rb = sre[j], ib = sim_[j];
        float c = csx[q], s = ssx[q];
        re = c * re + s * ib;
        im = c * im - s * rb;
        __syncthreads();
    }

    // ---- 2 layers of (RY,RZ) per qubit then CNOT chain ----
    #pragma unroll
    for (int l = 0; l < 2; l++) {
        #pragma unroll
        for (int q = 0; q < 8; q++) {
            int str = 1 << (7 - q);
            float cy = cqp[l * 16 + q * 2 + 0], sy = sqp[l * 16 + q * 2 + 0];
            float cz = cqp[l * 16 + q * 2 + 1], sz = sqp[l * 16 + q * 2 + 1];
            sre[tid] = re; sim_[tid] = im;
            __syncthreads();
            int j = tid ^ str;
            float rb = sre[j], ib = sim_[j];
            bool hi = (tid & str) != 0;
            // RY: s0' = c*s0 - s*s1 ; s1' = s*s0 + c*s1  (real coeffs)
            float sgn = hi ? sy : -sy;
            re = cy * re + sgn * rb;
            im = cy * im + sgn * ib;
            // RZ (diagonal, fused): s0' = (c - i s)*s0 ; s1' = (c + i s)*s1
            float zn = hi ? sz : -sz;
            float nr = cz * re - zn * im;
            float ni = cz * im + zn * re;
            re = nr; im = ni;
            __syncthreads();
        }
        #pragma unroll
        for (int ctrl = 0; ctrl < 7; ctrl++) {
            int cs = 1 << (7 - ctrl);   // control bit stride
            int ts = 1 << (6 - ctrl);   // target bit stride
            sre[tid] = re; sim_[tid] = im;
            __syncthreads();
            if (tid & cs) { int j = tid ^ ts; re = sre[j]; im = sim_[j]; }
            __syncthreads();
        }
    }

    // ---- measure Z on each qubit: z_q = sum prob_i * (bit(7-q)(i) ? -1 : +1) ----
    sre[tid] = re * re + im * im;
    __syncthreads();
    {
        int bitpos = 7 - warp;      // warp w handles qubit w
        float zacc = 0.f;
        for (int k = lane; k < NS; k += 32) {
            float p = sre[k];
            zacc += ((k >> bitpos) & 1) ? -p : p;
        }
        #pragma unroll
        for (int o = 16; o; o >>= 1) zacc += __shfl_xor_sync(0xffffffffu, zacc, o);
        if (lane == 0) zsh[warp] = zacc;
    }
    __syncthreads();

    // ---- H1 = relu(z @ pW1 + pb1) ----
    int row = b * 4 + g;
    for (int h = tid; h < H_; h += 256) {
        float a2 = pb1[h];
        #pragma unroll
        for (int q = 0; q < 8; q++) a2 += zsh[q] * pW1[q * H_ + h];
        g_H1[row * H_ + h] = fmaxf(a2, 0.f);
    }
}

__device__ __forceinline__ float sigmoidf_(float x) { return 1.f / (1.f + expf(-x)); }

// preact(B*4,512) = H1 @ pW2 + pb2, fused LSTM epilogue.
// Tile 64x64, BK=16, 256 threads, each thread 4x4 where the 4 M-rows are the
// 4 gates (f,i,u,o) of a single batch row (rows ordered r = b*4 + gate).
__global__ __launch_bounds__(256) void gemm_lstm_kernel(
    const float* __restrict__ pW2, const float* __restrict__ pb2,
    float* __restrict__ out_t,                   // d_out + t*B*H
    float* __restrict__ out_h, float* __restrict__ out_c)  // non-null only on last step
{
    __shared__ float As[16][68];
    __shared__ float Bs[16][64];

    int tid = threadIdx.x;
    int bx = blockIdx.x;            // n tile 0..7
    int by = blockIdx.y;            // m tile 0..15
    int ty = tid >> 4, tx = tid & 15;

    float acc[4][4];
    #pragma unroll
    for (int i = 0; i < 4; i++)
        #pragma unroll
        for (int j = 0; j < 4; j++) acc[i][j] = 0.f;

    int mbase = by * 64;
    int nbase = bx * 64;
    int ar = tid >> 2, ak = (tid & 3) * 4;       // A-tile load coords
    int bk = tid >> 4, bc = (tid & 15) * 4;      // B-tile load coords
    const float* Aptr = g_H1 + (size_t)(mbase + ar) * H_ + ak;
    const float* Bptr = pW2 + (size_t)bk * H_ + nbase + bc;

    for (int kk = 0; kk < H_; kk += 16) {
        float4 av = *(const float4*)(Aptr + kk);
        float4 bv = *(const float4*)(Bptr + (size_t)kk * H_);
        As[ak + 0][ar] = av.x; As[ak + 1][ar] = av.y;
        As[ak + 2][ar] = av.z; As[ak + 3][ar] = av.w;
        *(float4*)&Bs[bk][bc] = bv;
        __syncthreads();
        #pragma unroll
        for (int k = 0; k < 16; k++) {
            float4 a  = *(const float4*)&As[k][ty * 4];
            float4 bb = *(const float4*)&Bs[k][tx * 4];
            acc[0][0] += a.x * bb.x; acc[0][1] += a.x * bb.y;
            acc[0][2] += a.x * bb.z; acc[0][3] += a.x * bb.w;
            acc[1][0] += a.y * bb.x; acc[1][1] += a.y * bb.y;
            acc[1][2] += a.y * bb.z; acc[1][3] += a.y * bb.w;
            acc[2][0] += a.z * bb.x; acc[2][1] += a.z * bb.y;
            acc[2][2] += a.z * bb.z; acc[2][3] += a.z * bb.w;
            acc[3][0] += a.w * bb.x; acc[3][1] += a.w * bb.y;
            acc[3][2] += a.w * bb.z; acc[3][3] += a.w * bb.w;
        }
        __syncthreads();
    }

    // epilogue: rows ty*4+{0,1,2,3} = gates f,i,u,o of batch (by*16+ty)
    int bidx = by * 16 + ty;
    int col0 = nbase + tx * 4;
    #pragma unroll
    for (int ni = 0; ni < 4; ni++) {
        int col = col0 + ni;
        float bias = pb2[col];
        float fv = sigmoidf_(acc[0][ni] + bias);
        float iv = sigmoidf_(acc[1][ni] + bias);
        float uv = tanhf   (acc[2][ni] + bias);
        float ov = sigmoidf_(acc[3][ni] + bias);
        int idx = bidx * H_ + col;
        float c = fv * g_c[idx] + iv * uv;
        float h = ov * tanhf(c);
        g_c[idx] = c;
        g_h[idx] = h;
        out_t[idx] = h;
        if (out_h) { out_h[idx] = h; out_c[idx] = c; }
    }
}

extern "C" void kernel_launch(void* const* d_in, const int* in_sizes, int n_in,
                              void* d_out, int out_size) {
    const float* inputs = (const float*)d_in[0];
    const float* qpf = (const float*)d_in[1];
    const float* qpi = (const float*)d_in[2];
    const float* qpu = (const float*)d_in[3];
    const float* qpo = (const float*)d_in[4];
    const float* Wf  = (const float*)d_in[5];
    const float* bf  = (const float*)d_in[6];
    const float* Wi  = (const float*)d_in[7];
    const float* bi  = (const float*)d_in[8];
    const float* Wu  = (const float*)d_in[9];
    const float* bu  = (const float*)d_in[10];
    const float* Wo  = (const float*)d_in[11];
    const float* bo  = (const float*)d_in[12];
    const float* pW1 = (const float*)d_in[13];
    const float* pb1 = (const float*)d_in[14];
    const float* pW2 = (const float*)d_in[15];
    const float* pb2 = (const float*)d_in[16];
    float* out = (float*)d_out;

    zero_state_kernel<<<(B_ * H_ + 255) / 256, 256>>>();

    for (int t = 0; t < T_; t++) {
        quantum_kernel<<<dim3(B_, 4), 256>>>(
            inputs + (size_t)t * B_ * D_,
            Wf, Wi, Wu, Wo, bf, bi, bu, bo,
            qpf, qpi, qpu, qpo, pW1, pb1);
        bool last = (t == T_ - 1);
        gemm_lstm_kernel<<<dim3(8, 16), 256>>>(
            pW2, pb2,
            out + (size_t)t * B_ * H_,
            last ? out + (size_t)T_ * B_ * H_            : nullptr,
            last ? out + (size_t)T_ * B_ * H_ + B_ * H_  : nullptr);
    }
}

// round 2
// speedup vs baseline: 1.1675x; 1.1675x over previous
#include <cuda_runtime.h>
#include <math.h>

#define T_  64
#define B_  256
#define D_  512
#define H_  512

// scratch (allocation-free rule: device globals)
__device__ float g_H1[B_ * 4 * H_];    // relu(z@pW1+pb1), row = b*4+gate
__device__ float g_h[B_ * H_];
__device__ float g_c[B_ * H_];
__device__ float g_Xproj[T_ * B_ * 32];        // x_t @ W + b, [t*B+b][g*8+q]
__device__ float g_trig[4 * 2 * 8 * 4];        // [g][l][q][{cy,sy,cz,sz}]

__global__ void init_kernel(const float* __restrict__ qpf, const float* __restrict__ qpi,
                            const float* __restrict__ qpu, const float* __restrict__ qpo) {
    int i = blockIdx.x * blockDim.x + threadIdx.x;
    if (i < B_ * H_) { g_h[i] = 0.f; g_c[i] = 0.f; }
    if (i < 4 * 2 * 8) {
        int g = i >> 4, r = i & 15, l = r >> 3, q = r & 7;
        const float* qp = (g == 0) ? qpf : (g == 1) ? qpi : (g == 2) ? qpu : qpo;
        float ty = qp[(l * 8 + q) * 3 + 0] * 0.5f;
        float tz = qp[(l * 8 + q) * 3 + 1] * 0.5f;
        g_trig[i * 4 + 0] = cosf(ty);
        g_trig[i * 4 + 1] = sinf(ty);
        g_trig[i * 4 + 2] = cosf(tz);
        g_trig[i * 4 + 3] = sinf(tz);
    }
}

// One-time: Xproj[row][g*8+q] = x[row] . W_g[:D, q] + b_g[q],  row = t*B+b
__global__ __launch_bounds__(256) void xproj_kernel(
    const float* __restrict__ inputs,
    const float* __restrict__ Wf, const float* __restrict__ Wi,
    const float* __restrict__ Wu, const float* __restrict__ Wo,
    const float* __restrict__ bf, const float* __restrict__ bi,
    const float* __restrict__ bu, const float* __restrict__ bo)
{
    int tid = blockIdx.x * 256 + threadIdx.x;
    int row = tid >> 5;
    int o = tid & 31, g = o >> 3, q = o & 7;
    const float* W  = (g == 0) ? Wf : (g == 1) ? Wi : (g == 2) ? Wu : Wo;
    const float* bb = (g == 0) ? bf : (g == 1) ? bi : (g == 2) ? bu : bo;
    const float* x = inputs + (size_t)row * D_;
    float acc = bb[q];
    #pragma unroll 8
    for (int k = 0; k < D_; k++) acc += x[k] * W[k * 8 + q];
    g_Xproj[row * 32 + o] = acc;
}

// Warp-per-statevector quantum sim. Block = 4 warps = 4 gates of one batch row.
// Amp index i (0..255): bits[7:3] = lane, bits[2:0] = r (register index).
// wire q <-> bit (7-q):  q=0..4 lane-bit (shfl), q=5..7 register-bit (local).
__global__ __launch_bounds__(128) void quantum_kernel(
    int t,
    const float* __restrict__ Wf, const float* __restrict__ Wi,
    const float* __restrict__ Wu, const float* __restrict__ Wo,
    const float* __restrict__ pW1, const float* __restrict__ pb1)
{
    const unsigned FULL = 0xffffffffu;
    int warp = threadIdx.x >> 5, lane = threadIdx.x & 31;
    int b = blockIdx.x, g = warp;
    const float* W = (g == 0) ? Wf : (g == 1) ? Wi : (g == 2) ? Wu : Wo;

    // ---- angles: acc[q] = h . W[D+..., q]  (skip at t=0, h=0) ----
    float acc[8] = {0.f, 0.f, 0.f, 0.f, 0.f, 0.f, 0.f, 0.f};
    if (t != 0) {
        const float* hr = g_h + b * H_;
        const float* Wh = W + (size_t)D_ * 8;
        #pragma unroll
        for (int it = 0; it < 16; it++) {
            int k = it * 32 + lane;
            float hv = hr[k];
            float4 w0 = *(const float4*)(Wh + k * 8);
            float4 w1 = *(const float4*)(Wh + k * 8 + 4);
            acc[0] += hv * w0.x; acc[1] += hv * w0.y;
            acc[2] += hv * w0.z; acc[3] += hv * w0.w;
            acc[4] += hv * w1.x; acc[5] += hv * w1.y;
            acc[6] += hv * w1.z; acc[7] += hv * w1.w;
        }
    }
    #pragma unroll
    for (int q = 0; q < 8; q++) {
        #pragma unroll
        for (int o = 16; o; o >>= 1) acc[q] += __shfl_xor_sync(FULL, acc[q], o);
    }
    // lane computes sincos of angle (lane&7), then broadcast
    int myq = lane & 7;
    float a = acc[0];
    if (myq == 1) a = acc[1];
    if (myq == 2) a = acc[2];
    if (myq == 3) a = acc[3];
    if (myq == 4) a = acc[4];
    if (myq == 5) a = acc[5];
    if (myq == 6) a = acc[6];
    if (myq == 7) a = acc[7];
    a += g_Xproj[((t * B_ + b) * 4 + g) * 8 + myq];
    float sv, cv;
    __sincosf(a * 0.5f, &sv, &cv);
    float cx[8], sx[8];
    #pragma unroll
    for (int q = 0; q < 8; q++) {
        cx[q] = __shfl_sync(FULL, cv, q);
        sx[q] = __shfl_sync(FULL, sv, q);
    }

    const float* tg = g_trig + g * 64;   // (l*8+q)*4 + {cy,sy,cz,sz}

    // ---- statevector: |0..0> ----
    float re[8], im[8];
    #pragma unroll
    for (int r = 0; r < 8; r++) { re[r] = 0.f; im[r] = 0.f; }
    if (lane == 0) re[0] = 1.f;

    // ---- RX per qubit: a' = c*a - i*s*partner (uniform both halves) ----
    #pragma unroll
    for (int q = 0; q < 5; q++) {              // lane-bit qubits
        int d = 16 >> q;
        float c = cx[q], s = sx[q];
        float pr[8], pi[8];
        #pragma unroll
        for (int r = 0; r < 8; r++) {
            pr[r] = __shfl_xor_sync(FULL, re[r], d);
            pi[r] = __shfl_xor_sync(FULL, im[r], d);
        }
        #pragma unroll
        for (int r = 0; r < 8; r++) {
            re[r] = c * re[r] + s * pi[r];
            im[r] = c * im[r] - s * pr[r];
        }
    }
    #pragma unroll
    for (int q = 5; q < 8; q++) {              // register-bit qubits
        int str = 1 << (7 - q);
        float c = cx[q], s = sx[q];
        float tr[8], ti[8];
        #pragma unroll
        for (int r = 0; r < 8; r++) { tr[r] = re[r]; ti[r] = im[r]; }
        #pragma unroll
        for (int r = 0; r < 8; r++) {
            re[r] = c * tr[r] + s * ti[r ^ str];
            im[r] = c * ti[r] - s * tr[r ^ str];
        }
    }

    // ---- 2 layers: (RY+RZ fused) per qubit, then CNOT chain ----
    #pragma unroll
    for (int l = 0; l < 2; l++) {
        #pragma unroll
        for (int q = 0; q < 8; q++) {
            float cy = tg[(l * 8 + q) * 4 + 0];
            float sy = tg[(l * 8 + q) * 4 + 1];
            float cz = tg[(l * 8 + q) * 4 + 2];
            float sz = tg[(l * 8 + q) * 4 + 3];
            if (q < 5) {
                int d = 16 >> q, lb = 4 - q;
                int hi = (lane >> lb) & 1;
                float sgn = hi ? sy : -sy;
                float zn  = hi ? sz : -sz;
                float pr[8], pi[8];
                #pragma unroll
                for (int r = 0; r < 8; r++) {
                    pr[r] = __shfl_xor_sync(FULL, re[r], d);
                    pi[r] = __shfl_xor_sync(FULL, im[r], d);
                }
                #pragma unroll
                for (int r = 0; r < 8; r++) {
                    float nr = cy * re[r] + sgn * pr[r];
                    float ni = cy * im[r] + sgn * pi[r];
                    re[r] = cz * nr - zn * ni;
                    im[r] = cz * ni + zn * nr;
                }
            } else {
                int str = 1 << (7 - q);
                float tr[8], ti[8];
                #pragma unroll
                for (int r = 0; r < 8; r++) { tr[r] = re[r]; ti[r] = im[r]; }
                #pragma unroll
                for (int r = 0; r < 8; r++) {
                    float sgn = (r & str) ? sy : -sy;
                    float zn  = (r & str) ? sz : -sz;
                    float nr = cy * tr[r] + sgn * tr[r ^ str];
                    float ni = cy * ti[r] + sgn * ti[r ^ str];
                    re[r] = cz * nr - zn * ni;
                    im[r] = cz * ni + zn * nr;
                }
            }
        }
        // CNOT ctrl=0..3: control lane bit (4-ct), target lane bit -> shfl d = 8>>ct
        #pragma unroll
        for (int ct = 0; ct < 4; ct++) {
            int d = 8 >> ct, cb = 4 - ct;
            int cbit = (lane >> cb) & 1;
            float pr[8], pi[8];
            #pragma unroll
            for (int r = 0; r < 8; r++) {
                pr[r] = __shfl_xor_sync(FULL, re[r], d);
                pi[r] = __shfl_xor_sync(FULL, im[r], d);
            }
            #pragma unroll
            for (int r = 0; r < 8; r++) {
                re[r] = cbit ? pr[r] : re[r];
                im[r] = cbit ? pi[r] : im[r];
            }
        }
        // CNOT ctrl=4: control lane bit0, target reg bit2 -> predicated local swap
        {
            int cbit = lane & 1;
            #pragma unroll
            for (int r = 0; r < 4; r++) {
                float t1 = re[r], t2 = re[r + 4];
                re[r]     = cbit ? t2 : t1;
                re[r + 4] = cbit ? t1 : t2;
                t1 = im[r]; t2 = im[r + 4];
                im[r]     = cbit ? t2 : t1;
                im[r + 4] = cbit ? t1 : t2;
            }
        }
        // CNOT ctrl=5: control reg bit2, target reg bit1: swap (4,6),(5,7)
        {
            float t;
            t = re[4]; re[4] = re[6]; re[6] = t;
            t = re[5]; re[5] = re[7]; re[7] = t;
            t = im[4]; im[4] = im[6]; im[6] = t;
            t = im[5]; im[5] = im[7]; im[7] = t;
        }
        // CNOT ctrl=6: control reg bit1, target reg bit0: swap (2,3),(6,7)
        {
            float t;
            t = re[2]; re[2] = re[3]; re[3] = t;
            t = re[6]; re[6] = re[7]; re[7] = t;
            t = im[2]; im[2] = im[3]; im[3] = t;
            t = im[6]; im[6] = im[7]; im[7] = t;
        }
    }

    // ---- measure Z ----
    float p[8];
    #pragma unroll
    for (int r = 0; r < 8; r++) p[r] = re[r] * re[r] + im[r] * im[r];
    float S = p[0] + p[1] + p[2] + p[3] + p[4] + p[5] + p[6] + p[7];
    float z[8];
    #pragma unroll
    for (int q = 0; q < 5; q++) {
        int lb = 4 - q;
        z[q] = ((lane >> lb) & 1) ? -S : S;
    }
    z[5] = (p[0] + p[1] + p[2] + p[3]) - (p[4] + p[5] + p[6] + p[7]);
    z[6] = (p[0] + p[1] + p[4] + p[5]) - (p[2] + p[3] + p[6] + p[7]);
    z[7] = (p[0] + p[2] + p[4] + p[6]) - (p[1] + p[3] + p[5] + p[7]);
    #pragma unroll
    for (int q = 0; q < 8; q++) {
        #pragma unroll
        for (int o = 16; o; o >>= 1) z[q] += __shfl_xor_sync(FULL, z[q], o);
    }

    // ---- H1 = relu(z @ pW1 + pb1) ----
    int row = b * 4 + g;
    #pragma unroll
    for (int j = 0; j < 16; j++) {
        int col = j * 32 + lane;
        float a2 = pb1[col];
        #pragma unroll
        for (int q = 0; q < 8; q++) a2 += z[q] * pW1[q * H_ + col];
        g_H1[row * H_ + col] = fmaxf(a2, 0.f);
    }
}

__device__ __forceinline__ float sigmoidf_(float x) { return 1.f / (1.f + expf(-x)); }

// preact(B*4,512) = H1 @ pW2 + pb2, fused LSTM epilogue. (unchanged, known good)
__global__ __launch_bounds__(256) void gemm_lstm_kernel(
    const float* __restrict__ pW2, const float* __restrict__ pb2,
    float* __restrict__ out_t,
    float* __restrict__ out_h, float* __restrict__ out_c)
{
    __shared__ float As[16][68];
    __shared__ float Bs[16][64];

    int tid = threadIdx.x;
    int bx = blockIdx.x;
    int by = blockIdx.y;
    int ty = tid >> 4, tx = tid & 15;

    float acc[4][4];
    #pragma unroll
    for (int i = 0; i < 4; i++)
        #pragma unroll
        for (int j = 0; j < 4; j++) acc[i][j] = 0.f;

    int mbase = by * 64;
    int nbase = bx * 64;
    int ar = tid >> 2, ak = (tid & 3) * 4;
    int bk = tid >> 4, bc = (tid & 15) * 4;
    const float* Aptr = g_H1 + (size_t)(mbase + ar) * H_ + ak;
    const float* Bptr = pW2 + (size_t)bk * H_ + nbase + bc;

    for (int kk = 0; kk < H_; kk += 16) {
        float4 av = *(const float4*)(Aptr + kk);
        float4 bv = *(const float4*)(Bptr + (size_t)kk * H_);
        As[ak + 0][ar] = av.x; As[ak + 1][ar] = av.y;
        As[ak + 2][ar] = av.z; As[ak + 3][ar] = av.w;
        *(float4*)&Bs[bk][bc] = bv;
        __syncthreads();
        #pragma unroll
        for (int k = 0; k < 16; k++) {
            float4 a  = *(const float4*)&As[k][ty * 4];
            float4 bb = *(const float4*)&Bs[k][tx * 4];
            acc[0][0] += a.x * bb.x; acc[0][1] += a.x * bb.y;
            acc[0][2] += a.x * bb.z; acc[0][3] += a.x * bb.w;
            acc[1][0] += a.y * bb.x; acc[1][1] += a.y * bb.y;
            acc[1][2] += a.y * bb.z; acc[1][3] += a.y * bb.w;
            acc[2][0] += a.z * bb.x; acc[2][1] += a.z * bb.y;
            acc[2][2] += a.z * bb.z; acc[2][3] += a.z * bb.w;
            acc[3][0] += a.w * bb.x; acc[3][1] += a.w * bb.y;
            acc[3][2] += a.w * bb.z; acc[3][3] += a.w * bb.w;
        }
        __syncthreads();
    }

    int bidx = by * 16 + ty;
    int col0 = nbase + tx * 4;
    #pragma unroll
    for (int ni = 0; ni < 4; ni++) {
        int col = col0 + ni;
        float bias = pb2[col];
        float fv = sigmoidf_(acc[0][ni] + bias);
        float iv = sigmoidf_(acc[1][ni] + bias);
        float uv = tanhf   (acc[2][ni] + bias);
        float ov = sigmoidf_(acc[3][ni] + bias);
        int idx = bidx * H_ + col;
        float c = fv * g_c[idx] + iv * uv;
        float h = ov * tanhf(c);
        g_c[idx] = c;
        g_h[idx] = h;
        out_t[idx] = h;
        if (out_h) { out_h[idx] = h; out_c[idx] = c; }
    }
}

extern "C" void kernel_launch(void* const* d_in, const int* in_sizes, int n_in,
                              void* d_out, int out_size) {
    const float* inputs = (const float*)d_in[0];
    const float* qpf = (const float*)d_in[1];
    const float* qpi = (const float*)d_in[2];
    const float* qpu = (const float*)d_in[3];
    const float* qpo = (const float*)d_in[4];
    const float* Wf  = (const float*)d_in[5];
    const float* bf  = (const float*)d_in[6];
    const float* Wi  = (const float*)d_in[7];
    const float* bi  = (const float*)d_in[8];
    const float* Wu  = (const float*)d_in[9];
    const float* bu  = (const float*)d_in[10];
    const float* Wo  = (const float*)d_in[11];
    const float* bo  = (const float*)d_in[12];
    const float* pW1 = (const float*)d_in[13];
    const float* pb1 = (const float*)d_in[14];
    const float* pW2 = (const float*)d_in[15];
    const float* pb2 = (const float*)d_in[16];
    float* out = (float*)d_out;

    init_kernel<<<(B_ * H_ + 255) / 256, 256>>>(qpf, qpi, qpu, qpo);
    xproj_kernel<<<(T_ * B_ * 32) / 256, 256>>>(inputs, Wf, Wi, Wu, Wo, bf, bi, bu, bo);

    for (int t = 0; t < T_; t++) {
        quantum_kernel<<<B_, 128>>>(t, Wf, Wi, Wu, Wo, pW1, pb1);
        bool last = (t == T_ - 1);
        gemm_lstm_kernel<<<dim3(8, 16), 256>>>(
            pW2, pb2,
            out + (size_t)t * B_ * H_,
            last ? out + (size_t)T_ * B_ * H_            : nullptr,
            last ? out + (size_t)T_ * B_ * H_ + B_ * H_  : nullptr);
    }
}

// round 4
// speedup vs baseline: 1.8778x; 1.6084x over previous
#include <cuda_runtime.h>
#include <cuda_bf16.h>
#include <math.h>
#include <stdint.h>

#define T_  64
#define B_  256
#define D_  512
#define H_  512

// ---------------- device scratch (allocation-free rule) ----------------
__device__ __nv_bfloat16 g_H1h[B_ * 4 * H_];   // hi(H1), row = gate*256 + b
__device__ __nv_bfloat16 g_H1l[B_ * 4 * H_];   // lo(H1)
__device__ __nv_bfloat16 g_Bht[H_ * H_];       // hi(pW2^T), [n][k]
__device__ __nv_bfloat16 g_Blt[H_ * H_];       // lo(pW2^T)
__device__ float g_P[B_ * 4 * H_];             // preact, row = gate*256 + b
__device__ float g_h[B_ * H_];
__device__ float g_c[B_ * H_];
__device__ float g_Xproj[T_ * B_ * 32];        // x_t @ W + b, [t*B+b][g*8+q]
__device__ float g_trig[4 * 2 * 8 * 4];        // [g][l][q][{cy,sy,cz,sz}]

// ---------------- PTX helpers (baseline sm_80+/sm_90 features only) -------
__device__ __forceinline__ uint32_t smem_u32(const void* p) {
    uint32_t a;
    asm("{ .reg .u64 t; cvta.to.shared.u64 t, %1; cvt.u32.u64 %0, t; }" : "=r"(a) : "l"(p));
    return a;
}
__device__ __forceinline__ void cp16(uint32_t dst, const void* src) {
    asm volatile("cp.async.ca.shared.global [%0], [%1], 16;" :: "r"(dst), "l"(src) : "memory");
}
#define CP_COMMIT() asm volatile("cp.async.commit_group;" ::: "memory")
template<int N> __device__ __forceinline__ void cp_wait() {
    asm volatile("cp.async.wait_group %0;" :: "n"(N) : "memory");
}
__device__ __forceinline__ void ldm4(uint32_t addr, uint32_t* r) {
    asm volatile("ldmatrix.sync.aligned.m8n8.x4.shared.b16 {%0,%1,%2,%3}, [%4];"
        : "=r"(r[0]), "=r"(r[1]), "=r"(r[2]), "=r"(r[3]) : "r"(addr));
}
__device__ __forceinline__ void mma_bf16(float* c, const uint32_t* a, uint32_t b0, uint32_t b1) {
    asm volatile(
        "mma.sync.aligned.m16n8k16.row.col.f32.bf16.bf16.f32 "
        "{%0,%1,%2,%3}, {%4,%5,%6,%7}, {%8,%9}, {%0,%1,%2,%3};"
        : "+f"(c[0]), "+f"(c[1]), "+f"(c[2]), "+f"(c[3])
        : "r"(a[0]), "r"(a[1]), "r"(a[2]), "r"(a[3]), "r"(b0), "r"(b1));
}

// ---------------- init / prep ----------------
__global__ void init_kernel(const float* __restrict__ qpf, const float* __restrict__ qpi,
                            const float* __restrict__ qpu, const float* __restrict__ qpo) {
    int i = blockIdx.x * blockDim.x + threadIdx.x;
    if (i < B_ * H_) { g_h[i] = 0.f; g_c[i] = 0.f; }
    if (i < 4 * 2 * 8) {
        int g = i >> 4, r = i & 15, l = r >> 3, q = r & 7;
        const float* qp = (g == 0) ? qpf : (g == 1) ? qpi : (g == 2) ? qpu : qpo;
        float ty = qp[(l * 8 + q) * 3 + 0] * 0.5f;
        float tz = qp[(l * 8 + q) * 3 + 1] * 0.5f;
        g_trig[i * 4 + 0] = cosf(ty);
        g_trig[i * 4 + 1] = sinf(ty);
        g_trig[i * 4 + 2] = cosf(tz);
        g_trig[i * 4 + 3] = sinf(tz);
    }
}

// pW2 (K,N) -> transposed bf16 hi/lo [n][k]
__global__ void bprep_kernel(const float* __restrict__ pW2) {
    int i = blockIdx.x * blockDim.x + threadIdx.x;   // n*512+k
    int n = i >> 9, k = i & 511;
    float v = pW2[k * H_ + n];
    __nv_bfloat16 hi = __float2bfloat16(v);
    __nv_bfloat16 lo = __float2bfloat16(v - __bfloat162float(hi));
    g_Bht[i] = hi; g_Blt[i] = lo;
}

// One-time: Xproj[row][g*8+q] = x[row] . W_g[:D, q] + b_g[q],  row = t*B+b
__global__ __launch_bounds__(256) void xproj_kernel(
    const float* __restrict__ inputs,
    const float* __restrict__ Wf, const float* __restrict__ Wi,
    const float* __restrict__ Wu, const float* __restrict__ Wo,
    const float* __restrict__ bf, const float* __restrict__ bi,
    const float* __restrict__ bu, const float* __restrict__ bo)
{
    int tid = blockIdx.x * 256 + threadIdx.x;
    int row = tid >> 5;
    int o = tid & 31, g = o >> 3, q = o & 7;
    const float* W  = (g == 0) ? Wf : (g == 1) ? Wi : (g == 2) ? Wu : Wo;
    const float* bb = (g == 0) ? bf : (g == 1) ? bi : (g == 2) ? bu : bo;
    const float* x = inputs + (size_t)row * D_;
    float acc = bb[q];
    #pragma unroll 8
    for (int k = 0; k < D_; k++) acc += x[k] * W[k * 8 + q];
    g_Xproj[row * 32 + o] = acc;
}

// ---------------- quantum sim (warp per statevector) ----------------
__global__ __launch_bounds__(128) void quantum_kernel(
    int t,
    const float* __restrict__ Wf, const float* __restrict__ Wi,
    const float* __restrict__ Wu, const float* __restrict__ Wo,
    const float* __restrict__ pW1, const float* __restrict__ pb1)
{
    const unsigned FULL = 0xffffffffu;
    int warp = threadIdx.x >> 5, lane = threadIdx.x & 31;
    int b = blockIdx.x, g = warp;
    const float* W = (g == 0) ? Wf : (g == 1) ? Wi : (g == 2) ? Wu : Wo;

    float acc[8] = {0.f, 0.f, 0.f, 0.f, 0.f, 0.f, 0.f, 0.f};
    if (t != 0) {
        const float* hr = g_h + b * H_;
        const float* Wh = W + (size_t)D_ * 8;
        #pragma unroll
        for (int it = 0; it < 16; it++) {
            int k = it * 32 + lane;
            float hv = hr[k];
            float4 w0 = *(const float4*)(Wh + k * 8);
            float4 w1 = *(const float4*)(Wh + k * 8 + 4);
            acc[0] += hv * w0.x; acc[1] += hv * w0.y;
            acc[2] += hv * w0.z; acc[3] += hv * w0.w;
            acc[4] += hv * w1.x; acc[5] += hv * w1.y;
            acc[6] += hv * w1.z; acc[7] += hv * w1.w;
        }
    }
    #pragma unroll
    for (int q = 0; q < 8; q++) {
        #pragma unroll
        for (int o = 16; o; o >>= 1) acc[q] += __shfl_xor_sync(FULL, acc[q], o);
    }
    int myq = lane & 7;
    float a = acc[0];
    if (myq == 1) a = acc[1];
    if (myq == 2) a = acc[2];
    if (myq == 3) a = acc[3];
    if (myq == 4) a = acc[4];
    if (myq == 5) a = acc[5];
    if (myq == 6) a = acc[6];
    if (myq == 7) a = acc[7];
    a += g_Xproj[((t * B_ + b) * 4 + g) * 8 + myq];
    float sv, cv;
    __sincosf(a * 0.5f, &sv, &cv);
    float cx[8], sx[8];
    #pragma unroll
    for (int q = 0; q < 8; q++) {
        cx[q] = __shfl_sync(FULL, cv, q);
        sx[q] = __shfl_sync(FULL, sv, q);
    }

    const float* tg = g_trig + g * 64;

    float re[8], im[8];
    #pragma unroll
    for (int r = 0; r < 8; r++) { re[r] = 0.f; im[r] = 0.f; }
    if (lane == 0) re[0] = 1.f;

    #pragma unroll
    for (int q = 0; q < 5; q++) {
        int d = 16 >> q;
        float c = cx[q], s = sx[q];
        float pr[8], pi[8];
        #pragma unroll
        for (int r = 0; r < 8; r++) {
            pr[r] = __shfl_xor_sync(FULL, re[r], d);
            pi[r] = __shfl_xor_sync(FULL, im[r], d);
        }
        #pragma unroll
        for (int r = 0; r < 8; r++) {
            re[r] = c * re[r] + s * pi[r];
            im[r] = c * im[r] - s * pr[r];
        }
    }
    #pragma unroll
    for (int q = 5; q < 8; q++) {
        int str = 1 << (7 - q);
        float c = cx[q], s = sx[q];
        float tr[8], ti[8];
        #pragma unroll
        for (int r = 0; r < 8; r++) { tr[r] = re[r]; ti[r] = im[r]; }
        #pragma unroll
        for (int r = 0; r < 8; r++) {
            re[r] = c * tr[r] + s * ti[r ^ str];
            im[r] = c * ti[r] - s * tr[r ^ str];
        }
    }

    #pragma unroll
    for (int l = 0; l < 2; l++) {
        #pragma unroll
        for (int q = 0; q < 8; q++) {
            float cy = tg[(l * 8 + q) * 4 + 0];
            float sy = tg[(l * 8 + q) * 4 + 1];
            float cz = tg[(l * 8 + q) * 4 + 2];
            float sz = tg[(l * 8 + q) * 4 + 3];
            if (q < 5) {
                int d = 16 >> q, lb = 4 - q;
                int hi = (lane >> lb) & 1;
                float sgn = hi ? sy : -sy;
                float zn  = hi ? sz : -sz;
                float pr[8], pi[8];
                #pragma unroll
                for (int r = 0; r < 8; r++) {
                    pr[r] = __shfl_xor_sync(FULL, re[r], d);
                    pi[r] = __shfl_xor_sync(FULL, im[r], d);
                }
                #pragma unroll
                for (int r = 0; r < 8; r++) {
                    float nr = cy * re[r] + sgn * pr[r];
                    float ni = cy * im[r] + sgn * pi[r];
                    re[r] = cz * nr - zn * ni;
                    im[r] = cz * ni + zn * nr;
                }
            } else {
                int str = 1 << (7 - q);
                float tr[8], ti[8];
                #pragma unroll
                for (int r = 0; r < 8; r++) { tr[r] = re[r]; ti[r] = im[r]; }
                #pragma unroll
                for (int r = 0; r < 8; r++) {
                    float sgn = (r & str) ? sy : -sy;
                    float zn  = (r & str) ? sz : -sz;
                    float nr = cy * tr[r] + sgn * tr[r ^ str];
                    float ni = cy * ti[r] + sgn * ti[r ^ str];
                    re[r] = cz * nr - zn * ni;
                    im[r] = cz * ni + zn * nr;
                }
            }
        }
        #pragma unroll
        for (int ct = 0; ct < 4; ct++) {
            int d = 8 >> ct, cb = 4 - ct;
            int cbit = (lane >> cb) & 1;
            float pr[8], pi[8];
            #pragma unroll
            for (int r = 0; r < 8; r++) {
                pr[r] = __shfl_xor_sync(FULL, re[r], d);
                pi[r] = __shfl_xor_sync(FULL, im[r], d);
            }
            #pragma unroll
            for (int r = 0; r < 8; r++) {
                re[r] = cbit ? pr[r] : re[r];
                im[r] = cbit ? pi[r] : im[r];
            }
        }
        {
            int cbit = lane & 1;
            #pragma unroll
            for (int r = 0; r < 4; r++) {
                float t1 = re[r], t2 = re[r + 4];
                re[r]     = cbit ? t2 : t1;
                re[r + 4] = cbit ? t1 : t2;
                t1 = im[r]; t2 = im[r + 4];
                im[r]     = cbit ? t2 : t1;
                im[r + 4] = cbit ? t1 : t2;
            }
        }
        {
            float t;
            t = re[4]; re[4] = re[6]; re[6] = t;
            t = re[5]; re[5] = re[7]; re[7] = t;
            t = im[4]; im[4] = im[6]; im[6] = t;
            t = im[5]; im[5] = im[7]; im[7] = t;
        }
        {
            float t;
            t = re[2]; re[2] = re[3]; re[3] = t;
            t = re[6]; re[6] = re[7]; re[7] = t;
            t = im[2]; im[2] = im[3]; im[3] = t;
            t = im[6]; im[6] = im[7]; im[7] = t;
        }
    }

    float p[8];
    #pragma unroll
    for (int r = 0; r < 8; r++) p[r] = re[r] * re[r] + im[r] * im[r];
    float S = p[0] + p[1] + p[2] + p[3] + p[4] + p[5] + p[6] + p[7];
    float z[8];
    #pragma unroll
    for (int q = 0; q < 5; q++) {
        int lb = 4 - q;
        z[q] = ((lane >> lb) & 1) ? -S : S;
    }
    z[5] = (p[0] + p[1] + p[2] + p[3]) - (p[4] + p[5] + p[6] + p[7]);
    z[6] = (p[0] + p[1] + p[4] + p[5]) - (p[2] + p[3] + p[6] + p[7]);
    z[7] = (p[0] + p[2] + p[4] + p[6]) - (p[1] + p[3] + p[5] + p[7]);
    #pragma unroll
    for (int q = 0; q < 8; q++) {
        #pragma unroll
        for (int o = 16; o; o >>= 1) z[q] += __shfl_xor_sync(FULL, z[q], o);
    }

    // H1 = relu(z @ pW1 + pb1) -> bf16 hi/lo, row = gate*256 + b
    int row = g * B_ + b;
    #pragma unroll
    for (int j = 0; j < 16; j++) {
        int col = j * 32 + lane;
        float a2 = pb1[col];
        #pragma unroll
        for (int q = 0; q < 8; q++) a2 += z[q] * pW1[q * H_ + col];
        a2 = fmaxf(a2, 0.f);
        __nv_bfloat16 hi = __float2bfloat16(a2);
        __nv_bfloat16 lo = __float2bfloat16(a2 - __bfloat162float(hi));
        g_H1h[row * H_ + col] = hi;
        g_H1l[row * H_ + col] = lo;
    }
}

// ---------------- HMMA GEMM: P = H1 @ pW2 (split bf16, fp32 accum) ----------
// Block tile 64(M) x 64(N), 4 warps (32x32 each), K chunks of 64, cp.async
// double buffered. Smem rows padded to 144B -> conflict-free ldmatrix.
#define SROWB 144u                 // bytes per 64-elem bf16 row (64*2 + 16 pad)
#define SM_AH 0u
#define SM_AL 9216u
#define SM_BH 18432u
#define SM_BL 27648u
#define BUFSZ 36864u
#define SMEM_DYN (2 * 36864)

__global__ __launch_bounds__(128, 1) void gemm_mma_kernel()
{
    extern __shared__ char dsm[];
    uint32_t s0 = smem_u32(dsm);
    int tid = threadIdx.x, wid = tid >> 5, lane = tid & 31;
    int n0 = blockIdx.x * 64, m0 = blockIdx.y * 64;
    int wm = (wid >> 1) * 32, wn = (wid & 1) * 32;

    const __nv_bfloat16* Ah = g_H1h + (size_t)m0 * H_;
    const __nv_bfloat16* Al = g_H1l + (size_t)m0 * H_;
    const __nv_bfloat16* Bh = g_Bht + (size_t)n0 * H_;
    const __nv_bfloat16* Bl = g_Blt + (size_t)n0 * H_;

    // per-thread cp.async coords: unit u covers 16B = 8 bf16
    int lrow[4], lkc[4];
    uint32_t ldst[4];
    #pragma unroll
    for (int j = 0; j < 4; j++) {
        int u = tid + 128 * j;
        lrow[j] = u >> 3; lkc[j] = (u & 7) * 8;
        ldst[j] = (uint32_t)lrow[j] * SROWB + (uint32_t)(u & 7) * 16u;
    }

    // ldmatrix base offsets (within array): row = base + (lane&15), kbyte = ((lane>>4)<<4)
    uint32_t aOff = (uint32_t)(wm + (lane & 15)) * SROWB + (uint32_t)((lane >> 4) << 4);
    uint32_t bOff = (uint32_t)(wn + (lane & 15)) * SROWB + (uint32_t)((lane >> 4) << 4);

    float acc[2][4][4];
    #pragma unroll
    for (int i = 0; i < 2; i++)
        #pragma unroll
        for (int j = 0; j < 4; j++)
            #pragma unroll
            for (int r = 0; r < 4; r++) acc[i][j][r] = 0.f;

    // prefetch chunk 0
    {
        uint32_t sb = s0;
        #pragma unroll
        for (int j = 0; j < 4; j++) {
            size_t go = (size_t)lrow[j] * H_ + lkc[j];
            cp16(sb + SM_AH + ldst[j], Ah + go);
            cp16(sb + SM_AL + ldst[j], Al + go);
            cp16(sb + SM_BH + ldst[j], Bh + go);
            cp16(sb + SM_BL + ldst[j], Bl + go);
        }
        CP_COMMIT();
    }

    for (int c = 0; c < 8; c++) {
        if (c + 1 < 8) {
            uint32_t sb = s0 + ((c + 1) & 1) * BUFSZ;
            int kb = (c + 1) * 64;
            #pragma unroll
            for (int j = 0; j < 4; j++) {
                size_t go = (size_t)lrow[j] * H_ + kb + lkc[j];
                cp16(sb + SM_AH + ldst[j], Ah + go);
                cp16(sb + SM_AL + ldst[j], Al + go);
                cp16(sb + SM_BH + ldst[j], Bh + go);
                cp16(sb + SM_BL + ldst[j], Bl + go);
            }
            CP_COMMIT();
            cp_wait<1>();
        } else {
            cp_wait<0>();
        }
        __syncthreads();

        uint32_t buf = s0 + (c & 1) * BUFSZ;
        #pragma unroll
        for (int kk = 0; kk < 4; kk++) {
            uint32_t kb = kk * 32;
            uint32_t ah[2][4], al[2][4], bh[2][4], bl[2][4];
            #pragma unroll
            for (int i = 0; i < 2; i++) {
                ldm4(buf + SM_AH + aOff + i * (16 * SROWB) + kb, ah[i]);
                ldm4(buf + SM_AL + aOff + i * (16 * SROWB) + kb, al[i]);
            }
            #pragma unroll
            for (int p = 0; p < 2; p++) {
                ldm4(buf + SM_BH + bOff + p * (16 * SROWB) + kb, bh[p]);
                ldm4(buf + SM_BL + bOff + p * (16 * SROWB) + kb, bl[p]);
            }
            #pragma unroll
            for (int i = 0; i < 2; i++) {
                #pragma unroll
                for (int j = 0; j < 4; j++) {
                    int p = j >> 1, s = j & 1;
                    mma_bf16(acc[i][j], ah[i], bh[p][s], bh[p][2 + s]);
                    mma_bf16(acc[i][j], ah[i], bl[p][s], bl[p][2 + s]);
                    mma_bf16(acc[i][j], al[i], bh[p][s], bh[p][2 + s]);
                }
            }
        }
        __syncthreads();
    }

    // epilogue: thread frag rows lane/4, lane/4+8; cols 2*(lane&3), +1
    #pragma unroll
    for (int i = 0; i < 2; i++) {
        int mrow = m0 + wm + i * 16 + (lane >> 2);
        #pragma unroll
        for (int j = 0; j < 4; j++) {
            int ncol = n0 + wn + j * 8 + (lane & 3) * 2;
            *(float2*)(g_P + (size_t)mrow * H_ + ncol)       = make_float2(acc[i][j][0], acc[i][j][1]);
            *(float2*)(g_P + (size_t)(mrow + 8) * H_ + ncol) = make_float2(acc[i][j][2], acc[i][j][3]);
        }
    }
}

// ---------------- elementwise LSTM update ----------------
__device__ __forceinline__ float sigmoidf_(float x) { return 1.f / (1.f + expf(-x)); }

__global__ __launch_bounds__(256) void lstm_ew_kernel(
    const float* __restrict__ pb2,
    float* __restrict__ out_t,
    float* __restrict__ out_h, float* __restrict__ out_c)
{
    int i = blockIdx.x * 256 + threadIdx.x;      // b*512+col
    int col = i & 511;
    float bias = pb2[col];
    float fv = sigmoidf_(g_P[0 * B_ * H_ + i] + bias);
    float iv = sigmoidf_(g_P[1 * B_ * H_ + i] + bias);
    float uv = tanhf   (g_P[2 * B_ * H_ + i] + bias);
    float ov = sigmoidf_(g_P[3 * B_ * H_ + i] + bias);
    float c = fv * g_c[i] + iv * uv;
    float h = ov * tanhf(c);
    g_c[i] = c;
    g_h[i] = h;
    out_t[i] = h;
    if (out_h) { out_h[i] = h; out_c[i] = c; }
}

// ---------------- host ----------------
extern "C" void kernel_launch(void* const* d_in, const int* in_sizes, int n_in,
                              void* d_out, int out_size) {
    const float* inputs = (const float*)d_in[0];
    const float* qpf = (const float*)d_in[1];
    const float* qpi = (const float*)d_in[2];
    const float* qpu = (const float*)d_in[3];
    const float* qpo = (const float*)d_in[4];
    const float* Wf  = (const float*)d_in[5];
    const float* bf  = (const float*)d_in[6];
    const float* Wi  = (const float*)d_in[7];
    const float* bi  = (const float*)d_in[8];
    const float* Wu  = (const float*)d_in[9];
    const float* bu  = (const float*)d_in[10];
    const float* Wo  = (const float*)d_in[11];
    const float* bo  = (const float*)d_in[12];
    const float* pW1 = (const float*)d_in[13];
    const float* pb1 = (const float*)d_in[14];
    const float* pW2 = (const float*)d_in[15];
    const float* pb2 = (const float*)d_in[16];
    float* out = (float*)d_out;

    cudaFuncSetAttribute(gemm_mma_kernel, cudaFuncAttributeMaxDynamicSharedMemorySize, SMEM_DYN);

    init_kernel<<<(B_ * H_ + 255) / 256, 256>>>(qpf, qpi, qpu, qpo);
    bprep_kernel<<<(H_ * H_) / 256, 256>>>(pW2);
    xproj_kernel<<<(T_ * B_ * 32) / 256, 256>>>(inputs, Wf, Wi, Wu, Wo, bf, bi, bu, bo);

    for (int t = 0; t < T_; t++) {
        quantum_kernel<<<B_, 128>>>(t, Wf, Wi, Wu, Wo, pW1, pb1);
        gemm_mma_kernel<<<dim3(8, 16), 128, SMEM_DYN>>>();
        bool last = (t == T_ - 1);
        lstm_ew_kernel<<<(B_ * H_) / 256, 256>>>(
            pb2,
            out + (size_t)t * B_ * H_,
            last ? out + (size_t)T_ * B_ * H_            : nullptr,
            last ? out + (size_t)T_ * B_ * H_ + B_ * H_  : nullptr);
    }
}

// round 5
// speedup vs baseline: 2.1687x; 1.1549x over previous
#include <cuda_runtime.h>
#include <cuda_bf16.h>
#include <math.h>
#include <stdint.h>

#define T_  64
#define B_  256
#define D_  512
#define H_  512

// ---------------- device scratch (allocation-free rule) ----------------
__device__ __nv_bfloat16 g_H1h[B_ * 4 * H_];   // hi(H1), row = b*4 + gate
__device__ __nv_bfloat16 g_H1l[B_ * 4 * H_];   // lo(H1)
__device__ __nv_bfloat16 g_Bht[H_ * H_];       // hi(pW2^T), [n][k]
__device__ __nv_bfloat16 g_Blt[H_ * H_];       // lo(pW2^T)
__device__ float g_h[B_ * H_];
__device__ float g_c[B_ * H_];
__device__ float g_Xproj[T_ * B_ * 32];        // x_t @ W + b, [t*B+b][g*8+q]
__device__ float g_trig[4 * 2 * 8 * 4];        // [g][l][q][{cy,sy,cz,sz}]

// ---------------- PTX helpers ----------------
__device__ __forceinline__ uint32_t smem_u32(const void* p) {
    uint32_t a;
    asm("{ .reg .u64 t; cvta.to.shared.u64 t, %1; cvt.u32.u64 %0, t; }" : "=r"(a) : "l"(p));
    return a;
}
__device__ __forceinline__ void cp16(uint32_t dst, const void* src) {
    asm volatile("cp.async.ca.shared.global [%0], [%1], 16;" :: "r"(dst), "l"(src) : "memory");
}
#define CP_COMMIT() asm volatile("cp.async.commit_group;" ::: "memory")
template<int N> __device__ __forceinline__ void cp_wait() {
    asm volatile("cp.async.wait_group %0;" :: "n"(N) : "memory");
}
__device__ __forceinline__ void ldm4(uint32_t addr, uint32_t* r) {
    asm volatile("ldmatrix.sync.aligned.m8n8.x4.shared.b16 {%0,%1,%2,%3}, [%4];"
        : "=r"(r[0]), "=r"(r[1]), "=r"(r[2]), "=r"(r[3]) : "r"(addr));
}
__device__ __forceinline__ void mma_bf16(float* c, const uint32_t* a, uint32_t b0, uint32_t b1) {
    asm volatile(
        "mma.sync.aligned.m16n8k16.row.col.f32.bf16.bf16.f32 "
        "{%0,%1,%2,%3}, {%4,%5,%6,%7}, {%8,%9}, {%0,%1,%2,%3};"
        : "+f"(c[0]), "+f"(c[1]), "+f"(c[2]), "+f"(c[3])
        : "r"(a[0]), "r"(a[1]), "r"(a[2]), "r"(a[3]), "r"(b0), "r"(b1));
}

// ---------------- init / prep ----------------
__global__ void init_kernel(const float* __restrict__ qpf, const float* __restrict__ qpi,
                            const float* __restrict__ qpu, const float* __restrict__ qpo) {
    int i = blockIdx.x * blockDim.x + threadIdx.x;
    if (i < B_ * H_) { g_h[i] = 0.f; g_c[i] = 0.f; }
    if (i < 4 * 2 * 8) {
        int g = i >> 4, r = i & 15, l = r >> 3, q = r & 7;
        const float* qp = (g == 0) ? qpf : (g == 1) ? qpi : (g == 2) ? qpu : qpo;
        float ty = qp[(l * 8 + q) * 3 + 0] * 0.5f;
        float tz = qp[(l * 8 + q) * 3 + 1] * 0.5f;
        g_trig[i * 4 + 0] = cosf(ty);
        g_trig[i * 4 + 1] = sinf(ty);
        g_trig[i * 4 + 2] = cosf(tz);
        g_trig[i * 4 + 3] = sinf(tz);
    }
}

// pW2 (K,N) -> transposed bf16 hi/lo [n][k]
__global__ void bprep_kernel(const float* __restrict__ pW2) {
    int i = blockIdx.x * blockDim.x + threadIdx.x;   // n*512+k
    int n = i >> 9, k = i & 511;
    float v = pW2[k * H_ + n];
    __nv_bfloat16 hi = __float2bfloat16(v);
    __nv_bfloat16 lo = __float2bfloat16(v - __bfloat162float(hi));
    g_Bht[i] = hi; g_Blt[i] = lo;
}

// One-time: Xproj[row][g*8+q] = x[row] . W_g[:D, q] + b_g[q],  row = t*B+b
__global__ __launch_bounds__(256) void xproj_kernel(
    const float* __restrict__ inputs,
    const float* __restrict__ Wf, const float* __restrict__ Wi,
    const float* __restrict__ Wu, const float* __restrict__ Wo,
    const float* __restrict__ bf, const float* __restrict__ bi,
    const float* __restrict__ bu, const float* __restrict__ bo)
{
    int tid = blockIdx.x * 256 + threadIdx.x;
    int row = tid >> 5;
    int o = tid & 31, g = o >> 3, q = o & 7;
    const float* W  = (g == 0) ? Wf : (g == 1) ? Wi : (g == 2) ? Wu : Wo;
    const float* bb = (g == 0) ? bf : (g == 1) ? bi : (g == 2) ? bu : bo;
    const float* x = inputs + (size_t)row * D_;
    float acc = bb[q];
    #pragma unroll 8
    for (int k = 0; k < D_; k++) acc += x[k] * W[k * 8 + q];
    g_Xproj[row * 32 + o] = acc;
}

// ---------------- quantum sim (warp per statevector, scalar-temp phases) ----
// grid (B_, 2), block 64: warp handles gate g = blockIdx.y*2 + warpid.
__global__ __launch_bounds__(64, 1) void quantum_kernel(
    int t,
    const float* __restrict__ Wf, const float* __restrict__ Wi,
    const float* __restrict__ Wu, const float* __restrict__ Wo,
    const float* __restrict__ pW1, const float* __restrict__ pb1)
{
    const unsigned FULL = 0xffffffffu;
    int warp = threadIdx.x >> 5, lane = threadIdx.x & 31;
    int b = blockIdx.x, g = blockIdx.y * 2 + warp;
    const float* W = (g == 0) ? Wf : (g == 1) ? Wi : (g == 2) ? Wu : Wo;

    // ---- angles: acc[q] = h . W[D+..., q]  (skip at t=0, h=0) ----
    float acc[8] = {0.f, 0.f, 0.f, 0.f, 0.f, 0.f, 0.f, 0.f};
    if (t != 0) {
        const float* hr = g_h + b * H_;
        const float* Wh = W + (size_t)D_ * 8;
        #pragma unroll 4
        for (int it = 0; it < 16; it++) {
            int k = it * 32 + lane;
            float hv = hr[k];
            float4 w0 = *(const float4*)(Wh + k * 8);
            float4 w1 = *(const float4*)(Wh + k * 8 + 4);
            acc[0] += hv * w0.x; acc[1] += hv * w0.y;
            acc[2] += hv * w0.z; acc[3] += hv * w0.w;
            acc[4] += hv * w1.x; acc[5] += hv * w1.y;
            acc[6] += hv * w1.z; acc[7] += hv * w1.w;
        }
    }
    #pragma unroll
    for (int q = 0; q < 8; q++) {
        #pragma unroll
        for (int o = 16; o; o >>= 1) acc[q] += __shfl_xor_sync(FULL, acc[q], o);
    }
    int myq = lane & 7;
    float a = acc[0];
    if (myq == 1) a = acc[1];
    if (myq == 2) a = acc[2];
    if (myq == 3) a = acc[3];
    if (myq == 4) a = acc[4];
    if (myq == 5) a = acc[5];
    if (myq == 6) a = acc[6];
    if (myq == 7) a = acc[7];
    a += g_Xproj[((t * B_ + b) * 4 + g) * 8 + myq];
    float sv, cv;
    __sincosf(a * 0.5f, &sv, &cv);

    // ---- statevector: |0..0>, amp bits[7:3]=lane, [2:0]=reg ----
    float re[8], im[8];
    #pragma unroll
    for (int r = 0; r < 8; r++) { re[r] = 0.f; im[r] = 0.f; }
    if (lane == 0) re[0] = 1.f;

    // ---- RX per qubit ----
    #pragma unroll
    for (int q = 0; q < 5; q++) {
        int d = 16 >> q;
        float c = __shfl_sync(FULL, cv, q);
        float s = __shfl_sync(FULL, sv, q);
        #pragma unroll
        for (int r = 0; r < 8; r++) {
            float pr = __shfl_xor_sync(FULL, re[r], d);
            float pi = __shfl_xor_sync(FULL, im[r], d);
            re[r] = c * re[r] + s * pi;
            im[r] = c * im[r] - s * pr;
        }
    }
    #pragma unroll
    for (int q = 5; q < 8; q++) {
        int str = 1 << (7 - q);
        float c = __shfl_sync(FULL, cv, q);
        float s = __shfl_sync(FULL, sv, q);
        #pragma unroll
        for (int a0 = 0; a0 < 8; a0++) {
            if (a0 & str) continue;
            int b0 = a0 | str;
            float tr0 = re[a0], ti0 = im[a0], tr1 = re[b0], ti1 = im[b0];
            re[a0] = c * tr0 + s * ti1;
            im[a0] = c * ti0 - s * tr1;
            re[b0] = c * tr1 + s * ti0;
            im[b0] = c * ti1 - s * tr0;
        }
    }

    const float* tg = g_trig + g * 64;

    // ---- 2 layers: (RY+RZ fused) per qubit, then CNOT chain ----
    #pragma unroll
    for (int l = 0; l < 2; l++) {
        #pragma unroll
        for (int q = 0; q < 8; q++) {
            float4 tv = *(const float4*)(tg + (l * 8 + q) * 4);
            float cy = tv.x, sy = tv.y, cz = tv.z, sz = tv.w;
            if (q < 5) {
                int d = 16 >> q, lb = 4 - q;
                int hi = (lane >> lb) & 1;
                float sgn = hi ? sy : -sy;
                float zn  = hi ? sz : -sz;
                #pragma unroll
                for (int r = 0; r < 8; r++) {
                    float pr = __shfl_xor_sync(FULL, re[r], d);
                    float pi = __shfl_xor_sync(FULL, im[r], d);
                    float nr = cy * re[r] + sgn * pr;
                    float ni = cy * im[r] + sgn * pi;
                    re[r] = cz * nr - zn * ni;
                    im[r] = cz * ni + zn * nr;
                }
            } else {
                int str = 1 << (7 - q);
                #pragma unroll
                for (int a0 = 0; a0 < 8; a0++) {
                    if (a0 & str) continue;
                    int b0 = a0 | str;
                    float tr0 = re[a0], ti0 = im[a0], tr1 = re[b0], ti1 = im[b0];
                    float nr0 = cy * tr0 - sy * tr1;
                    float ni0 = cy * ti0 - sy * ti1;
                    float nr1 = cy * tr1 + sy * tr0;
                    float ni1 = cy * ti1 + sy * ti0;
                    re[a0] = cz * nr0 + sz * ni0;
                    im[a0] = cz * ni0 - sz * nr0;
                    re[b0] = cz * nr1 - sz * ni1;
                    im[b0] = cz * ni1 + sz * nr1;
                }
            }
        }
        // CNOT ctrl=0..3: control lane bit (4-ct), target lane bit -> shfl
        #pragma unroll
        for (int ct = 0; ct < 4; ct++) {
            int d = 8 >> ct, cb = 4 - ct;
            int cbit = (lane >> cb) & 1;
            #pragma unroll
            for (int r = 0; r < 8; r++) {
                float pr = __shfl_xor_sync(FULL, re[r], d);
                float pi = __shfl_xor_sync(FULL, im[r], d);
                re[r] = cbit ? pr : re[r];
                im[r] = cbit ? pi : im[r];
            }
        }
        // CNOT ctrl=4: control lane bit0, target reg bit2
        {
            int cbit = lane & 1;
            #pragma unroll
            for (int r = 0; r < 4; r++) {
                float t1 = re[r], t2 = re[r + 4];
                re[r]     = cbit ? t2 : t1;
                re[r + 4] = cbit ? t1 : t2;
                t1 = im[r]; t2 = im[r + 4];
                im[r]     = cbit ? t2 : t1;
                im[r + 4] = cbit ? t1 : t2;
            }
        }
        // CNOT ctrl=5: swap (4,6),(5,7)
        {
            float t;
            t = re[4]; re[4] = re[6]; re[6] = t;
            t = re[5]; re[5] = re[7]; re[7] = t;
            t = im[4]; im[4] = im[6]; im[6] = t;
            t = im[5]; im[5] = im[7]; im[7] = t;
        }
        // CNOT ctrl=6: swap (2,3),(6,7)
        {
            float t;
            t = re[2]; re[2] = re[3]; re[3] = t;
            t = re[6]; re[6] = re[7]; re[7] = t;
            t = im[2]; im[2] = im[3]; im[3] = t;
            t = im[6]; im[6] = im[7]; im[7] = t;
        }
    }

    // ---- measure Z ----
    float p0 = re[0]*re[0]+im[0]*im[0], p1 = re[1]*re[1]+im[1]*im[1];
    float p2 = re[2]*re[2]+im[2]*im[2], p3 = re[3]*re[3]+im[3]*im[3];
    float p4 = re[4]*re[4]+im[4]*im[4], p5 = re[5]*re[5]+im[5]*im[5];
    float p6 = re[6]*re[6]+im[6]*im[6], p7 = re[7]*re[7]+im[7]*im[7];
    float S = p0+p1+p2+p3+p4+p5+p6+p7;
    float z[8];
    #pragma unroll
    for (int q = 0; q < 5; q++) {
        int lb = 4 - q;
        z[q] = ((lane >> lb) & 1) ? -S : S;
    }
    z[5] = (p0+p1+p2+p3) - (p4+p5+p6+p7);
    z[6] = (p0+p1+p4+p5) - (p2+p3+p6+p7);
    z[7] = (p0+p2+p4+p6) - (p1+p3+p5+p7);
    #pragma unroll
    for (int q = 0; q < 8; q++) {
        #pragma unroll
        for (int o = 16; o; o >>= 1) z[q] += __shfl_xor_sync(FULL, z[q], o);
    }

    // ---- H1 = relu(z @ pW1 + pb1) -> bf16 hi/lo, row = b*4 + g ----
    int row = b * 4 + g;
    #pragma unroll
    for (int j = 0; j < 16; j++) {
        int col = j * 32 + lane;
        float a2 = pb1[col];
        #pragma unroll
        for (int q = 0; q < 8; q++) a2 += z[q] * pW1[q * H_ + col];
        a2 = fmaxf(a2, 0.f);
        __nv_bfloat16 hi = __float2bfloat16(a2);
        __nv_bfloat16 lo = __float2bfloat16(a2 - __bfloat162float(hi));
        g_H1h[row * H_ + col] = hi;
        g_H1l[row * H_ + col] = lo;
    }
}

// ---------------- HMMA GEMM + fused LSTM epilogue -----------------------
// Block tile 64(M) x 64(N). M rows ordered b*4+gate -> tile = 16 full batches.
#define SROWB 144u
#define SM_AH 0u
#define SM_AL 9216u
#define SM_BH 18432u
#define SM_BL 27648u
#define BUFSZ 36864u
#define SMEM_DYN (2 * 36864)
#define EPAD 68

__device__ __forceinline__ float sigmoidf_(float x) { return 1.f / (1.f + expf(-x)); }

__global__ __launch_bounds__(128, 1) void gemm_lstm_kernel(
    const float* __restrict__ pb2,
    float* __restrict__ out_t,
    float* __restrict__ out_h, float* __restrict__ out_c)
{
    extern __shared__ __align__(16) char dsm[];
    uint32_t s0 = smem_u32(dsm);
    int tid = threadIdx.x, wid = tid >> 5, lane = tid & 31;
    int n0 = blockIdx.x * 64, m0 = blockIdx.y * 64;
    int wm = (wid >> 1) * 32, wn = (wid & 1) * 32;

    const __nv_bfloat16* Ah = g_H1h + (size_t)m0 * H_;
    const __nv_bfloat16* Al = g_H1l + (size_t)m0 * H_;
    const __nv_bfloat16* Bh = g_Bht + (size_t)n0 * H_;
    const __nv_bfloat16* Bl = g_Blt + (size_t)n0 * H_;

    int lrow[4], lkc[4];
    uint32_t ldst[4];
    #pragma unroll
    for (int j = 0; j < 4; j++) {
        int u = tid + 128 * j;
        lrow[j] = u >> 3; lkc[j] = (u & 7) * 8;
        ldst[j] = (uint32_t)lrow[j] * SROWB + (uint32_t)(u & 7) * 16u;
    }
    uint32_t aOff = (uint32_t)(wm + (lane & 15)) * SROWB + (uint32_t)((lane >> 4) << 4);
    uint32_t bOff = (uint32_t)(wn + (lane & 15)) * SROWB + (uint32_t)((lane >> 4) << 4);

    float acc[2][4][4];
    #pragma unroll
    for (int i = 0; i < 2; i++)
        #pragma unroll
        for (int j = 0; j < 4; j++)
            #pragma unroll
            for (int r = 0; r < 4; r++) acc[i][j][r] = 0.f;

    {
        uint32_t sb = s0;
        #pragma unroll
        for (int j = 0; j < 4; j++) {
            size_t go = (size_t)lrow[j] * H_ + lkc[j];
            cp16(sb + SM_AH + ldst[j], Ah + go);
            cp16(sb + SM_AL + ldst[j], Al + go);
            cp16(sb + SM_BH + ldst[j], Bh + go);
            cp16(sb + SM_BL + ldst[j], Bl + go);
        }
        CP_COMMIT();
    }

    for (int c = 0; c < 8; c++) {
        if (c + 1 < 8) {
            uint32_t sb = s0 + ((c + 1) & 1) * BUFSZ;
            int kb = (c + 1) * 64;
            #pragma unroll
            for (int j = 0; j < 4; j++) {
                size_t go = (size_t)lrow[j] * H_ + kb + lkc[j];
                cp16(sb + SM_AH + ldst[j], Ah + go);
                cp16(sb + SM_AL + ldst[j], Al + go);
                cp16(sb + SM_BH + ldst[j], Bh + go);
                cp16(sb + SM_BL + ldst[j], Bl + go);
            }
            CP_COMMIT();
            cp_wait<1>();
        } else {
            cp_wait<0>();
        }
        __syncthreads();

        uint32_t buf = s0 + (c & 1) * BUFSZ;
        #pragma unroll
        for (int kk = 0; kk < 4; kk++) {
            uint32_t kb = kk * 32;
            uint32_t ah[2][4], al[2][4], bh[2][4], bl[2][4];
            #pragma unroll
            for (int i = 0; i < 2; i++) {
                ldm4(buf + SM_AH + aOff + i * (16 * SROWB) + kb, ah[i]);
                ldm4(buf + SM_AL + aOff + i * (16 * SROWB) + kb, al[i]);
            }
            #pragma unroll
            for (int p = 0; p < 2; p++) {
                ldm4(buf + SM_BH + bOff + p * (16 * SROWB) + kb, bh[p]);
                ldm4(buf + SM_BL + bOff + p * (16 * SROWB) + kb, bl[p]);
            }
            #pragma unroll
            for (int i = 0; i < 2; i++) {
                #pragma unroll
                for (int j = 0; j < 4; j++) {
                    int p = j >> 1, s = j & 1;
                    mma_bf16(acc[i][j], ah[i], bh[p][s], bh[p][2 + s]);
                    mma_bf16(acc[i][j], ah[i], bl[p][s], bl[p][2 + s]);
                    mma_bf16(acc[i][j], al[i], bh[p][s], bh[p][2 + s]);
                }
            }
        }
        __syncthreads();
    }

    // ---- stage preact tile to smem ----
    float* sp = (float*)dsm;
    #pragma unroll
    for (int i = 0; i < 2; i++) {
        int r0 = wm + i * 16 + (lane >> 2);
        #pragma unroll
        for (int j = 0; j < 4; j++) {
            int cc = wn + j * 8 + (lane & 3) * 2;
            sp[r0 * EPAD + cc]           = acc[i][j][0];
            sp[r0 * EPAD + cc + 1]       = acc[i][j][1];
            sp[(r0 + 8) * EPAD + cc]     = acc[i][j][2];
            sp[(r0 + 8) * EPAD + cc + 1] = acc[i][j][3];
        }
    }
    __syncthreads();

    // ---- fused LSTM: 16 batches x 64 cols, 8 elems/thread ----
    #pragma unroll
    for (int j = 0; j < 8; j++) {
        int e = tid + 128 * j;
        int bi = e >> 6, col = e & 63;
        float bias = pb2[n0 + col];
        float fv = sigmoidf_(sp[(bi * 4 + 0) * EPAD + col] + bias);
        float iv = sigmoidf_(sp[(bi * 4 + 1) * EPAD + col] + bias);
        float uv = tanhf   (sp[(bi * 4 + 2) * EPAD + col] + bias);
        float ov = sigmoidf_(sp[(bi * 4 + 3) * EPAD + col] + bias);
        int batch = (m0 >> 2) + bi;
        int idx = batch * H_ + n0 + col;
        float c = fv * g_c[idx] + iv * uv;
        float h = ov * tanhf(c);
        g_c[idx] = c;
        g_h[idx] = h;
        out_t[idx] = h;
        if (out_h) { out_h[idx] = h; out_c[idx] = c; }
    }
}

// ---------------- host ----------------
extern "C" void kernel_launch(void* const* d_in, const int* in_sizes, int n_in,
                              void* d_out, int out_size) {
    const float* inputs = (const float*)d_in[0];
    const float* qpf = (const float*)d_in[1];
    const float* qpi = (const float*)d_in[2];
    const float* qpu = (const float*)d_in[3];
    const float* qpo = (const float*)d_in[4];
    const float* Wf  = (const float*)d_in[5];
    const float* bf  = (const float*)d_in[6];
    const float* Wi  = (const float*)d_in[7];
    const float* bi  = (const float*)d_in[8];
    const float* Wu  = (const float*)d_in[9];
    const float* bu  = (const float*)d_in[10];
    const float* Wo  = (const float*)d_in[11];
    const float* bo  = (const float*)d_in[12];
    const float* pW1 = (const float*)d_in[13];
    const float* pb1 = (const float*)d_in[14];
    const float* pW2 = (const float*)d_in[15];
    const float* pb2 = (const float*)d_in[16];
    float* out = (float*)d_out;

    cudaFuncSetAttribute(gemm_lstm_kernel, cudaFuncAttributeMaxDynamicSharedMemorySize, SMEM_DYN);

    init_kernel<<<(B_ * H_ + 255) / 256, 256>>>(qpf, qpi, qpu, qpo);
    bprep_kernel<<<(H_ * H_) / 256, 256>>>(pW2);
    xproj_kernel<<<(T_ * B_ * 32) / 256, 256>>>(inputs, Wf, Wi, Wu, Wo, bf, bi, bu, bo);

    for (int t = 0; t < T_; t++) {
        quantum_kernel<<<dim3(B_, 2), 64>>>(t, Wf, Wi, Wu, Wo, pW1, pb1);
        bool last = (t == T_ - 1);
        gemm_lstm_kernel<<<dim3(8, 16), 128, SMEM_DYN>>>(
            pb2,
            out + (size_t)t * B_ * H_,
            last ? out + (size_t)T_ * B_ * H_            : nullptr,
            last ? out + (size_t)T_ * B_ * H_ + B_ * H_  : nullptr);
    }
}

// round 6
// speedup vs baseline: 2.3801x; 1.0975x over previous
#include <cuda_runtime.h>
#include <cuda_bf16.h>
#include <math.h>
#include <stdint.h>

#define T_  64
#define B_  256
#define D_  512
#define H_  512

// ---------------- device scratch (allocation-free rule) ----------------
__device__ __nv_bfloat16 g_H1h[B_ * 4 * H_];   // hi(H1), row = b*4 + gate
__device__ __nv_bfloat16 g_H1l[B_ * 4 * H_];   // lo(H1)
__device__ __nv_bfloat16 g_Bht[H_ * H_];       // hi(pW2^T), [n][k]
__device__ __nv_bfloat16 g_Blt[H_ * H_];       // lo(pW2^T)
__device__ float g_c[B_ * H_];
__device__ float g_Xproj[T_ * B_ * 32];        // x_t @ W + b, [t*B+b][g*8+q]
__device__ float g_Zpart[8 * B_ * 32];         // per-n-tile partial h-projections
__device__ float g_Wh2t[H_ * 32];              // W[D+col][g*8+q] as [col][32]
__device__ float2 g_ry[4 * 2 * 8];             // (cy,sy) per (g,l,q)
__device__ float2 g_pl2[4 * 2 * 32];           // lane-deferred RZ phase per (g,l,lane)
__device__ float2 g_pr2[4 * 2 * 8];            // reg-deferred RZ phase per (g,l,r)
__device__ int g_barcnt;
__device__ volatile int g_bargen;

// ---------------- PTX helpers ----------------
__device__ __forceinline__ uint32_t smem_u32(const void* p) {
    uint32_t a;
    asm("{ .reg .u64 t; cvta.to.shared.u64 t, %1; cvt.u32.u64 %0, t; }" : "=r"(a) : "l"(p));
    return a;
}
__device__ __forceinline__ void cp16cg(uint32_t dst, const void* src) {
    asm volatile("cp.async.cg.shared.global [%0], [%1], 16;" :: "r"(dst), "l"(src) : "memory");
}
#define CP_COMMIT() asm volatile("cp.async.commit_group;" ::: "memory")
template<int N> __device__ __forceinline__ void cp_wait() {
    asm volatile("cp.async.wait_group %0;" :: "n"(N) : "memory");
}
__device__ __forceinline__ void ldm4(uint32_t addr, uint32_t* r) {
    asm volatile("ldmatrix.sync.aligned.m8n8.x4.shared.b16 {%0,%1,%2,%3}, [%4];"
        : "=r"(r[0]), "=r"(r[1]), "=r"(r[2]), "=r"(r[3]) : "r"(addr));
}
__device__ __forceinline__ void mma_bf16(float* c, const uint32_t* a, uint32_t b0, uint32_t b1) {
    asm volatile(
        "mma.sync.aligned.m16n8k16.row.col.f32.bf16.bf16.f32 "
        "{%0,%1,%2,%3}, {%4,%5,%6,%7}, {%8,%9}, {%0,%1,%2,%3};"
        : "+f"(c[0]), "+f"(c[1]), "+f"(c[2]), "+f"(c[3])
        : "r"(a[0]), "r"(a[1]), "r"(a[2]), "r"(a[3]), "r"(b0), "r"(b1));
}
__device__ __forceinline__ float sigmoidf_(float x) { return 1.f / (1.f + expf(-x)); }

// ---------------- grid barrier (all 128 blocks co-resident) ----------------
__device__ __forceinline__ void gridbar() {
    __syncthreads();
    if (threadIdx.x == 0) {
        __threadfence();
        int gen = g_bargen;
        if (atomicAdd(&g_barcnt, 1) == (int)gridDim.x - 1) {
            g_barcnt = 0;
            __threadfence();
            g_bargen = gen + 1;
        } else {
            while (g_bargen == gen) __nanosleep(32);
        }
    }
    __syncthreads();
}

// ---------------- prep kernels ----------------
// pW2 (K,N) -> transposed bf16 hi/lo [n][k]
__global__ void bprep_kernel(const float* __restrict__ pW2) {
    int i = blockIdx.x * blockDim.x + threadIdx.x;
    int n = i >> 9, k = i & 511;
    float v = pW2[k * H_ + n];
    __nv_bfloat16 hi = __float2bfloat16(v);
    __nv_bfloat16 lo = __float2bfloat16(v - __bfloat162float(hi));
    g_Bht[i] = hi; g_Blt[i] = lo;
}

// Wh2t[col][o] = W_g[D+col][q],  o = g*8+q
__global__ void whprep_kernel(
    const float* __restrict__ Wf, const float* __restrict__ Wi,
    const float* __restrict__ Wu, const float* __restrict__ Wo)
{
    int i = blockIdx.x * blockDim.x + threadIdx.x;  // col*32 + o
    int col = i >> 5, o = i & 31, g = o >> 3, q = o & 7;
    const float* W = (g == 0) ? Wf : (g == 1) ? Wi : (g == 2) ? Wu : Wo;
    g_Wh2t[i] = W[(D_ + col) * 8 + q];
}

// trig + deferred-phase tables
__global__ void tabprep_kernel(
    const float* __restrict__ qpf, const float* __restrict__ qpi,
    const float* __restrict__ qpu, const float* __restrict__ qpo)
{
    int i = threadIdx.x;   // 0..255
    const float* qps[4] = {qpf, qpi, qpu, qpo};
    if (i < 64) {
        int g = i >> 4, l = (i >> 3) & 1, q = i & 7;
        const float* qp = qps[g];
        float th = qp[(l * 8 + q) * 3 + 0] * 0.5f;
        g_ry[i] = make_float2(cosf(th), sinf(th));
        // reg-phase product over qubits 5..7, r = q slot reuse
        int r = q;
        float prr = 1.f, pri = 0.f;
        #pragma unroll
        for (int qq = 5; qq < 8; qq++) {
            float tz = qp[(l * 8 + qq) * 3 + 1] * 0.5f;
            float cz = cosf(tz), sz = sinf(tz);
            float zn = ((r >> (7 - qq)) & 1) ? sz : -sz;
            float nr = prr * cz - pri * zn;
            float ni = prr * zn + pri * cz;
            prr = nr; pri = ni;
        }
        g_pr2[i] = make_float2(prr, pri);
    }
    {
        int g = i >> 6, l = (i >> 5) & 1, ln = i & 31;
        const float* qp = qps[g];
        float prr = 1.f, pri = 0.f;
        #pragma unroll
        for (int q = 0; q < 5; q++) {
            float tz = qp[(l * 8 + q) * 3 + 1] * 0.5f;
            float cz = cosf(tz), sz = sinf(tz);
            float zn = ((ln >> (4 - q)) & 1) ? sz : -sz;
            float nr = prr * cz - pri * zn;
            float ni = prr * zn + pri * cz;
            prr = nr; pri = ni;
        }
        g_pl2[i] = make_float2(prr, pri);
    }
}

// Xproj[row][g*8+q] = x[row] . W_g[:D, q] + b_g[q],  row = t*B+b
__global__ __launch_bounds__(256) void xproj_kernel(
    const float* __restrict__ inputs,
    const float* __restrict__ Wf, const float* __restrict__ Wi,
    const float* __restrict__ Wu, const float* __restrict__ Wo,
    const float* __restrict__ bf, const float* __restrict__ bi,
    const float* __restrict__ bu, const float* __restrict__ bo)
{
    int tid = blockIdx.x * 256 + threadIdx.x;
    int row = tid >> 5;
    int o = tid & 31, g = o >> 3, q = o & 7;
    const float* W  = (g == 0) ? Wf : (g == 1) ? Wi : (g == 2) ? Wu : Wo;
    const float* bb = (g == 0) ? bf : (g == 1) ? bi : (g == 2) ? bu : bo;
    const float* x = inputs + (size_t)row * D_;
    float acc = bb[q];
    #pragma unroll 8
    for (int k = 0; k < D_; k++) acc += x[k] * W[k * 8 + q];
    g_Xproj[row * 32 + o] = acc;
}

// ---------------- the persistent recurrence kernel ----------------
#define SROWB 144u
#define SM_AH 0u
#define SM_AL 9216u
#define SM_BH 18432u
#define SM_BL 27648u
#define BUFSZ 36864u
#define SMEM_DYN (2 * 36864)
#define EPAD 68
#define HOFF 32768

__global__ __launch_bounds__(256, 1) void qlstm_kernel(
    const float* __restrict__ pW1, const float* __restrict__ pb1,
    const float* __restrict__ pb2, float* __restrict__ out)
{
    extern __shared__ __align__(16) char dsm[];
    const unsigned FULL = 0xffffffffu;
    uint32_t s0 = smem_u32(dsm);
    int tid = threadIdx.x, wid = tid >> 5, lane = tid & 31;
    int bid = blockIdx.x;
    int nt = bid & 7, mt = bid >> 3;
    int n0 = nt * 64, m0 = mt * 64;

    // quantum identity for this warp
    int sidx = bid * 8 + wid;          // 0..1023
    int qb = sidx >> 2, qg = sidx & 3;

    // ---- init: zero Zpart + this block's c tile ----
    g_Zpart[bid * 512 + tid] = 0.f;
    g_Zpart[bid * 512 + 256 + tid] = 0.f;
    #pragma unroll
    for (int jj = 0; jj < 4; jj++) {
        int e = tid + 256 * jj;
        g_c[(mt * 16 + (e >> 6)) * H_ + n0 + (e & 63)] = 0.f;
    }
    gridbar();

    // ---- hoisted GEMM constants ----
    const __nv_bfloat16* Ah = g_H1h + (size_t)m0 * H_;
    const __nv_bfloat16* Al = g_H1l + (size_t)m0 * H_;
    const __nv_bfloat16* Bh = g_Bht + (size_t)n0 * H_;
    const __nv_bfloat16* Bl = g_Blt + (size_t)n0 * H_;
    int wm = (wid >> 1) * 16, wn = (wid & 1) * 32;
    uint32_t aOff = (uint32_t)(wm + (lane & 15)) * SROWB + (uint32_t)((lane >> 4) << 4);
    uint32_t bOff = (uint32_t)(wn + (lane & 15)) * SROWB + (uint32_t)((lane >> 4) << 4);
    int lrow0 = tid >> 3,        lun0 = tid & 7;
    int lrow1 = (tid + 256) >> 3, lun1 = (tid + 256) & 7;
    uint32_t ld0 = (uint32_t)lrow0 * SROWB + (uint32_t)lun0 * 16u;
    uint32_t ld1 = (uint32_t)lrow1 * SROWB + (uint32_t)lun1 * 16u;

    const float2* ryp = g_ry + qg * 16;
    const float2* prp = g_pr2 + qg * 16;

    for (int t = 0; t < T_; t++) {
        // ================= Q phase: quantum sim for (qb, qg) =================
        {
            float a = 0.f;
            if (lane < 8) {
                float zacc = 0.f;
                const float* zp = g_Zpart + qb * 32 + qg * 8 + lane;
                #pragma unroll
                for (int p = 0; p < 8; p++) zacc += __ldcg(zp + p * (B_ * 32));
                a = zacc + g_Xproj[((t * B_ + qb) * 4 + qg) * 8 + lane];
            }
            float sv, cv;
            __sincosf(a * 0.5f, &sv, &cv);

            float re[8], im[8];
            #pragma unroll
            for (int r = 0; r < 8; r++) { re[r] = 0.f; im[r] = 0.f; }
            if (lane == 0) re[0] = 1.f;

            // RX per qubit
            #pragma unroll
            for (int q = 0; q < 5; q++) {
                int d = 16 >> q;
                float c = __shfl_sync(FULL, cv, q);
                float s = __shfl_sync(FULL, sv, q);
                #pragma unroll
                for (int r = 0; r < 8; r++) {
                    float pr = __shfl_xor_sync(FULL, re[r], d);
                    float pi = __shfl_xor_sync(FULL, im[r], d);
                    re[r] = c * re[r] + s * pi;
                    im[r] = c * im[r] - s * pr;
                }
            }
            #pragma unroll
            for (int q = 5; q < 8; q++) {
                int str = 1 << (7 - q);
                float c = __shfl_sync(FULL, cv, q);
                float s = __shfl_sync(FULL, sv, q);
                #pragma unroll
                for (int a0 = 0; a0 < 8; a0++) {
                    if (a0 & str) continue;
                    int b0 = a0 | str;
                    float tr0 = re[a0], ti0 = im[a0], tr1 = re[b0], ti1 = im[b0];
                    re[a0] = c * tr0 + s * ti1;
                    im[a0] = c * ti0 - s * tr1;
                    re[b0] = c * tr1 + s * ti0;
                    im[b0] = c * ti1 - s * tr0;
                }
            }

            // 2 layers: RY all qubits, deferred RZ (layer 0 only), CNOT chain
            #pragma unroll
            for (int l = 0; l < 2; l++) {
                #pragma unroll
                for (int q = 0; q < 5; q++) {
                    float2 ys = ryp[l * 8 + q];
                    int d = 16 >> q;
                    int hi = (lane >> (4 - q)) & 1;
                    float sgn = hi ? ys.y : -ys.y;
                    #pragma unroll
                    for (int r = 0; r < 8; r++) {
                        float pr = __shfl_xor_sync(FULL, re[r], d);
                        float pi = __shfl_xor_sync(FULL, im[r], d);
                        re[r] = ys.x * re[r] + sgn * pr;
                        im[r] = ys.x * im[r] + sgn * pi;
                    }
                }
                #pragma unroll
                for (int q = 5; q < 8; q++) {
                    float2 ys = ryp[l * 8 + q];
                    int str = 1 << (7 - q);
                    #pragma unroll
                    for (int a0 = 0; a0 < 8; a0++) {
                        if (a0 & str) continue;
                        int b0 = a0 | str;
                        float tr0 = re[a0], ti0 = im[a0], tr1 = re[b0], ti1 = im[b0];
                        re[a0] = ys.x * tr0 - ys.y * tr1;
                        im[a0] = ys.x * ti0 - ys.y * ti1;
                        re[b0] = ys.y * tr0 + ys.x * tr1;
                        im[b0] = ys.y * ti0 + ys.x * ti1;
                    }
                }
                if (l == 0) {
                    // apply deferred RZ phases (layer-1 RZ provably cancels in |amp|^2)
                    float2 pl = g_pl2[(qg * 2 + l) * 32 + lane];
                    #pragma unroll
                    for (int r = 0; r < 8; r++) {
                        float nr = pl.x * re[r] - pl.y * im[r];
                        im[r] = pl.x * im[r] + pl.y * re[r];
                        re[r] = nr;
                    }
                    #pragma unroll
                    for (int r = 0; r < 8; r++) {
                        float2 pq = prp[l * 8 + r];
                        float nr = pq.x * re[r] - pq.y * im[r];
                        im[r] = pq.x * im[r] + pq.y * re[r];
                        re[r] = nr;
                    }
                }
                // CNOT chain
                #pragma unroll
                for (int ct = 0; ct < 4; ct++) {
                    int d = 8 >> ct, cb = 4 - ct;
                    int cbit = (lane >> cb) & 1;
                    #pragma unroll
                    for (int r = 0; r < 8; r++) {
                        float pr = __shfl_xor_sync(FULL, re[r], d);
                        float pi = __shfl_xor_sync(FULL, im[r], d);
                        re[r] = cbit ? pr : re[r];
                        im[r] = cbit ? pi : im[r];
                    }
                }
                {
                    int cbit = lane & 1;
                    #pragma unroll
                    for (int r = 0; r < 4; r++) {
                        float t1 = re[r], t2 = re[r + 4];
                        re[r]     = cbit ? t2 : t1;
                        re[r + 4] = cbit ? t1 : t2;
                        t1 = im[r]; t2 = im[r + 4];
                        im[r]     = cbit ? t2 : t1;
                        im[r + 4] = cbit ? t1 : t2;
                    }
                }
                {
                    float tt;
                    tt = re[4]; re[4] = re[6]; re[6] = tt;
                    tt = re[5]; re[5] = re[7]; re[7] = tt;
                    tt = im[4]; im[4] = im[6]; im[6] = tt;
                    tt = im[5]; im[5] = im[7]; im[7] = tt;
                }
                {
                    float tt;
                    tt = re[2]; re[2] = re[3]; re[3] = tt;
                    tt = re[6]; re[6] = re[7]; re[7] = tt;
                    tt = im[2]; im[2] = im[3]; im[3] = tt;
                    tt = im[6]; im[6] = im[7]; im[7] = tt;
                }
            }

            // measure Z
            float p0 = re[0]*re[0]+im[0]*im[0], p1 = re[1]*re[1]+im[1]*im[1];
            float p2 = re[2]*re[2]+im[2]*im[2], p3 = re[3]*re[3]+im[3]*im[3];
            float p4 = re[4]*re[4]+im[4]*im[4], p5 = re[5]*re[5]+im[5]*im[5];
            float p6 = re[6]*re[6]+im[6]*im[6], p7 = re[7]*re[7]+im[7]*im[7];
            float S = p0+p1+p2+p3+p4+p5+p6+p7;
            float z[8];
            #pragma unroll
            for (int q = 0; q < 5; q++)
                z[q] = ((lane >> (4 - q)) & 1) ? -S : S;
            z[5] = (p0+p1+p2+p3) - (p4+p5+p6+p7);
            z[6] = (p0+p1+p4+p5) - (p2+p3+p6+p7);
            z[7] = (p0+p2+p4+p6) - (p1+p3+p5+p7);
            #pragma unroll
            for (int q = 0; q < 8; q++) {
                #pragma unroll
                for (int o = 16; o; o >>= 1) z[q] += __shfl_xor_sync(FULL, z[q], o);
            }

            // H1 = relu(z @ pW1 + pb1) -> bf16 hi/lo, row = qb*4 + qg
            int row = qb * 4 + qg;
            #pragma unroll
            for (int j = 0; j < 16; j++) {
                int col = j * 32 + lane;
                float a2 = pb1[col];
                #pragma unroll
                for (int q = 0; q < 8; q++) a2 += z[q] * pW1[q * H_ + col];
                a2 = fmaxf(a2, 0.f);
                __nv_bfloat16 hi = __float2bfloat16(a2);
                __nv_bfloat16 lo = __float2bfloat16(a2 - __bfloat162float(hi));
                g_H1h[row * H_ + col] = hi;
                g_H1l[row * H_ + col] = lo;
            }
        }
        gridbar();

        // ================= G phase: GEMM + LSTM + h-projection =================
        {
            float* outt = out + (size_t)t * (B_ * H_);
            // prefetch chunk 0
            {
                size_t g0 = (size_t)lrow0 * H_ + lun0 * 8;
                size_t g1 = (size_t)lrow1 * H_ + lun1 * 8;
                cp16cg(s0 + SM_AH + ld0, Ah + g0); cp16cg(s0 + SM_AH + ld1, Ah + g1);
                cp16cg(s0 + SM_AL + ld0, Al + g0); cp16cg(s0 + SM_AL + ld1, Al + g1);
                cp16cg(s0 + SM_BH + ld0, Bh + g0); cp16cg(s0 + SM_BH + ld1, Bh + g1);
                cp16cg(s0 + SM_BL + ld0, Bl + g0); cp16cg(s0 + SM_BL + ld1, Bl + g1);
                CP_COMMIT();
            }
            float acc[4][4];
            #pragma unroll
            for (int j = 0; j < 4; j++)
                #pragma unroll
                for (int r = 0; r < 4; r++) acc[j][r] = 0.f;

            for (int c = 0; c < 8; c++) {
                if (c + 1 < 8) {
                    uint32_t sb = s0 + ((c + 1) & 1) * BUFSZ;
                    int kb = (c + 1) * 64;
                    size_t g0 = (size_t)lrow0 * H_ + kb + lun0 * 8;
                    size_t g1 = (size_t)lrow1 * H_ + kb + lun1 * 8;
                    cp16cg(sb + SM_AH + ld0, Ah + g0); cp16cg(sb + SM_AH + ld1, Ah + g1);
                    cp16cg(sb + SM_AL + ld0, Al + g0); cp16cg(sb + SM_AL + ld1, Al + g1);
                    cp16cg(sb + SM_BH + ld0, Bh + g0); cp16cg(sb + SM_BH + ld1, Bh + g1);
                    cp16cg(sb + SM_BL + ld0, Bl + g0); cp16cg(sb + SM_BL + ld1, Bl + g1);
                    CP_COMMIT();
                    cp_wait<1>();
                } else {
                    cp_wait<0>();
                }
                __syncthreads();

                uint32_t buf = s0 + (c & 1) * BUFSZ;
                #pragma unroll
                for (int kk = 0; kk < 4; kk++) {
                    uint32_t kb2 = kk * 32;
                    uint32_t ahf[4], alf[4], bhf[2][4], blf[2][4];
                    ldm4(buf + SM_AH + aOff + kb2, ahf);
                    ldm4(buf + SM_AL + aOff + kb2, alf);
                    ldm4(buf + SM_BH + bOff + kb2, bhf[0]);
                    ldm4(buf + SM_BH + bOff + 16 * SROWB + kb2, bhf[1]);
                    ldm4(buf + SM_BL + bOff + kb2, blf[0]);
                    ldm4(buf + SM_BL + bOff + 16 * SROWB + kb2, blf[1]);
                    #pragma unroll
                    for (int j = 0; j < 4; j++) {
                        int p = j >> 1, sb2 = j & 1;
                        mma_bf16(acc[j], ahf, bhf[p][sb2], bhf[p][2 + sb2]);
                        mma_bf16(acc[j], ahf, blf[p][sb2], blf[p][2 + sb2]);
                        mma_bf16(acc[j], alf, bhf[p][sb2], bhf[p][2 + sb2]);
                    }
                }
                __syncthreads();
            }

            // stage preact to smem
            float* sp = (float*)dsm;
            int r0 = wm + (lane >> 2);
            #pragma unroll
            for (int j = 0; j < 4; j++) {
                int cc = wn + j * 8 + (lane & 3) * 2;
                sp[r0 * EPAD + cc]           = acc[j][0];
                sp[r0 * EPAD + cc + 1]       = acc[j][1];
                sp[(r0 + 8) * EPAD + cc]     = acc[j][2];
                sp[(r0 + 8) * EPAD + cc + 1] = acc[j][3];
            }
            __syncthreads();

            // fused LSTM (16 batches x 64 cols), stage h for projection
            float* hs = (float*)(dsm + HOFF);
            bool last = (t == T_ - 1);
            #pragma unroll
            for (int jj = 0; jj < 4; jj++) {
                int e = tid + 256 * jj;
                int bi = e >> 6, col = e & 63;
                float bias = pb2[n0 + col];
                float fv = sigmoidf_(sp[(bi * 4 + 0) * EPAD + col] + bias);
                float iv = sigmoidf_(sp[(bi * 4 + 1) * EPAD + col] + bias);
                float uv = tanhf   (sp[(bi * 4 + 2) * EPAD + col] + bias);
                float ov = sigmoidf_(sp[(bi * 4 + 3) * EPAD + col] + bias);
                int batch = mt * 16 + bi;
                int idx = batch * H_ + n0 + col;
                float cc2 = fv * g_c[idx] + iv * uv;
                float hh2 = ov * tanhf(cc2);
                g_c[idx] = cc2;
                outt[idx] = hh2;
                hs[bi * 64 + col] = hh2;
                if (last) {
                    out[(size_t)T_ * B_ * H_ + idx] = hh2;
                    out[(size_t)T_ * B_ * H_ + B_ * H_ + idx] = cc2;
                }
            }
            __syncthreads();

            // h-projection partials: Zpart[nt][batch][o] = sum_cols h * Wh2t
            #pragma unroll
            for (int jj = 0; jj < 2; jj++) {
                int idx2 = tid + 256 * jj;    // 0..511
                int bi = idx2 >> 5, o = idx2 & 31;
                const float* hh = hs + bi * 64;
                const float* wr = g_Wh2t + (size_t)n0 * 32 + o;
                float sacc = 0.f;
                #pragma unroll 16
                for (int c2 = 0; c2 < 64; c2++) sacc += hh[c2] * wr[c2 * 32];
                __stcg(g_Zpart + nt * (B_ * 32) + (mt * 16 + bi) * 32 + o, sacc);
            }
        }
        if (t < T_ - 1) gridbar();
    }
}

// ---------------- host ----------------
extern "C" void kernel_launch(void* const* d_in, const int* in_sizes, int n_in,
                              void* d_out, int out_size) {
    const float* inputs = (const float*)d_in[0];
    const float* qpf = (const float*)d_in[1];
    const float* qpi = (const float*)d_in[2];
    const float* qpu = (const float*)d_in[3];
    const float* qpo = (const float*)d_in[4];
    const float* Wf  = (const float*)d_in[5];
    const float* bf  = (const float*)d_in[6];
    const float* Wi  = (const float*)d_in[7];
    const float* bi  = (const float*)d_in[8];
    const float* Wu  = (const float*)d_in[9];
    const float* bu  = (const float*)d_in[10];
    const float* Wo  = (const float*)d_in[11];
    const float* bo  = (const float*)d_in[12];
    const float* pW1 = (const float*)d_in[13];
    const float* pb1 = (const float*)d_in[14];
    const float* pW2 = (const float*)d_in[15];
    const float* pb2 = (const float*)d_in[16];
    float* out = (float*)d_out;

    cudaFuncSetAttribute(qlstm_kernel, cudaFuncAttributeMaxDynamicSharedMemorySize, SMEM_DYN);

    bprep_kernel<<<(H_ * H_) / 256, 256>>>(pW2);
    whprep_kernel<<<(H_ * 32) / 256, 256>>>(Wf, Wi, Wu, Wo);
    tabprep_kernel<<<1, 256>>>(qpf, qpi, qpu, qpo);
    xproj_kernel<<<(T_ * B_ * 32) / 256, 256>>>(inputs, Wf, Wi, Wu, Wo, bf, bi, bu, bo);
    qlstm_kernel<<<128, 256, SMEM_DYN>>>(pW1, pb1, pb2, out);
}

// round 8
// speedup vs baseline: 2.4412x; 1.0257x over previous
#include <cuda_runtime.h>
#include <cuda_bf16.h>
#include <math.h>
#include <stdint.h>

#define T_  64
#define B_  256
#define D_  512
#define H_  512

// ---------------- device scratch (allocation-free rule) ----------------
__device__ __nv_bfloat16 g_H1h[B_ * 4 * H_];   // hi(H1), row = b*4 + gate
__device__ __nv_bfloat16 g_H1l[B_ * 4 * H_];   // lo(H1)
__device__ __nv_bfloat16 g_Bht[H_ * H_];       // hi(pW2^T), [n][k]
__device__ __nv_bfloat16 g_Blt[H_ * H_];       // lo(pW2^T)
__device__ float g_c[B_ * H_];
__device__ float g_Xproj[T_ * B_ * 32];        // x_t @ W + b, [t*B+b][g*8+q]
__device__ float g_Zpart[8 * B_ * 32];         // per-n-tile partial h-projections
__device__ float g_Wh2t[H_ * 32];              // W[D+col][g*8+q] as [col][32]
__device__ float2 g_ry[4 * 2 * 8];             // (cy,sy) per (g,l,q)
__device__ float2 g_pl2[4 * 2 * 32];           // lane-deferred RZ phase per (g,l,lane)
__device__ float2 g_pr2[4 * 2 * 8];            // reg-deferred RZ phase per (g,l,r)
__device__ int g_gcnt[16];
__device__ volatile int g_ggen[16];

// ---------------- PTX helpers ----------------
__device__ __forceinline__ uint32_t smem_u32(const void* p) {
    uint32_t a;
    asm("{ .reg .u64 t; cvta.to.shared.u64 t, %1; cvt.u32.u64 %0, t; }" : "=r"(a) : "l"(p));
    return a;
}
__device__ __forceinline__ void cp16cg(uint32_t dst, const void* src) {
    asm volatile("cp.async.cg.shared.global [%0], [%1], 16;" :: "r"(dst), "l"(src) : "memory");
}
#define CP_COMMIT() asm volatile("cp.async.commit_group;" ::: "memory")
template<int N> __device__ __forceinline__ void cp_wait() {
    asm volatile("cp.async.wait_group %0;" :: "n"(N) : "memory");
}
__device__ __forceinline__ void ldm4(uint32_t addr, uint32_t* r) {
    asm volatile("ldmatrix.sync.aligned.m8n8.x4.shared.b16 {%0,%1,%2,%3}, [%4];"
        : "=r"(r[0]), "=r"(r[1]), "=r"(r[2]), "=r"(r[3]) : "r"(addr));
}
__device__ __forceinline__ void mma_bf16(float* c, const uint32_t* a, uint32_t b0, uint32_t b1) {
    asm volatile(
        "mma.sync.aligned.m16n8k16.row.col.f32.bf16.bf16.f32 "
        "{%0,%1,%2,%3}, {%4,%5,%6,%7}, {%8,%9}, {%0,%1,%2,%3};"
        : "+f"(c[0]), "+f"(c[1]), "+f"(c[2]), "+f"(c[3])
        : "r"(a[0]), "r"(a[1]), "r"(a[2]), "r"(a[3]), "r"(b0), "r"(b1));
}
__device__ __forceinline__ float sigmoidf_(float x) { return 1.f / (1.f + expf(-x)); }

// ---------------- group barrier: 8 blocks (one m-tile group) ----------------
__device__ __forceinline__ void groupbar(int grp) {
    __syncthreads();
    if (threadIdx.x == 0) {
        __threadfence();
        int gen = g_ggen[grp];
        if (atomicAdd(&g_gcnt[grp], 1) == 7) {
            g_gcnt[grp] = 0;
            __threadfence();
            g_ggen[grp] = gen + 1;
        } else {
            while (g_ggen[grp] == gen) __nanosleep(20);
        }
    }
    __syncthreads();
}

// ---------------- prep kernels ----------------
// pW2 (K,N) -> transposed bf16 hi/lo [n][k]
__global__ void bprep_kernel(const float* __restrict__ pW2) {
    int i = blockIdx.x * blockDim.x + threadIdx.x;
    int n = i >> 9, k = i & 511;
    float v = pW2[k * H_ + n];
    __nv_bfloat16 hi = __float2bfloat16(v);
    __nv_bfloat16 lo = __float2bfloat16(v - __bfloat162float(hi));
    g_Bht[i] = hi; g_Blt[i] = lo;
}

// Wh2t[col][o] = W_g[D+col][q],  o = g*8+q
__global__ void whprep_kernel(
    const float* __restrict__ Wf, const float* __restrict__ Wi,
    const float* __restrict__ Wu, const float* __restrict__ Wo)
{
    int i = blockIdx.x * blockDim.x + threadIdx.x;
    int col = i >> 5, o = i & 31, g = o >> 3, q = o & 7;
    const float* W = (g == 0) ? Wf : (g == 1) ? Wi : (g == 2) ? Wu : Wo;
    g_Wh2t[i] = W[(D_ + col) * 8 + q];
}

// trig + deferred-phase tables
__global__ void tabprep_kernel(
    const float* __restrict__ qpf, const float* __restrict__ qpi,
    const float* __restrict__ qpu, const float* __restrict__ qpo)
{
    int i = threadIdx.x;   // 0..255
    const float* qps[4] = {qpf, qpi, qpu, qpo};
    if (i < 64) {
        int g = i >> 4, l = (i >> 3) & 1, q = i & 7;
        const float* qp = qps[g];
        float th = qp[(l * 8 + q) * 3 + 0] * 0.5f;
        g_ry[i] = make_float2(cosf(th), sinf(th));
        int r = q;
        float prr = 1.f, pri = 0.f;
        #pragma unroll
        for (int qq = 5; qq < 8; qq++) {
            float tz = qp[(l * 8 + qq) * 3 + 1] * 0.5f;
            float cz = cosf(tz), sz = sinf(tz);
            float zn = ((r >> (7 - qq)) & 1) ? sz : -sz;
            float nr = prr * cz - pri * zn;
            float ni = prr * zn + pri * cz;
            prr = nr; pri = ni;
        }
        g_pr2[i] = make_float2(prr, pri);
    }
    {
        int g = i >> 6, l = (i >> 5) & 1, ln = i & 31;
        const float* qp = qps[g];
        float prr = 1.f, pri = 0.f;
        #pragma unroll
        for (int q = 0; q < 5; q++) {
            float tz = qp[(l * 8 + q) * 3 + 1] * 0.5f;
            float cz = cosf(tz), sz = sinf(tz);
            float zn = ((ln >> (4 - q)) & 1) ? sz : -sz;
            float nr = prr * cz - pri * zn;
            float ni = prr * zn + pri * cz;
            prr = nr; pri = ni;
        }
        g_pl2[i] = make_float2(prr, pri);
    }
}

// xproj v2: W staged in smem [k][33], warp-per-row, lane = output column.
// Xproj[row][o] = x[row] . W_g[:D, q] + b_g[q],  o = g*8+q, row = t*B+b
#define XP_SMEM (512 * 33 * 4)
__global__ __launch_bounds__(256) void xproj_kernel(
    const float* __restrict__ inputs,
    const float* __restrict__ Wf, const float* __restrict__ Wi,
    const float* __restrict__ Wu, const float* __restrict__ Wo,
    const float* __restrict__ bf, const float* __restrict__ bi,
    const float* __restrict__ bu, const float* __restrict__ bo)
{
    extern __shared__ float Ws[];   // [512][33]
    int tid = threadIdx.x, warp = tid >> 5, lane = tid & 31;
    int g = lane >> 3, q = lane & 7;
    const float* Wsel = (g == 0) ? Wf : (g == 1) ? Wi : (g == 2) ? Wu : Wo;
    const float* bsel = (g == 0) ? bf : (g == 1) ? bi : (g == 2) ? bu : bo;

    for (int k = warp; k < 512; k += 8)
        Ws[k * 33 + lane] = Wsel[k * 8 + q];
    __syncthreads();

    float bias = bsel[q];
    int row0 = blockIdx.x * 32 + warp * 4;
    #pragma unroll
    for (int rr = 0; rr < 4; rr++) {
        int row = row0 + rr;
        const float4* x4 = (const float4*)(inputs + (size_t)row * D_);
        float acc = bias;
        #pragma unroll 4
        for (int k4 = 0; k4 < 128; k4++) {
            float4 xv = x4[k4];
            const float* wk = Ws + (k4 * 4) * 33 + lane;
            acc += xv.x * wk[0];
            acc += xv.y * wk[33];
            acc += xv.z * wk[66];
            acc += xv.w * wk[99];
        }
        g_Xproj[row * 32 + lane] = acc;
    }
}

// ---------------- the persistent recurrence kernel ----------------
#define SROWB 144u
#define SM_AH 0u
#define SM_AL 9216u
#define SM_BH 18432u
#define SM_BL 27648u
#define BUFSZ 36864u
#define SMEM_DYN (2 * 36864)
#define EPAD 68
#define HOFF 32768

__global__ __launch_bounds__(256, 1) void qlstm_kernel(
    const float* __restrict__ pW1, const float* __restrict__ pb1,
    const float* __restrict__ pb2, float* __restrict__ out)
{
    extern __shared__ __align__(16) char dsm[];
    const unsigned FULL = 0xffffffffu;
    uint32_t s0 = smem_u32(dsm);
    int tid = threadIdx.x, wid = tid >> 5, lane = tid & 31;
    int bid = blockIdx.x;
    int nt = bid & 7, mt = bid >> 3;
    int grp = mt;                       // group = the 8 blocks sharing mt
    int n0 = nt * 64, m0 = mt * 64;

    int sidx = bid * 8 + wid;
    int qb = sidx >> 2, qg = sidx & 3;  // qb in [mt*16, mt*16+16)

    // ---- init: zero this block's Zpart slices (batches bid*2, bid*2+1) + c tile
    if (tid < 64) {
        #pragma unroll
        for (int p = 0; p < 8; p++)
            __stcg(g_Zpart + p * (B_ * 32) + bid * 64 + tid, 0.f);
    }
    #pragma unroll
    for (int jj = 0; jj < 4; jj++) {
        int e = tid + 256 * jj;
        g_c[(mt * 16 + (e >> 6)) * H_ + n0 + (e & 63)] = 0.f;
    }
    groupbar(grp);

    // ---- hoisted GEMM constants ----
    const __nv_bfloat16* Ah = g_H1h + (size_t)m0 * H_;
    const __nv_bfloat16* Al = g_H1l + (size_t)m0 * H_;
    const __nv_bfloat16* Bh = g_Bht + (size_t)n0 * H_;
    const __nv_bfloat16* Bl = g_Blt + (size_t)n0 * H_;
    int wm = (wid >> 1) * 16, wn = (wid & 1) * 32;
    uint32_t aOff = (uint32_t)(wm + (lane & 15)) * SROWB + (uint32_t)((lane >> 4) << 4);
    uint32_t bOff = (uint32_t)(wn + (lane & 15)) * SROWB + (uint32_t)((lane >> 4) << 4);
    int lrow0 = tid >> 3,         lun0 = tid & 7;
    int lrow1 = (tid + 256) >> 3, lun1 = (tid + 256) & 7;
    uint32_t ld0 = (uint32_t)lrow0 * SROWB + (uint32_t)lun0 * 16u;
    uint32_t ld1 = (uint32_t)lrow1 * SROWB + (uint32_t)lun1 * 16u;

    const float2* ryp = g_ry + qg * 16;
    const float2* prp = g_pr2 + qg * 16;

    for (int t = 0; t < T_; t++) {
        // ================= Q phase =================
        {
            float a = 0.f;
            if (lane < 8) {
                float zacc = 0.f;
                const float* zp = g_Zpart + qb * 32 + qg * 8 + lane;
                #pragma unroll
                for (int p = 0; p < 8; p++) zacc += __ldcg(zp + p * (B_ * 32));
                a = zacc + g_Xproj[((t * B_ + qb) * 4 + qg) * 8 + lane];
            }
            float sv, cv;
            __sincosf(a * 0.5f, &sv, &cv);

            float re[8], im[8];
            #pragma unroll
            for (int r = 0; r < 8; r++) { re[r] = 0.f; im[r] = 0.f; }
            if (lane == 0) re[0] = 1.f;

            #pragma unroll
            for (int q = 0; q < 5; q++) {
                int d = 16 >> q;
                float c = __shfl_sync(FULL, cv, q);
                float s = __shfl_sync(FULL, sv, q);
                #pragma unroll
                for (int r = 0; r < 8; r++) {
                    float pr = __shfl_xor_sync(FULL, re[r], d);
                    float pi = __shfl_xor_sync(FULL, im[r], d);
                    re[r] = c * re[r] + s * pi;
                    im[r] = c * im[r] - s * pr;
                }
            }
            #pragma unroll
            for (int q = 5; q < 8; q++) {
                int str = 1 << (7 - q);
                float c = __shfl_sync(FULL, cv, q);
                float s = __shfl_sync(FULL, sv, q);
                #pragma unroll
                for (int a0 = 0; a0 < 8; a0++) {
                    if (a0 & str) continue;
                    int b0 = a0 | str;
                    float tr0 = re[a0], ti0 = im[a0], tr1 = re[b0], ti1 = im[b0];
                    re[a0] = c * tr0 + s * ti1;
                    im[a0] = c * ti0 - s * tr1;
                    re[b0] = c * tr1 + s * ti0;
                    im[b0] = c * ti1 - s * tr0;
                }
            }

            #pragma unroll
            for (int l = 0; l < 2; l++) {
                #pragma unroll
                for (int q = 0; q < 5; q++) {
                    float2 ys = ryp[l * 8 + q];
                    int d = 16 >> q;
                    int hi = (lane >> (4 - q)) & 1;
                    float sgn = hi ? ys.y : -ys.y;
                    #pragma unroll
                    for (int r = 0; r < 8; r++) {
                        float pr = __shfl_xor_sync(FULL, re[r], d);
                        float pi = __shfl_xor_sync(FULL, im[r], d);
                        re[r] = ys.x * re[r] + sgn * pr;
                        im[r] = ys.x * im[r] + sgn * pi;
                    }
                }
                #pragma unroll
                for (int q = 5; q < 8; q++) {
                    float2 ys = ryp[l * 8 + q];
                    int str = 1 << (7 - q);
                    #pragma unroll
                    for (int a0 = 0; a0 < 8; a0++) {
                        if (a0 & str) continue;
                        int b0 = a0 | str;
                        float tr0 = re[a0], ti0 = im[a0], tr1 = re[b0], ti1 = im[b0];
                        re[a0] = ys.x * tr0 - ys.y * tr1;
                        im[a0] = ys.x * ti0 - ys.y * ti1;
                        re[b0] = ys.y * tr0 + ys.x * tr1;
                        im[b0] = ys.y * ti0 + ys.x * ti1;
                    }
                }
                if (l == 0) {
                    float2 pl = g_pl2[(qg * 2 + l) * 32 + lane];
                    #pragma unroll
                    for (int r = 0; r < 8; r++) {
                        float nr = pl.x * re[r] - pl.y * im[r];
                        im[r] = pl.x * im[r] + pl.y * re[r];
                        re[r] = nr;
                    }
                    #pragma unroll
                    for (int r = 0; r < 8; r++) {
                        float2 pq = prp[l * 8 + r];
                        float nr = pq.x * re[r] - pq.y * im[r];
                        im[r] = pq.x * im[r] + pq.y * re[r];
                        re[r] = nr;
                    }
                }
                #pragma unroll
                for (int ct = 0; ct < 4; ct++) {
                    int d = 8 >> ct, cb = 4 - ct;
                    int cbit = (lane >> cb) & 1;
                    #pragma unroll
                    for (int r = 0; r < 8; r++) {
                        float pr = __shfl_xor_sync(FULL, re[r], d);
                        float pi = __shfl_xor_sync(FULL, im[r], d);
                        re[r] = cbit ? pr : re[r];
                        im[r] = cbit ? pi : im[r];
                    }
                }
                {
                    int cbit = lane & 1;
                    #pragma unroll
                    for (int r = 0; r < 4; r++) {
                        float t1 = re[r], t2 = re[r + 4];
                        re[r]     = cbit ? t2 : t1;
                        re[r + 4] = cbit ? t1 : t2;
                        t1 = im[r]; t2 = im[r + 4];
                        im[r]     = cbit ? t2 : t1;
                        im[r + 4] = cbit ? t1 : t2;
                    }
                }
                {
                    float tt;
                    tt = re[4]; re[4] = re[6]; re[6] = tt;
                    tt = re[5]; re[5] = re[7]; re[7] = tt;
                    tt = im[4]; im[4] = im[6]; im[6] = tt;
                    tt = im[5]; im[5] = im[7]; im[7] = tt;
                }
                {
                    float tt;
                    tt = re[2]; re[2] = re[3]; re[3] = tt;
                    tt = re[6]; re[6] = re[7]; re[7] = tt;
                    tt = im[2]; im[2] = im[3]; im[3] = tt;
                    tt = im[6]; im[6] = im[7]; im[7] = tt;
                }
            }

            float p0 = re[0]*re[0]+im[0]*im[0], p1 = re[1]*re[1]+im[1]*im[1];
            float p2 = re[2]*re[2]+im[2]*im[2], p3 = re[3]*re[3]+im[3]*im[3];
            float p4 = re[4]*re[4]+im[4]*im[4], p5 = re[5]*re[5]+im[5]*im[5];
            float p6 = re[6]*re[6]+im[6]*im[6], p7 = re[7]*re[7]+im[7]*im[7];
            float S = p0+p1+p2+p3+p4+p5+p6+p7;
            float z[8];
            #pragma unroll
            for (int q = 0; q < 5; q++)
                z[q] = ((lane >> (4 - q)) & 1) ? -S : S;
            z[5] = (p0+p1+p2+p3) - (p4+p5+p6+p7);
            z[6] = (p0+p1+p4+p5) - (p2+p3+p6+p7);
            z[7] = (p0+p2+p4+p6) - (p1+p3+p5+p7);
            #pragma unroll
            for (int q = 0; q < 8; q++) {
                #pragma unroll
                for (int o = 16; o; o >>= 1) z[q] += __shfl_xor_sync(FULL, z[q], o);
            }

            int row = qb * 4 + qg;
            #pragma unroll
            for (int j = 0; j < 16; j++) {
                int col = j * 32 + lane;
                float a2 = pb1[col];
                #pragma unroll
                for (int q = 0; q < 8; q++) a2 += z[q] * pW1[q * H_ + col];
                a2 = fmaxf(a2, 0.f);
                __nv_bfloat16 hi = __float2bfloat16(a2);
                __nv_bfloat16 lo = __float2bfloat16(a2 - __bfloat162float(hi));
                g_H1h[row * H_ + col] = hi;
                g_H1l[row * H_ + col] = lo;
            }
        }
        groupbar(grp);

        // ================= G phase: GEMM + LSTM + h-projection =================
        {
            float* outt = out + (size_t)t * (B_ * H_);
            {
                size_t g0 = (size_t)lrow0 * H_ + lun0 * 8;
                size_t g1 = (size_t)lrow1 * H_ + lun1 * 8;
                cp16cg(s0 + SM_AH + ld0, Ah + g0); cp16cg(s0 + SM_AH + ld1, Ah + g1);
                cp16cg(s0 + SM_AL + ld0, Al + g0); cp16cg(s0 + SM_AL + ld1, Al + g1);
                cp16cg(s0 + SM_BH + ld0, Bh + g0); cp16cg(s0 + SM_BH + ld1, Bh + g1);
                cp16cg(s0 + SM_BL + ld0, Bl + g0); cp16cg(s0 + SM_BL + ld1, Bl + g1);
                CP_COMMIT();
            }
            float acc[4][4];
            #pragma unroll
            for (int j = 0; j < 4; j++)
                #pragma unroll
                for (int r = 0; r < 4; r++) acc[j][r] = 0.f;

            for (int c = 0; c < 8; c++) {
                if (c + 1 < 8) {
                    uint32_t sb = s0 + ((c + 1) & 1) * BUFSZ;
                    int kb = (c + 1) * 64;
                    size_t g0 = (size_t)lrow0 * H_ + kb + lun0 * 8;
                    size_t g1 = (size_t)lrow1 * H_ + kb + lun1 * 8;
                    cp16cg(sb + SM_AH + ld0, Ah + g0); cp16cg(sb + SM_AH + ld1, Ah + g1);
                    cp16cg(sb + SM_AL + ld0, Al + g0); cp16cg(sb + SM_AL + ld1, Al + g1);
                    cp16cg(sb + SM_BH + ld0, Bh + g0); cp16cg(sb + SM_BH + ld1, Bh + g1);
                    cp16cg(sb + SM_BL + ld0, Bl + g0); cp16cg(sb + SM_BL + ld1, Bl + g1);
                    CP_COMMIT();
                    cp_wait<1>();
                } else {
                    cp_wait<0>();
                }
                __syncthreads();

                uint32_t buf = s0 + (c & 1) * BUFSZ;
                #pragma unroll
                for (int kk = 0; kk < 4; kk++) {
                    uint32_t kb2 = kk * 32;
                    uint32_t ahf[4], alf[4], bhf[2][4], blf[2][4];
                    ldm4(buf + SM_AH + aOff + kb2, ahf);
                    ldm4(buf + SM_AL + aOff + kb2, alf);
                    ldm4(buf + SM_BH + bOff + kb2, bhf[0]);
                    ldm4(buf + SM_BH + bOff + 16 * SROWB + kb2, bhf[1]);
                    ldm4(buf + SM_BL + bOff + kb2, blf[0]);
                    ldm4(buf + SM_BL + bOff + 16 * SROWB + kb2, blf[1]);
                    #pragma unroll
                    for (int j = 0; j < 4; j++) {
                        int p = j >> 1, sb2 = j & 1;
                        mma_bf16(acc[j], ahf, bhf[p][sb2], bhf[p][2 + sb2]);
                        mma_bf16(acc[j], ahf, blf[p][sb2], blf[p][2 + sb2]);
                        mma_bf16(acc[j], alf, bhf[p][sb2], bhf[p][2 + sb2]);
                    }
                }
                __syncthreads();
            }

            float* sp = (float*)dsm;
            int r0 = wm + (lane >> 2);
            #pragma unroll
            for (int j = 0; j < 4; j++) {
                int cc = wn + j * 8 + (lane & 3) * 2;
                sp[r0 * EPAD + cc]           = acc[j][0];
                sp[r0 * EPAD + cc + 1]       = acc[j][1];
                sp[(r0 + 8) * EPAD + cc]     = acc[j][2];
                sp[(r0 + 8) * EPAD + cc + 1] = acc[j][3];
            }
            __syncthreads();

            float* hs = (float*)(dsm + HOFF);
            bool last = (t == T_ - 1);
            #pragma unroll
            for (int jj = 0; jj < 4; jj++) {
                int e = tid + 256 * jj;
                int bi = e >> 6, col = e & 63;
                float bias = pb2[n0 + col];
                float fv = sigmoidf_(sp[(bi * 4 + 0) * EPAD + col] + bias);
                float iv = sigmoidf_(sp[(bi * 4 + 1) * EPAD + col] + bias);
                float uv = tanhf   (sp[(bi * 4 + 2) * EPAD + col] + bias);
                float ov = sigmoidf_(sp[(bi * 4 + 3) * EPAD + col] + bias);
                int batch = mt * 16 + bi;
                int idx = batch * H_ + n0 + col;
                float cc2 = fv * g_c[idx] + iv * uv;
                float hh2 = ov * tanhf(cc2);
                g_c[idx] = cc2;
                outt[idx] = hh2;
                hs[bi * 64 + col] = hh2;
                if (last) {
                    out[(size_t)T_ * B_ * H_ + idx] = hh2;
                    out[(size_t)T_ * B_ * H_ + B_ * H_ + idx] = cc2;
                }
            }
            __syncthreads();

            #pragma unroll
            for (int jj = 0; jj < 2; jj++) {
                int idx2 = tid + 256 * jj;
                int bi = idx2 >> 5, o = idx2 & 31;
                const float* hh = hs + bi * 64;
                const float* wr = g_Wh2t + (size_t)n0 * 32 + o;
                float sacc = 0.f;
                #pragma unroll 16
                for (int c2 = 0; c2 < 64; c2++) sacc += hh[c2] * wr[c2 * 32];
                __stcg(g_Zpart + nt * (B_ * 32) + (mt * 16 + bi) * 32 + o, sacc);
            }
        }
        if (t < T_ - 1) groupbar(grp);
    }
}

// ---------------- host ----------------
extern "C" void kernel_launch(void* const* d_in, const int* in_sizes, int n_in,
                              void* d_out, int out_size) {
    const float* inputs = (const float*)d_in[0];
    const float* qpf = (const float*)d_in[1];
    const float* qpi = (const float*)d_in[2];
    const float* qpu = (const float*)d_in[3];
    const float* qpo = (const float*)d_in[4];
    const float* Wf  = (const float*)d_in[5];
    const float* bf  = (const float*)d_in[6];
    const float* Wi  = (const float*)d_in[7];
    const float* bi  = (const float*)d_in[8];
    const float* Wu  = (const float*)d_in[9];
    const float* bu  = (const float*)d_in[10];
    const float* Wo  = (const float*)d_in[11];
    const float* bo  = (const float*)d_in[12];
    const float* pW1 = (const float*)d_in[13];
    const float* pb1 = (const float*)d_in[14];
    const float* pW2 = (const float*)d_in[15];
    const float* pb2 = (const float*)d_in[16];
    float* out = (float*)d_out;

    cudaFuncSetAttribute(qlstm_kernel, cudaFuncAttributeMaxDynamicSharedMemorySize, SMEM_DYN);
    cudaFuncSetAttribute(xproj_kernel, cudaFuncAttributeMaxDynamicSharedMemorySize, XP_SMEM);

    bprep_kernel<<<(H_ * H_) / 256, 256>>>(pW2);
    whprep_kernel<<<(H_ * 32) / 256, 256>>>(Wf, Wi, Wu, Wo);
    tabprep_kernel<<<1, 256>>>(qpf, qpi, qpu, qpo);
    xproj_kernel<<<(T_ * B_) / 32, 256, XP_SMEM>>>(inputs, Wf, Wi, Wu, Wo, bf, bi, bu, bo);
    qlstm_kernel<<<128, 256, SMEM_DYN>>>(pW1, pb1, pb2, out);
}

// round 9
// speedup vs baseline: 2.7856x; 1.1411x over previous
#include <cuda_runtime.h>
#include <cuda_bf16.h>
#include <math.h>
#include <stdint.h>

#define T_  64
#define B_  256
#define D_  512
#define H_  512

// ---------------- device scratch (allocation-free rule) ----------------
__device__ __nv_bfloat16 g_H1h[B_ * 4 * H_];   // hi(H1), row = b*4 + gate
__device__ __nv_bfloat16 g_H1l[B_ * 4 * H_];   // lo(H1)
__device__ __nv_bfloat16 g_Bht[H_ * H_];       // hi(pW2^T), [n][k]
__device__ __nv_bfloat16 g_Blt[H_ * H_];       // lo(pW2^T)
__device__ __nv_bfloat16 g_Wxh[32 * D_];       // hi(Wx^T) [o][k] for xproj
__device__ __nv_bfloat16 g_Wxl[32 * D_];       // lo(Wx^T)
__device__ float g_bx[32];                     // gate bias vector
__device__ float g_c[B_ * H_];
__device__ float g_Xproj[T_ * B_ * 32];        // x_t @ W + b, [t*B+b][g*8+q]
__device__ float g_Zpart[8 * B_ * 32];         // per-n-tile partial h-projections
__device__ float g_Wh2t[H_ * 32];              // W[D+col][g*8+q] as [col][32]
__device__ float2 g_ry[4 * 2 * 8];             // (cy,sy) per (g,l,q)
__device__ float2 g_pl2[4 * 2 * 32];           // lane-deferred RZ phase per (g,l,lane)
__device__ float2 g_pr2[4 * 2 * 8];            // reg-deferred RZ phase per (g,l,r)
__device__ int g_gcnt[16];
__device__ volatile int g_ggen[16];

// ---------------- PTX helpers ----------------
__device__ __forceinline__ uint32_t smem_u32(const void* p) {
    uint32_t a;
    asm("{ .reg .u64 t; cvta.to.shared.u64 t, %1; cvt.u32.u64 %0, t; }" : "=r"(a) : "l"(p));
    return a;
}
__device__ __forceinline__ void cp16cg(uint32_t dst, const void* src) {
    asm volatile("cp.async.cg.shared.global [%0], [%1], 16;" :: "r"(dst), "l"(src) : "memory");
}
#define CP_COMMIT() asm volatile("cp.async.commit_group;" ::: "memory")
template<int N> __device__ __forceinline__ void cp_wait() {
    asm volatile("cp.async.wait_group %0;" :: "n"(N) : "memory");
}
__device__ __forceinline__ void ldm4(uint32_t addr, uint32_t* r) {
    asm volatile("ldmatrix.sync.aligned.m8n8.x4.shared.b16 {%0,%1,%2,%3}, [%4];"
        : "=r"(r[0]), "=r"(r[1]), "=r"(r[2]), "=r"(r[3]) : "r"(addr));
}
__device__ __forceinline__ void mma_bf16(float* c, const uint32_t* a, uint32_t b0, uint32_t b1) {
    asm volatile(
        "mma.sync.aligned.m16n8k16.row.col.f32.bf16.bf16.f32 "
        "{%0,%1,%2,%3}, {%4,%5,%6,%7}, {%8,%9}, {%0,%1,%2,%3};"
        : "+f"(c[0]), "+f"(c[1]), "+f"(c[2]), "+f"(c[3])
        : "r"(a[0]), "r"(a[1]), "r"(a[2]), "r"(a[3]), "r"(b0), "r"(b1));
}
__device__ __forceinline__ float sigmoidf_(float x) { return 1.f / (1.f + expf(-x)); }

// ---------------- group barrier: 8 blocks (one m-tile group) ----------------
__device__ __forceinline__ void groupbar(int grp) {
    __syncthreads();
    if (threadIdx.x == 0) {
        __threadfence();
        int gen = g_ggen[grp];
        if (atomicAdd(&g_gcnt[grp], 1) == 7) {
            g_gcnt[grp] = 0;
            __threadfence();
            g_ggen[grp] = gen + 1;
        } else {
            while (g_ggen[grp] == gen) __nanosleep(20);
        }
    }
    __syncthreads();
}

// ---------------- prep kernels ----------------
// pW2 (K,N) -> transposed bf16 hi/lo [n][k]
__global__ void bprep_kernel(const float* __restrict__ pW2) {
    int i = blockIdx.x * blockDim.x + threadIdx.x;
    int n = i >> 9, k = i & 511;
    float v = pW2[k * H_ + n];
    __nv_bfloat16 hi = __float2bfloat16(v);
    __nv_bfloat16 lo = __float2bfloat16(v - __bfloat162float(hi));
    g_Bht[i] = hi; g_Blt[i] = lo;
}

// Wh2t[col][o] = W_g[D+col][q] ; Wx^T[o][k] = W_g[k][q] bf16 split ; bias vec
__global__ void whprep_kernel(
    const float* __restrict__ Wf, const float* __restrict__ Wi,
    const float* __restrict__ Wu, const float* __restrict__ Wo,
    const float* __restrict__ bf, const float* __restrict__ bi,
    const float* __restrict__ bu, const float* __restrict__ bo)
{
    int i = blockIdx.x * blockDim.x + threadIdx.x;   // 0..16383
    {
        int col = i >> 5, o = i & 31, g = o >> 3, q = o & 7;
        const float* W = (g == 0) ? Wf : (g == 1) ? Wi : (g == 2) ? Wu : Wo;
        g_Wh2t[i] = W[(D_ + col) * 8 + q];
    }
    {
        int o = i >> 9, k = i & 511, g = o >> 3, q = o & 7;
        const float* W = (g == 0) ? Wf : (g == 1) ? Wi : (g == 2) ? Wu : Wo;
        float v = W[k * 8 + q];
        __nv_bfloat16 hi = __float2bfloat16(v);
        __nv_bfloat16 lo = __float2bfloat16(v - __bfloat162float(hi));
        g_Wxh[i] = hi; g_Wxl[i] = lo;
    }
    if (i < 32) {
        int g = i >> 3, q = i & 7;
        const float* bb = (g == 0) ? bf : (g == 1) ? bi : (g == 2) ? bu : bo;
        g_bx[i] = bb[q];
    }
}

// trig + deferred-phase tables
__global__ void tabprep_kernel(
    const float* __restrict__ qpf, const float* __restrict__ qpi,
    const float* __restrict__ qpu, const float* __restrict__ qpo)
{
    int i = threadIdx.x;   // 0..255
    const float* qps[4] = {qpf, qpi, qpu, qpo};
    if (i < 64) {
        int g = i >> 4, l = (i >> 3) & 1, q = i & 7;
        const float* qp = qps[g];
        float th = qp[(l * 8 + q) * 3 + 0] * 0.5f;
        g_ry[i] = make_float2(cosf(th), sinf(th));
        int r = q;
        float prr = 1.f, pri = 0.f;
        #pragma unroll
        for (int qq = 5; qq < 8; qq++) {
            float tz = qp[(l * 8 + qq) * 3 + 1] * 0.5f;
            float cz = cosf(tz), sz = sinf(tz);
            float zn = ((r >> (7 - qq)) & 1) ? sz : -sz;
            float nr = prr * cz - pri * zn;
            float ni = prr * zn + pri * cz;
            prr = nr; pri = ni;
        }
        g_pr2[i] = make_float2(prr, pri);
    }
    {
        int g = i >> 6, l = (i >> 5) & 1, ln = i & 31;
        const float* qp = qps[g];
        float prr = 1.f, pri = 0.f;
        #pragma unroll
        for (int q = 0; q < 5; q++) {
            float tz = qp[(l * 8 + q) * 3 + 1] * 0.5f;
            float cz = cosf(tz), sz = sinf(tz);
            float zn = ((ln >> (4 - q)) & 1) ? sz : -sz;
            float nr = prr * cz - pri * zn;
            float ni = prr * zn + pri * cz;
            prr = nr; pri = ni;
        }
        g_pl2[i] = make_float2(prr, pri);
    }
}

// ---------------- xproj v3: HMMA GEMM, X(16384x512) @ Wx(512x32) -------------
// Block: 128 thr, M-tile 64, N=32, full K staged. Row stride 1040B in smem.
#define XROWB 1040u
#define XA_H 0u
#define XA_L 66560u
#define XB_H 133120u
#define XB_L 166400u
#define XP3_SMEM 199680

__global__ __launch_bounds__(128, 1) void xproj_kernel(const float* __restrict__ inputs)
{
    extern __shared__ __align__(16) char xsm[];
    uint32_t s0 = smem_u32(xsm);
    int tid = threadIdx.x, wid = tid >> 5, lane = tid & 31;
    int m0 = blockIdx.x * 64;

    // stage B (Wx^T hi/lo, 32 rows x 512 k) via cp.async
    #pragma unroll
    for (int j = 0; j < 16; j++) {
        int u = tid + 128 * j;            // 2048 16B units
        int row = u >> 6, ku = u & 63;
        uint32_t dst = (uint32_t)row * XROWB + (uint32_t)ku * 16u;
        cp16cg(s0 + XB_H + dst, g_Wxh + row * D_ + ku * 8);
        cp16cg(s0 + XB_L + dst, g_Wxl + row * D_ + ku * 8);
    }
    CP_COMMIT();

    // stage A: fp32 -> split bf16 hi/lo (64 rows x 512 k)
    #pragma unroll
    for (int j = 0; j < 64; j++) {
        int u = tid + 128 * j;            // 8192 float4 units
        int row = u >> 7, f4 = u & 127;
        float4 xv = *(const float4*)(inputs + (size_t)(m0 + row) * D_ + f4 * 4);
        __nv_bfloat16 h0 = __float2bfloat16(xv.x), h1 = __float2bfloat16(xv.y);
        __nv_bfloat16 h2 = __float2bfloat16(xv.z), h3 = __float2bfloat16(xv.w);
        __nv_bfloat16 l0 = __float2bfloat16(xv.x - __bfloat162float(h0));
        __nv_bfloat16 l1 = __float2bfloat16(xv.y - __bfloat162float(h1));
        __nv_bfloat16 l2 = __float2bfloat16(xv.z - __bfloat162float(h2));
        __nv_bfloat16 l3 = __float2bfloat16(xv.w - __bfloat162float(h3));
        uint2 ph, pl;
        ph.x = ((uint32_t)__bfloat16_as_ushort(h1) << 16) | __bfloat16_as_ushort(h0);
        ph.y = ((uint32_t)__bfloat16_as_ushort(h3) << 16) | __bfloat16_as_ushort(h2);
        pl.x = ((uint32_t)__bfloat16_as_ushort(l1) << 16) | __bfloat16_as_ushort(l0);
        pl.y = ((uint32_t)__bfloat16_as_ushort(l3) << 16) | __bfloat16_as_ushort(l2);
        uint32_t off = (uint32_t)row * XROWB + (uint32_t)f4 * 8u;
        *(uint2*)(xsm + XA_H + off) = ph;
        *(uint2*)(xsm + XA_L + off) = pl;
    }
    cp_wait<0>();
    __syncthreads();

    // MMA: warp m-tile = wid*16 rows, N=32 (4 n8 tiles)
    float acc[4][4];
    #pragma unroll
    for (int j = 0; j < 4; j++)
        #pragma unroll
        for (int r = 0; r < 4; r++) acc[j][r] = 0.f;

    uint32_t aOff = (uint32_t)(wid * 16 + (lane & 15)) * XROWB + (uint32_t)((lane >> 4) << 4);
    uint32_t bOff = (uint32_t)(lane & 15) * XROWB + (uint32_t)((lane >> 4) << 4);

    #pragma unroll 4
    for (int k16 = 0; k16 < 32; k16++) {
        uint32_t kb = (uint32_t)k16 * 32u;
        uint32_t ah[4], al[4], bh[2][4], bl[2][4];
        ldm4(s0 + XA_H + aOff + kb, ah);
        ldm4(s0 + XA_L + aOff + kb, al);
        ldm4(s0 + XB_H + bOff + kb, bh[0]);
        ldm4(s0 + XB_H + bOff + 16 * XROWB + kb, bh[1]);
        ldm4(s0 + XB_L + bOff + kb, bl[0]);
        ldm4(s0 + XB_L + bOff + 16 * XROWB + kb, bl[1]);
        #pragma unroll
        for (int j = 0; j < 4; j++) {
            int p = j >> 1, sb = j & 1;
            mma_bf16(acc[j], ah, bh[p][sb], bh[p][2 + sb]);
            mma_bf16(acc[j], ah, bl[p][sb], bl[p][2 + sb]);
            mma_bf16(acc[j], al, bh[p][sb], bh[p][2 + sb]);
        }
    }

    // epilogue: + bias, write to g_Xproj
    int r0 = m0 + wid * 16 + (lane >> 2);
    #pragma unroll
    for (int j = 0; j < 4; j++) {
        int col = j * 8 + (lane & 3) * 2;
        float b0 = g_bx[col], b1 = g_bx[col + 1];
        *(float2*)(g_Xproj + (size_t)r0 * 32 + col)       = make_float2(acc[j][0] + b0, acc[j][1] + b1);
        *(float2*)(g_Xproj + (size_t)(r0 + 8) * 32 + col) = make_float2(acc[j][2] + b0, acc[j][3] + b1);
    }
}

// ---------------- the persistent recurrence kernel ----------------
// smem: B resident [64 n][512 k] hi/lo (stride 1040), A double buffer (stride 144)
#define BROWB 1040u
#define PB_H 0u
#define PB_L 66560u
#define PA   133120u
#define PABUF 18432u
#define SROWB 144u
#define SMEM_DYN (133120 + 2 * 18432)
#define EPAD 68

__global__ __launch_bounds__(256, 1) void qlstm_kernel(
    const float* __restrict__ pW1, const float* __restrict__ pb1,
    const float* __restrict__ pb2, float* __restrict__ out)
{
    extern __shared__ __align__(16) char dsm[];
    const unsigned FULL = 0xffffffffu;
    uint32_t s0 = smem_u32(dsm);
    int tid = threadIdx.x, wid = tid >> 5, lane = tid & 31;
    int bid = blockIdx.x;
    int nt = bid & 7, mt = bid >> 3;
    int grp = mt;
    int n0 = nt * 64, m0 = mt * 64;

    int sidx = bid * 8 + wid;
    int qb = sidx >> 2, qg = sidx & 3;

    // ---- stage resident B tiles (pW2^T rows n0..n0+63, hi+lo) ----
    #pragma unroll
    for (int j = 0; j < 16; j++) {
        int u = tid + 256 * j;            // 4096 16B units
        int row = u >> 6, ku = u & 63;
        uint32_t dst = (uint32_t)row * BROWB + (uint32_t)ku * 16u;
        cp16cg(s0 + PB_H + dst, g_Bht + (size_t)(n0 + row) * H_ + ku * 8);
        cp16cg(s0 + PB_L + dst, g_Blt + (size_t)(n0 + row) * H_ + ku * 8);
    }
    CP_COMMIT();

    // ---- init: zero Zpart slices + c tile ----
    if (tid < 64) {
        #pragma unroll
        for (int p = 0; p < 8; p++)
            __stcg(g_Zpart + p * (B_ * 32) + bid * 64 + tid, 0.f);
    }
    #pragma unroll
    for (int jj = 0; jj < 4; jj++) {
        int e = tid + 256 * jj;
        g_c[(mt * 16 + (e >> 6)) * H_ + n0 + (e & 63)] = 0.f;
    }
    cp_wait<0>();
    groupbar(grp);

    // ---- hoisted GEMM constants ----
    const __nv_bfloat16* Ah = g_H1h + (size_t)m0 * H_;
    const __nv_bfloat16* Al = g_H1l + (size_t)m0 * H_;
    int wm = (wid >> 1) * 16, wn = (wid & 1) * 32;
    uint32_t aOff = (uint32_t)(wm + (lane & 15)) * SROWB + (uint32_t)((lane >> 4) << 4);
    uint32_t bOff = (uint32_t)(wn + (lane & 15)) * BROWB + (uint32_t)((lane >> 4) << 4);
    int lrow = tid >> 3, lun = tid & 7;          // A chunk: 512 units, 2 per thread
    int lrow2 = (tid + 256) >> 3, lun2 = (tid + 256) & 7;
    uint32_t ld0 = (uint32_t)lrow * SROWB + (uint32_t)lun * 16u;
    uint32_t ld1 = (uint32_t)lrow2 * SROWB + (uint32_t)lun2 * 16u;

    const float2* ryp = g_ry + qg * 16;
    const float2* prp = g_pr2 + qg * 16;

    for (int t = 0; t < T_; t++) {
        // ================= Q phase =================
        {
            float a = 0.f;
            if (lane < 8) {
                float zacc = 0.f;
                const float* zp = g_Zpart + qb * 32 + qg * 8 + lane;
                #pragma unroll
                for (int p = 0; p < 8; p++) zacc += __ldcg(zp + p * (B_ * 32));
                a = zacc + g_Xproj[((t * B_ + qb) * 4 + qg) * 8 + lane];
            }
            float sv, cv;
            __sincosf(a * 0.5f, &sv, &cv);

            float re[8], im[8];
            #pragma unroll
            for (int r = 0; r < 8; r++) { re[r] = 0.f; im[r] = 0.f; }
            if (lane == 0) re[0] = 1.f;

            #pragma unroll
            for (int q = 0; q < 5; q++) {
                int d = 16 >> q;
                float c = __shfl_sync(FULL, cv, q);
                float s = __shfl_sync(FULL, sv, q);
                #pragma unroll
                for (int r = 0; r < 8; r++) {
                    float pr = __shfl_xor_sync(FULL, re[r], d);
                    float pi = __shfl_xor_sync(FULL, im[r], d);
                    re[r] = c * re[r] + s * pi;
                    im[r] = c * im[r] - s * pr;
                }
            }
            #pragma unroll
            for (int q = 5; q < 8; q++) {
                int str = 1 << (7 - q);
                float c = __shfl_sync(FULL, cv, q);
                float s = __shfl_sync(FULL, sv, q);
                #pragma unroll
                for (int a0 = 0; a0 < 8; a0++) {
                    if (a0 & str) continue;
                    int b0 = a0 | str;
                    float tr0 = re[a0], ti0 = im[a0], tr1 = re[b0], ti1 = im[b0];
                    re[a0] = c * tr0 + s * ti1;
                    im[a0] = c * ti0 - s * tr1;
                    re[b0] = c * tr1 + s * ti0;
                    im[b0] = c * ti1 - s * tr0;
                }
            }

            #pragma unroll
            for (int l = 0; l < 2; l++) {
                #pragma unroll
                for (int q = 0; q < 5; q++) {
                    float2 ys = ryp[l * 8 + q];
                    int d = 16 >> q;
                    int hi = (lane >> (4 - q)) & 1;
                    float sgn = hi ? ys.y : -ys.y;
                    #pragma unroll
                    for (int r = 0; r < 8; r++) {
                        float pr = __shfl_xor_sync(FULL, re[r], d);
                        float pi = __shfl_xor_sync(FULL, im[r], d);
                        re[r] = ys.x * re[r] + sgn * pr;
                        im[r] = ys.x * im[r] + sgn * pi;
                    }
                }
                #pragma unroll
                for (int q = 5; q < 8; q++) {
                    float2 ys = ryp[l * 8 + q];
                    int str = 1 << (7 - q);
                    #pragma unroll
                    for (int a0 = 0; a0 < 8; a0++) {
                        if (a0 & str) continue;
                        int b0 = a0 | str;
                        float tr0 = re[a0], ti0 = im[a0], tr1 = re[b0], ti1 = im[b0];
                        re[a0] = ys.x * tr0 - ys.y * tr1;
                        im[a0] = ys.x * ti0 - ys.y * ti1;
                        re[b0] = ys.y * tr0 + ys.x * tr1;
                        im[b0] = ys.y * ti0 + ys.x * ti1;
                    }
                }
                if (l == 0) {
                    float2 pl = g_pl2[(qg * 2 + l) * 32 + lane];
                    #pragma unroll
                    for (int r = 0; r < 8; r++) {
                        float nr = pl.x * re[r] - pl.y * im[r];
                        im[r] = pl.x * im[r] + pl.y * re[r];
                        re[r] = nr;
                    }
                    #pragma unroll
                    for (int r = 0; r < 8; r++) {
                        float2 pq = prp[l * 8 + r];
                        float nr = pq.x * re[r] - pq.y * im[r];
                        im[r] = pq.x * im[r] + pq.y * re[r];
                        re[r] = nr;
                    }
                }
                #pragma unroll
                for (int ct = 0; ct < 4; ct++) {
                    int d = 8 >> ct, cb = 4 - ct;
                    int cbit = (lane >> cb) & 1;
                    #pragma unroll
                    for (int r = 0; r < 8; r++) {
                        float pr = __shfl_xor_sync(FULL, re[r], d);
                        float pi = __shfl_xor_sync(FULL, im[r], d);
                        re[r] = cbit ? pr : re[r];
                        im[r] = cbit ? pi : im[r];
                    }
                }
                {
                    int cbit = lane & 1;
                    #pragma unroll
                    for (int r = 0; r < 4; r++) {
                        float t1 = re[r], t2 = re[r + 4];
                        re[r]     = cbit ? t2 : t1;
                        re[r + 4] = cbit ? t1 : t2;
                        t1 = im[r]; t2 = im[r + 4];
                        im[r]     = cbit ? t2 : t1;
                        im[r + 4] = cbit ? t1 : t2;
                    }
                }
                {
                    float tt;
                    tt = re[4]; re[4] = re[6]; re[6] = tt;
                    tt = re[5]; re[5] = re[7]; re[7] = tt;
                    tt = im[4]; im[4] = im[6]; im[6] = tt;
                    tt = im[5]; im[5] = im[7]; im[7] = tt;
                }
                {
                    float tt;
                    tt = re[2]; re[2] = re[3]; re[3] = tt;
                    tt = re[6]; re[6] = re[7]; re[7] = tt;
                    tt = im[2]; im[2] = im[3]; im[3] = tt;
                    tt = im[6]; im[6] = im[7]; im[7] = tt;
                }
            }

            float p0 = re[0]*re[0]+im[0]*im[0], p1 = re[1]*re[1]+im[1]*im[1];
            float p2 = re[2]*re[2]+im[2]*im[2], p3 = re[3]*re[3]+im[3]*im[3];
            float p4 = re[4]*re[4]+im[4]*im[4], p5 = re[5]*re[5]+im[5]*im[5];
            float p6 = re[6]*re[6]+im[6]*im[6], p7 = re[7]*re[7]+im[7]*im[7];
            float S = p0+p1+p2+p3+p4+p5+p6+p7;
            float z[8];
            #pragma unroll
            for (int q = 0; q < 5; q++)
                z[q] = ((lane >> (4 - q)) & 1) ? -S : S;
            z[5] = (p0+p1+p2+p3) - (p4+p5+p6+p7);
            z[6] = (p0+p1+p4+p5) - (p2+p3+p6+p7);
            z[7] = (p0+p2+p4+p6) - (p1+p3+p5+p7);
            #pragma unroll
            for (int q = 0; q < 8; q++) {
                #pragma unroll
                for (int o = 16; o; o >>= 1) z[q] += __shfl_xor_sync(FULL, z[q], o);
            }

            int row = qb * 4 + qg;
            #pragma unroll
            for (int j = 0; j < 16; j++) {
                int col = j * 32 + lane;
                float a2 = pb1[col];
                #pragma unroll
                for (int q = 0; q < 8; q++) a2 += z[q] * pW1[q * H_ + col];
                a2 = fmaxf(a2, 0.f);
                __nv_bfloat16 hi = __float2bfloat16(a2);
                __nv_bfloat16 lo = __float2bfloat16(a2 - __bfloat162float(hi));
                g_H1h[row * H_ + col] = hi;
                g_H1l[row * H_ + col] = lo;
            }
        }
        groupbar(grp);

        // ================= G phase: GEMM + LSTM + h-projection =================
        {
            float* outt = out + (size_t)t * (B_ * H_);
            // prefetch A chunk 0
            {
                size_t g0 = (size_t)lrow * H_ + lun * 8;
                size_t g1 = (size_t)lrow2 * H_ + lun2 * 8;
                cp16cg(s0 + PA + ld0, Ah + g0);        cp16cg(s0 + PA + ld1, Ah + g1);
                cp16cg(s0 + PA + 9216 + ld0, Al + g0); cp16cg(s0 + PA + 9216 + ld1, Al + g1);
                CP_COMMIT();
            }
            float acc[4][4];
            #pragma unroll
            for (int j = 0; j < 4; j++)
                #pragma unroll
                for (int r = 0; r < 4; r++) acc[j][r] = 0.f;

            for (int c = 0; c < 8; c++) {
                if (c + 1 < 8) {
                    uint32_t sb = s0 + PA + ((c + 1) & 1) * PABUF;
                    int kb = (c + 1) * 64;
                    size_t g0 = (size_t)lrow * H_ + kb + lun * 8;
                    size_t g1 = (size_t)lrow2 * H_ + kb + lun2 * 8;
                    cp16cg(sb + ld0, Ah + g0);        cp16cg(sb + ld1, Ah + g1);
                    cp16cg(sb + 9216 + ld0, Al + g0); cp16cg(sb + 9216 + ld1, Al + g1);
                    CP_COMMIT();
                    cp_wait<1>();
                } else {
                    cp_wait<0>();
                }
                __syncthreads();

                uint32_t abuf = s0 + PA + (c & 1) * PABUF;
                uint32_t bko = (uint32_t)c * 128u;
                #pragma unroll
                for (int kk = 0; kk < 4; kk++) {
                    uint32_t kb2 = kk * 32;
                    uint32_t ahf[4], alf[4], bhf[2][4], blf[2][4];
                    ldm4(abuf + aOff + kb2, ahf);
                    ldm4(abuf + 9216 + aOff + kb2, alf);
                    ldm4(s0 + PB_H + bOff + bko + kb2, bhf[0]);
                    ldm4(s0 + PB_H + bOff + 16 * BROWB + bko + kb2, bhf[1]);
                    ldm4(s0 + PB_L + bOff + bko + kb2, blf[0]);
                    ldm4(s0 + PB_L + bOff + 16 * BROWB + bko + kb2, blf[1]);
                    #pragma unroll
                    for (int j = 0; j < 4; j++) {
                        int p = j >> 1, sb2 = j & 1;
                        mma_bf16(acc[j], ahf, bhf[p][sb2], bhf[p][2 + sb2]);
                        mma_bf16(acc[j], ahf, blf[p][sb2], blf[p][2 + sb2]);
                        mma_bf16(acc[j], alf, bhf[p][sb2], bhf[p][2 + sb2]);
                    }
                }
                __syncthreads();
            }

            // stage preact (aliases A buffers — consumed, safe until next prefetch)
            float* sp = (float*)(dsm + PA);
            int r0 = wm + (lane >> 2);
            #pragma unroll
            for (int j = 0; j < 4; j++) {
                int cc = wn + j * 8 + (lane & 3) * 2;
                sp[r0 * EPAD + cc]           = acc[j][0];
                sp[r0 * EPAD + cc + 1]       = acc[j][1];
                sp[(r0 + 8) * EPAD + cc]     = acc[j][2];
                sp[(r0 + 8) * EPAD + cc + 1] = acc[j][3];
            }
            __syncthreads();

            float* hs = (float*)(dsm + PA + 17408);
            bool last = (t == T_ - 1);
            #pragma unroll
            for (int jj = 0; jj < 4; jj++) {
                int e = tid + 256 * jj;
                int bi = e >> 6, col = e & 63;
                float bias = pb2[n0 + col];
                float fv = sigmoidf_(sp[(bi * 4 + 0) * EPAD + col] + bias);
                float iv = sigmoidf_(sp[(bi * 4 + 1) * EPAD + col] + bias);
                float uv = tanhf   (sp[(bi * 4 + 2) * EPAD + col] + bias);
                float ov = sigmoidf_(sp[(bi * 4 + 3) * EPAD + col] + bias);
                int batch = mt * 16 + bi;
                int idx = batch * H_ + n0 + col;
                float cc2 = fv * g_c[idx] + iv * uv;
                float hh2 = ov * tanhf(cc2);
                g_c[idx] = cc2;
                outt[idx] = hh2;
                hs[bi * 64 + col] = hh2;
                if (last) {
                    out[(size_t)T_ * B_ * H_ + idx] = hh2;
                    out[(size_t)T_ * B_ * H_ + B_ * H_ + idx] = cc2;
                }
            }
            __syncthreads();

            #pragma unroll
            for (int jj = 0; jj < 2; jj++) {
                int idx2 = tid + 256 * jj;
                int bi = idx2 >> 5, o = idx2 & 31;
                const float* hh = hs + bi * 64;
                const float* wr = g_Wh2t + (size_t)n0 * 32 + o;
                float sacc = 0.f;
                #pragma unroll 16
                for (int c2 = 0; c2 < 64; c2++) sacc += hh[c2] * wr[c2 * 32];
                __stcg(g_Zpart + nt * (B_ * 32) + (mt * 16 + bi) * 32 + o, sacc);
            }
        }
        if (t < T_ - 1) groupbar(grp);
    }
}

// ---------------- host ----------------
extern "C" void kernel_launch(void* const* d_in, const int* in_sizes, int n_in,
                              void* d_out, int out_size) {
    const float* inputs = (const float*)d_in[0];
    const float* qpf = (const float*)d_in[1];
    const float* qpi = (const float*)d_in[2];
    const float* qpu = (const float*)d_in[3];
    const float* qpo = (const float*)d_in[4];
    const float* Wf  = (const float*)d_in[5];
    const float* bf  = (const float*)d_in[6];
    const float* Wi  = (const float*)d_in[7];
    const float* bi  = (const float*)d_in[8];
    const float* Wu  = (const float*)d_in[9];
    const float* bu  = (const float*)d_in[10];
    const float* Wo  = (const float*)d_in[11];
    const float* bo  = (const float*)d_in[12];
    const float* pW1 = (const float*)d_in[13];
    const float* pb1 = (const float*)d_in[14];
    const float* pW2 = (const float*)d_in[15];
    const float* pb2 = (const float*)d_in[16];
    float* out = (float*)d_out;

    cudaFuncSetAttribute(qlstm_kernel, cudaFuncAttributeMaxDynamicSharedMemorySize, SMEM_DYN);
    cudaFuncSetAttribute(xproj_kernel, cudaFuncAttributeMaxDynamicSharedMemorySize, XP3_SMEM);

    bprep_kernel<<<(H_ * H_) / 256, 256>>>(pW2);
    whprep_kernel<<<(H_ * 32) / 256, 256>>>(Wf, Wi, Wu, Wo, bf, bi, bu, bo);
    tabprep_kernel<<<1, 256>>>(qpf, qpi, qpu, qpo);
    xproj_kernel<<<(T_ * B_) / 64, 128, XP3_SMEM>>>(inputs);
    qlstm_kernel<<<128, 256, SMEM_DYN>>>(pW1, pb1, pb2, out);
}

// round 10
// speedup vs baseline: 3.1582x; 1.1338x over previous
#include <cuda_runtime.h>
#include <cuda_bf16.h>
#include <math.h>
#include <stdint.h>

#define T_  64
#define B_  256
#define D_  512
#define H_  512

// ---------------- device scratch (allocation-free rule) ----------------
__device__ __nv_bfloat16 g_H1h[B_ * 4 * H_];   // hi(H1), row = b*4 + gate
__device__ __nv_bfloat16 g_H1l[B_ * 4 * H_];   // lo(H1)
__device__ __nv_bfloat16 g_Bht[H_ * H_];       // hi(pW2^T), [n][k]
__device__ __nv_bfloat16 g_Blt[H_ * H_];       // lo(pW2^T)
__device__ __nv_bfloat16 g_Wxh[32 * D_];       // hi(Wx^T) [o][k] for xproj
__device__ __nv_bfloat16 g_Wxl[32 * D_];       // lo(Wx^T)
__device__ float g_bx[32];                     // gate bias vector
__device__ float g_Xproj[T_ * B_ * 32];        // x_t @ W + b, [t*B+b][g*8+q]
__device__ float g_Zpart[8 * B_ * 32];         // per-n-tile partial h-projections
__device__ float g_Wh2t[H_ * 32];              // W[D+col][g*8+q] as [col][32]
__device__ float2 g_ry[4 * 2 * 8];             // (cy,sy) per (g,l,q)
__device__ float2 g_pl2[4 * 2 * 32];           // lane-deferred RZ phase per (g,l,lane)
__device__ float2 g_pr2[4 * 2 * 8];            // reg-deferred RZ phase per (g,l,r)
__device__ int g_gcnt[16 * 32];                // padded: one 128B line per group
__device__ volatile int g_ggen[16 * 32];

// ---------------- PTX helpers ----------------
__device__ __forceinline__ uint32_t smem_u32(const void* p) {
    uint32_t a;
    asm("{ .reg .u64 t; cvta.to.shared.u64 t, %1; cvt.u32.u64 %0, t; }" : "=r"(a) : "l"(p));
    return a;
}
__device__ __forceinline__ void cp16cg(uint32_t dst, const void* src) {
    asm volatile("cp.async.cg.shared.global [%0], [%1], 16;" :: "r"(dst), "l"(src) : "memory");
}
#define CP_COMMIT() asm volatile("cp.async.commit_group;" ::: "memory")
template<int N> __device__ __forceinline__ void cp_wait() {
    asm volatile("cp.async.wait_group %0;" :: "n"(N) : "memory");
}
__device__ __forceinline__ void ldm4(uint32_t addr, uint32_t* r) {
    asm volatile("ldmatrix.sync.aligned.m8n8.x4.shared.b16 {%0,%1,%2,%3}, [%4];"
        : "=r"(r[0]), "=r"(r[1]), "=r"(r[2]), "=r"(r[3]) : "r"(addr));
}
__device__ __forceinline__ void mma_bf16(float* c, const uint32_t* a, uint32_t b0, uint32_t b1) {
    asm volatile(
        "mma.sync.aligned.m16n8k16.row.col.f32.bf16.bf16.f32 "
        "{%0,%1,%2,%3}, {%4,%5,%6,%7}, {%8,%9}, {%0,%1,%2,%3};"
        : "+f"(c[0]), "+f"(c[1]), "+f"(c[2]), "+f"(c[3])
        : "r"(a[0]), "r"(a[1]), "r"(a[2]), "r"(a[3]), "r"(b0), "r"(b1));
}
__device__ __forceinline__ float sigmoidf_(float x) { return 1.f / (1.f + expf(-x)); }

// ---------------- group barrier: 8 blocks (one m-tile group), padded lines ---
__device__ __forceinline__ void groupbar(int grp) {
    __syncthreads();
    if (threadIdx.x == 0) {
        __threadfence();
        int gen = g_ggen[grp * 32];
        if (atomicAdd(&g_gcnt[grp * 32], 1) == 7) {
            g_gcnt[grp * 32] = 0;
            __threadfence();
            g_ggen[grp * 32] = gen + 1;
        } else {
            while (g_ggen[grp * 32] == gen) __nanosleep(20);
        }
    }
    __syncthreads();
}

// ---------------- prep kernels ----------------
__global__ void bprep_kernel(const float* __restrict__ pW2) {
    int i = blockIdx.x * blockDim.x + threadIdx.x;
    int n = i >> 9, k = i & 511;
    float v = pW2[k * H_ + n];
    __nv_bfloat16 hi = __float2bfloat16(v);
    __nv_bfloat16 lo = __float2bfloat16(v - __bfloat162float(hi));
    g_Bht[i] = hi; g_Blt[i] = lo;
}

__global__ void whprep_kernel(
    const float* __restrict__ Wf, const float* __restrict__ Wi,
    const float* __restrict__ Wu, const float* __restrict__ Wo,
    const float* __restrict__ bf, const float* __restrict__ bi,
    const float* __restrict__ bu, const float* __restrict__ bo)
{
    int i = blockIdx.x * blockDim.x + threadIdx.x;   // 0..16383
    {
        int col = i >> 5, o = i & 31, g = o >> 3, q = o & 7;
        const float* W = (g == 0) ? Wf : (g == 1) ? Wi : (g == 2) ? Wu : Wo;
        g_Wh2t[i] = W[(D_ + col) * 8 + q];
    }
    {
        int o = i >> 9, k = i & 511, g = o >> 3, q = o & 7;
        const float* W = (g == 0) ? Wf : (g == 1) ? Wi : (g == 2) ? Wu : Wo;
        float v = W[k * 8 + q];
        __nv_bfloat16 hi = __float2bfloat16(v);
        __nv_bfloat16 lo = __float2bfloat16(v - __bfloat162float(hi));
        g_Wxh[i] = hi; g_Wxl[i] = lo;
    }
    if (i < 32) {
        int g = i >> 3, q = i & 7;
        const float* bb = (g == 0) ? bf : (g == 1) ? bi : (g == 2) ? bu : bo;
        g_bx[i] = bb[q];
    }
}

__global__ void tabprep_kernel(
    const float* __restrict__ qpf, const float* __restrict__ qpi,
    const float* __restrict__ qpu, const float* __restrict__ qpo)
{
    int i = threadIdx.x;   // 0..255
    const float* qps[4] = {qpf, qpi, qpu, qpo};
    if (i < 64) {
        int g = i >> 4, l = (i >> 3) & 1, q = i & 7;
        const float* qp = qps[g];
        float th = qp[(l * 8 + q) * 3 + 0] * 0.5f;
        g_ry[i] = make_float2(cosf(th), sinf(th));
        int r = q;
        float prr = 1.f, pri = 0.f;
        #pragma unroll
        for (int qq = 5; qq < 8; qq++) {
            float tz = qp[(l * 8 + qq) * 3 + 1] * 0.5f;
            float cz = cosf(tz), sz = sinf(tz);
            float zn = ((r >> (7 - qq)) & 1) ? sz : -sz;
            float nr = prr * cz - pri * zn;
            float ni = prr * zn + pri * cz;
            prr = nr; pri = ni;
        }
        g_pr2[i] = make_float2(prr, pri);
    }
    {
        int g = i >> 6, l = (i >> 5) & 1, ln = i & 31;
        const float* qp = qps[g];
        float prr = 1.f, pri = 0.f;
        #pragma unroll
        for (int q = 0; q < 5; q++) {
            float tz = qp[(l * 8 + q) * 3 + 1] * 0.5f;
            float cz = cosf(tz), sz = sinf(tz);
            float zn = ((ln >> (4 - q)) & 1) ? sz : -sz;
            float nr = prr * cz - pri * zn;
            float ni = prr * zn + pri * cz;
            prr = nr; pri = ni;
        }
        g_pl2[i] = make_float2(prr, pri);
    }
}

// ---------------- xproj v3: HMMA GEMM (unchanged, known good) ---------------
#define XROWB 1040u
#define XA_H 0u
#define XA_L 66560u
#define XB_H 133120u
#define XB_L 166400u
#define XP3_SMEM 199680

__global__ __launch_bounds__(128, 1) void xproj_kernel(const float* __restrict__ inputs)
{
    extern __shared__ __align__(16) char xsm[];
    uint32_t s0 = smem_u32(xsm);
    int tid = threadIdx.x, wid = tid >> 5, lane = tid & 31;
    int m0 = blockIdx.x * 64;

    #pragma unroll
    for (int j = 0; j < 16; j++) {
        int u = tid + 128 * j;
        int row = u >> 6, ku = u & 63;
        uint32_t dst = (uint32_t)row * XROWB + (uint32_t)ku * 16u;
        cp16cg(s0 + XB_H + dst, g_Wxh + row * D_ + ku * 8);
        cp16cg(s0 + XB_L + dst, g_Wxl + row * D_ + ku * 8);
    }
    CP_COMMIT();

    #pragma unroll
    for (int j = 0; j < 64; j++) {
        int u = tid + 128 * j;
        int row = u >> 7, f4 = u & 127;
        float4 xv = *(const float4*)(inputs + (size_t)(m0 + row) * D_ + f4 * 4);
        __nv_bfloat16 h0 = __float2bfloat16(xv.x), h1 = __float2bfloat16(xv.y);
        __nv_bfloat16 h2 = __float2bfloat16(xv.z), h3 = __float2bfloat16(xv.w);
        __nv_bfloat16 l0 = __float2bfloat16(xv.x - __bfloat162float(h0));
        __nv_bfloat16 l1 = __float2bfloat16(xv.y - __bfloat162float(h1));
        __nv_bfloat16 l2 = __float2bfloat16(xv.z - __bfloat162float(h2));
        __nv_bfloat16 l3 = __float2bfloat16(xv.w - __bfloat162float(h3));
        uint2 ph, pl;
        ph.x = ((uint32_t)__bfloat16_as_ushort(h1) << 16) | __bfloat16_as_ushort(h0);
        ph.y = ((uint32_t)__bfloat16_as_ushort(h3) << 16) | __bfloat16_as_ushort(h2);
        pl.x = ((uint32_t)__bfloat16_as_ushort(l1) << 16) | __bfloat16_as_ushort(l0);
        pl.y = ((uint32_t)__bfloat16_as_ushort(l3) << 16) | __bfloat16_as_ushort(l2);
        uint32_t off = (uint32_t)row * XROWB + (uint32_t)f4 * 8u;
        *(uint2*)(xsm + XA_H + off) = ph;
        *(uint2*)(xsm + XA_L + off) = pl;
    }
    cp_wait<0>();
    __syncthreads();

    float acc[4][4];
    #pragma unroll
    for (int j = 0; j < 4; j++)
        #pragma unroll
        for (int r = 0; r < 4; r++) acc[j][r] = 0.f;

    uint32_t aOff = (uint32_t)(wid * 16 + (lane & 15)) * XROWB + (uint32_t)((lane >> 4) << 4);
    uint32_t bOff = (uint32_t)(lane & 15) * XROWB + (uint32_t)((lane >> 4) << 4);

    #pragma unroll 4
    for (int k16 = 0; k16 < 32; k16++) {
        uint32_t kb = (uint32_t)k16 * 32u;
        uint32_t ah[4], al[4], bh[2][4], bl[2][4];
        ldm4(s0 + XA_H + aOff + kb, ah);
        ldm4(s0 + XA_L + aOff + kb, al);
        ldm4(s0 + XB_H + bOff + kb, bh[0]);
        ldm4(s0 + XB_H + bOff + 16 * XROWB + kb, bh[1]);
        ldm4(s0 + XB_L + bOff + kb, bl[0]);
        ldm4(s0 + XB_L + bOff + 16 * XROWB + kb, bl[1]);
        #pragma unroll
        for (int j = 0; j < 4; j++) {
            int p = j >> 1, sb = j & 1;
            mma_bf16(acc[j], ah, bh[p][sb], bh[p][2 + sb]);
            mma_bf16(acc[j], ah, bl[p][sb], bl[p][2 + sb]);
            mma_bf16(acc[j], al, bh[p][sb], bh[p][2 + sb]);
        }
    }

    int r0 = m0 + wid * 16 + (lane >> 2);
    #pragma unroll
    for (int j = 0; j < 4; j++) {
        int col = j * 8 + (lane & 3) * 2;
        float b0 = g_bx[col], b1 = g_bx[col + 1];
        *(float2*)(g_Xproj + (size_t)r0 * 32 + col)       = make_float2(acc[j][0] + b0, acc[j][1] + b1);
        *(float2*)(g_Xproj + (size_t)(r0 + 8) * 32 + col) = make_float2(acc[j][2] + b0, acc[j][3] + b1);
    }
}

// ---------------- the persistent recurrence kernel ----------------
// smem: B resident hi/lo; A double buffer; resident pW1/Wh/pb1/pb2/c-tile.
#define BROWB 1040u
#define PB_H 0u
#define PB_L 66560u
#define PA    133120u
#define PABUF 18432u
#define PW1S  169984u
#define WHS   186368u
#define PB1S  194560u
#define PB2S  196608u
#define CS    196864u
#define SMEM_DYN 200960
#define SROWB 144u
#define EPAD 68

__global__ __launch_bounds__(256, 1) void qlstm_kernel(
    const float* __restrict__ pW1, const float* __restrict__ pb1,
    const float* __restrict__ pb2, float* __restrict__ out)
{
    extern __shared__ __align__(16) char dsm[];
    const unsigned FULL = 0xffffffffu;
    uint32_t s0 = smem_u32(dsm);
    int tid = threadIdx.x, wid = tid >> 5, lane = tid & 31;
    int bid = blockIdx.x;
    int nt = bid & 7, mt = bid >> 3;
    int grp = mt;
    int n0 = nt * 64, m0 = mt * 64;

    int sidx = bid * 8 + wid;
    int qb = sidx >> 2, qg = sidx & 3;

    // ---- stage all resident smem (one-time) ----
    #pragma unroll
    for (int j = 0; j < 16; j++) {              // B tiles
        int u = tid + 256 * j;
        int row = u >> 6, ku = u & 63;
        uint32_t dst = (uint32_t)row * BROWB + (uint32_t)ku * 16u;
        cp16cg(s0 + PB_H + dst, g_Bht + (size_t)(n0 + row) * H_ + ku * 8);
        cp16cg(s0 + PB_L + dst, g_Blt + (size_t)(n0 + row) * H_ + ku * 8);
    }
    #pragma unroll
    for (int j = 0; j < 4; j++) {               // pW1 (16KB)
        int u = tid + 256 * j;
        cp16cg(s0 + PW1S + (uint32_t)u * 16u, pW1 + u * 4);
    }
    #pragma unroll
    for (int j = 0; j < 2; j++) {               // Wh tile (8KB)
        int u = tid + 256 * j;
        cp16cg(s0 + WHS + (uint32_t)u * 16u, g_Wh2t + (size_t)n0 * 32 + u * 4);
    }
    if (tid < 128) cp16cg(s0 + PB1S + (uint32_t)tid * 16u, pb1 + tid * 4);
    if (tid < 16)  cp16cg(s0 + PB2S + (uint32_t)tid * 16u, pb2 + n0 + tid * 4);
    CP_COMMIT();

    // zero c tile (smem) and Zpart slices
    float* cs = (float*)(dsm + CS);
    #pragma unroll
    for (int j = 0; j < 4; j++) cs[tid + 256 * j] = 0.f;
    if (tid < 64) {
        #pragma unroll
        for (int p = 0; p < 8; p++)
            __stcg(g_Zpart + p * (B_ * 32) + bid * 64 + tid, 0.f);
    }
    cp_wait<0>();
    groupbar(grp);

    // ---- hoisted constants ----
    const __nv_bfloat16* Ah = g_H1h + (size_t)m0 * H_;
    const __nv_bfloat16* Al = g_H1l + (size_t)m0 * H_;
    int wm = (wid >> 1) * 16, wn = (wid & 1) * 32;
    uint32_t aOff = (uint32_t)(wm + (lane & 15)) * SROWB + (uint32_t)((lane >> 4) << 4);
    uint32_t bOff = (uint32_t)(wn + (lane & 15)) * BROWB + (uint32_t)((lane >> 4) << 4);
    int lrow = tid >> 3, lun = tid & 7;
    int lrow2 = (tid + 256) >> 3, lun2 = (tid + 256) & 7;
    uint32_t ld0 = (uint32_t)lrow * SROWB + (uint32_t)lun * 16u;
    uint32_t ld1 = (uint32_t)lrow2 * SROWB + (uint32_t)lun2 * 16u;

    const float2* ryp = g_ry + qg * 16;
    const float2* prp = g_pr2 + qg * 16;
    const float* pw1s = (const float*)(dsm + PW1S);
    const float* pb1s = (const float*)(dsm + PB1S);
    const float* pb2s = (const float*)(dsm + PB2S);
    const float* whs  = (const float*)(dsm + WHS);

    for (int t = 0; t < T_; t++) {
        // ================= Q phase =================
        {
            float a = 0.f;
            if (lane < 8) {
                float zacc = 0.f;
                const float* zp = g_Zpart + qb * 32 + qg * 8 + lane;
                #pragma unroll
                for (int p = 0; p < 8; p++) zacc += __ldcg(zp + p * (B_ * 32));
                a = zacc + g_Xproj[((t * B_ + qb) * 4 + qg) * 8 + lane];
            }
            float sv, cv;
            __sincosf(a * 0.5f, &sv, &cv);

            float re[8], im[8];
            #pragma unroll
            for (int r = 0; r < 8; r++) { re[r] = 0.f; im[r] = 0.f; }
            if (lane == 0) re[0] = 1.f;

            #pragma unroll
            for (int q = 0; q < 5; q++) {
                int d = 16 >> q;
                float c = __shfl_sync(FULL, cv, q);
                float s = __shfl_sync(FULL, sv, q);
                #pragma unroll
                for (int r = 0; r < 8; r++) {
                    float pr = __shfl_xor_sync(FULL, re[r], d);
                    float pi = __shfl_xor_sync(FULL, im[r], d);
                    re[r] = c * re[r] + s * pi;
                    im[r] = c * im[r] - s * pr;
                }
            }
            #pragma unroll
            for (int q = 5; q < 8; q++) {
                int str = 1 << (7 - q);
                float c = __shfl_sync(FULL, cv, q);
                float s = __shfl_sync(FULL, sv, q);
                #pragma unroll
                for (int a0 = 0; a0 < 8; a0++) {
                    if (a0 & str) continue;
                    int b0 = a0 | str;
                    float tr0 = re[a0], ti0 = im[a0], tr1 = re[b0], ti1 = im[b0];
                    re[a0] = c * tr0 + s * ti1;
                    im[a0] = c * ti0 - s * tr1;
                    re[b0] = c * tr1 + s * ti0;
                    im[b0] = c * ti1 - s * tr0;
                }
            }

            #pragma unroll
            for (int l = 0; l < 2; l++) {
                #pragma unroll
                for (int q = 0; q < 5; q++) {
                    float2 ys = ryp[l * 8 + q];
                    int d = 16 >> q;
                    int hi = (lane >> (4 - q)) & 1;
                    float sgn = hi ? ys.y : -ys.y;
                    #pragma unroll
                    for (int r = 0; r < 8; r++) {
                        float pr = __shfl_xor_sync(FULL, re[r], d);
                        float pi = __shfl_xor_sync(FULL, im[r], d);
                        re[r] = ys.x * re[r] + sgn * pr;
                        im[r] = ys.x * im[r] + sgn * pi;
                    }
                }
                #pragma unroll
                for (int q = 5; q < 8; q++) {
                    float2 ys = ryp[l * 8 + q];
                    int str = 1 << (7 - q);
                    #pragma unroll
                    for (int a0 = 0; a0 < 8; a0++) {
                        if (a0 & str) continue;
                        int b0 = a0 | str;
                        float tr0 = re[a0], ti0 = im[a0], tr1 = re[b0], ti1 = im[b0];
                        re[a0] = ys.x * tr0 - ys.y * tr1;
                        im[a0] = ys.x * ti0 - ys.y * ti1;
                        re[b0] = ys.y * tr0 + ys.x * tr1;
                        im[b0] = ys.y * ti0 + ys.x * ti1;
                    }
                }
                if (l == 0) {
                    float2 pl = g_pl2[(qg * 2 + l) * 32 + lane];
                    #pragma unroll
                    for (int r = 0; r < 8; r++) {
                        float nr = pl.x * re[r] - pl.y * im[r];
                        im[r] = pl.x * im[r] + pl.y * re[r];
                        re[r] = nr;
                    }
                    #pragma unroll
                    for (int r = 0; r < 8; r++) {
                        float2 pq = prp[l * 8 + r];
                        float nr = pq.x * re[r] - pq.y * im[r];
                        im[r] = pq.x * im[r] + pq.y * re[r];
                        re[r] = nr;
                    }
                }
                #pragma unroll
                for (int ct = 0; ct < 4; ct++) {
                    int d = 8 >> ct, cb = 4 - ct;
                    int cbit = (lane >> cb) & 1;
                    #pragma unroll
                    for (int r = 0; r < 8; r++) {
                        float pr = __shfl_xor_sync(FULL, re[r], d);
                        float pi = __shfl_xor_sync(FULL, im[r], d);
                        re[r] = cbit ? pr : re[r];
                        im[r] = cbit ? pi : im[r];
                    }
                }
                {
                    int cbit = lane & 1;
                    #pragma unroll
                    for (int r = 0; r < 4; r++) {
                        float t1 = re[r], t2 = re[r + 4];
                        re[r]     = cbit ? t2 : t1;
                        re[r + 4] = cbit ? t1 : t2;
                        t1 = im[r]; t2 = im[r + 4];
                        im[r]     = cbit ? t2 : t1;
                        im[r + 4] = cbit ? t1 : t2;
                    }
                }
                {
                    float tt;
                    tt = re[4]; re[4] = re[6]; re[6] = tt;
                    tt = re[5]; re[5] = re[7]; re[7] = tt;
                    tt = im[4]; im[4] = im[6]; im[6] = tt;
                    tt = im[5]; im[5] = im[7]; im[7] = tt;
                }
                {
                    float tt;
                    tt = re[2]; re[2] = re[3]; re[3] = tt;
                    tt = re[6]; re[6] = re[7]; re[7] = tt;
                    tt = im[2]; im[2] = im[3]; im[3] = tt;
                    tt = im[6]; im[6] = im[7]; im[7] = tt;
                }
            }

            float p0 = re[0]*re[0]+im[0]*im[0], p1 = re[1]*re[1]+im[1]*im[1];
            float p2 = re[2]*re[2]+im[2]*im[2], p3 = re[3]*re[3]+im[3]*im[3];
            float p4 = re[4]*re[4]+im[4]*im[4], p5 = re[5]*re[5]+im[5]*im[5];
            float p6 = re[6]*re[6]+im[6]*im[6], p7 = re[7]*re[7]+im[7]*im[7];
            float S = p0+p1+p2+p3+p4+p5+p6+p7;
            float z[8];
            #pragma unroll
            for (int q = 0; q < 5; q++)
                z[q] = ((lane >> (4 - q)) & 1) ? -S : S;
            z[5] = (p0+p1+p2+p3) - (p4+p5+p6+p7);
            z[6] = (p0+p1+p4+p5) - (p2+p3+p6+p7);
            z[7] = (p0+p2+p4+p6) - (p1+p3+p5+p7);
            #pragma unroll
            for (int q = 0; q < 8; q++) {
                #pragma unroll
                for (int o = 16; o; o >>= 1) z[q] += __shfl_xor_sync(FULL, z[q], o);
            }

            int row = qb * 4 + qg;
            #pragma unroll
            for (int j = 0; j < 16; j++) {
                int col = j * 32 + lane;
                float a2 = pb1s[col];
                #pragma unroll
                for (int q = 0; q < 8; q++) a2 += z[q] * pw1s[q * H_ + col];
                a2 = fmaxf(a2, 0.f);
                __nv_bfloat16 hi = __float2bfloat16(a2);
                __nv_bfloat16 lo = __float2bfloat16(a2 - __bfloat162float(hi));
                g_H1h[row * H_ + col] = hi;
                g_H1l[row * H_ + col] = lo;
            }
        }
        groupbar(grp);

        // ================= G phase: GEMM + LSTM + h-projection =================
        {
            float* outt = out + (size_t)t * (B_ * H_);
            {
                size_t g0 = (size_t)lrow * H_ + lun * 8;
                size_t g1 = (size_t)lrow2 * H_ + lun2 * 8;
                cp16cg(s0 + PA + ld0, Ah + g0);        cp16cg(s0 + PA + ld1, Ah + g1);
                cp16cg(s0 + PA + 9216 + ld0, Al + g0); cp16cg(s0 + PA + 9216 + ld1, Al + g1);
                CP_COMMIT();
            }
            float acc[4][4];
            #pragma unroll
            for (int j = 0; j < 4; j++)
                #pragma unroll
                for (int r = 0; r < 4; r++) acc[j][r] = 0.f;

            for (int c = 0; c < 8; c++) {
                if (c + 1 < 8) {
                    uint32_t sb = s0 + PA + ((c + 1) & 1) * PABUF;
                    int kb = (c + 1) * 64;
                    size_t g0 = (size_t)lrow * H_ + kb + lun * 8;
                    size_t g1 = (size_t)lrow2 * H_ + kb + lun2 * 8;
                    cp16cg(sb + ld0, Ah + g0);        cp16cg(sb + ld1, Ah + g1);
                    cp16cg(sb + 9216 + ld0, Al + g0); cp16cg(sb + 9216 + ld1, Al + g1);
                    CP_COMMIT();
                    cp_wait<1>();
                } else {
                    cp_wait<0>();
                }
                __syncthreads();

                uint32_t abuf = s0 + PA + (c & 1) * PABUF;
                uint32_t bko = (uint32_t)c * 128u;
                #pragma unroll
                for (int kk = 0; kk < 4; kk++) {
                    uint32_t kb2 = kk * 32;
                    uint32_t ahf[4], alf[4], bhf[2][4], blf[2][4];
                    ldm4(abuf + aOff + kb2, ahf);
                    ldm4(abuf + 9216 + aOff + kb2, alf);
                    ldm4(s0 + PB_H + bOff + bko + kb2, bhf[0]);
                    ldm4(s0 + PB_H + bOff + 16 * BROWB + bko + kb2, bhf[1]);
                    ldm4(s0 + PB_L + bOff + bko + kb2, blf[0]);
                    ldm4(s0 + PB_L + bOff + 16 * BROWB + bko + kb2, blf[1]);
                    #pragma unroll
                    for (int j = 0; j < 4; j++) {
                        int p = j >> 1, sb2 = j & 1;
                        mma_bf16(acc[j], ahf, bhf[p][sb2], bhf[p][2 + sb2]);
                        mma_bf16(acc[j], ahf, blf[p][sb2], blf[p][2 + sb2]);
                        mma_bf16(acc[j], alf, bhf[p][sb2], bhf[p][2 + sb2]);
                    }
                }
                __syncthreads();
            }

            // stage preact (aliases A buffers)
            float* sp = (float*)(dsm + PA);
            int r0 = wm + (lane >> 2);
            #pragma unroll
            for (int j = 0; j < 4; j++) {
                int cc = wn + j * 8 + (lane & 3) * 2;
                sp[r0 * EPAD + cc]           = acc[j][0];
                sp[r0 * EPAD + cc + 1]       = acc[j][1];
                sp[(r0 + 8) * EPAD + cc]     = acc[j][2];
                sp[(r0 + 8) * EPAD + cc + 1] = acc[j][3];
            }
            __syncthreads();

            float* hs = (float*)(dsm + PA + 17408);
            bool last = (t == T_ - 1);
            #pragma unroll
            for (int jj = 0; jj < 4; jj++) {
                int e = tid + 256 * jj;
                int bi = e >> 6, col = e & 63;
                float bias = pb2s[col];
                float fv = sigmoidf_(sp[(bi * 4 + 0) * EPAD + col] + bias);
                float iv = sigmoidf_(sp[(bi * 4 + 1) * EPAD + col] + bias);
                float uv = tanhf   (sp[(bi * 4 + 2) * EPAD + col] + bias);
                float ov = sigmoidf_(sp[(bi * 4 + 3) * EPAD + col] + bias);
                float cc2 = fv * cs[e] + iv * uv;
                float hh2 = ov * tanhf(cc2);
                cs[e] = cc2;
                int batch = mt * 16 + bi;
                int idx = batch * H_ + n0 + col;
                outt[idx] = hh2;
                hs[bi * 64 + col] = hh2;
                if (last) {
                    out[(size_t)T_ * B_ * H_ + idx] = hh2;
                    out[(size_t)T_ * B_ * H_ + B_ * H_ + idx] = cc2;
                }
            }
            __syncthreads();

            #pragma unroll
            for (int jj = 0; jj < 2; jj++) {
                int idx2 = tid + 256 * jj;
                int bi = idx2 >> 5, o = idx2 & 31;
                const float* hh = hs + bi * 64;
                const float* wr = whs + o;
                float sacc = 0.f;
                #pragma unroll 16
                for (int c2 = 0; c2 < 64; c2++) sacc += hh[c2] * wr[c2 * 32];
                __stcg(g_Zpart + nt * (B_ * 32) + (mt * 16 + bi) * 32 + o, sacc);
            }
        }
        if (t < T_ - 1) groupbar(grp);
    }
}

// ---------------- host ----------------
extern "C" void kernel_launch(void* const* d_in, const int* in_sizes, int n_in,
                              void* d_out, int out_size) {
    const float* inputs = (const float*)d_in[0];
    const float* qpf = (const float*)d_in[1];
    const float* qpi = (const float*)d_in[2];
    const float* qpu = (const float*)d_in[3];
    const float* qpo = (const float*)d_in[4];
    const float* Wf  = (const float*)d_in[5];
    const float* bf  = (const float*)d_in[6];
    const float* Wi  = (const float*)d_in[7];
    const float* bi  = (const float*)d_in[8];
    const float* Wu  = (const float*)d_in[9];
    const float* bu  = (const float*)d_in[10];
    const float* Wo  = (const float*)d_in[11];
    const float* bo  = (const float*)d_in[12];
    const float* pW1 = (const float*)d_in[13];
    const float* pb1 = (const float*)d_in[14];
    const float* pW2 = (const float*)d_in[15];
    const float* pb2 = (const float*)d_in[16];
    float* out = (float*)d_out;

    cudaFuncSetAttribute(qlstm_kernel, cudaFuncAttributeMaxDynamicSharedMemorySize, SMEM_DYN);
    cudaFuncSetAttribute(xproj_kernel, cudaFuncAttributeMaxDynamicSharedMemorySize, XP3_SMEM);

    bprep_kernel<<<(H_ * H_) / 256, 256>>>(pW2);
    whprep_kernel<<<(H_ * 32) / 256, 256>>>(Wf, Wi, Wu, Wo, bf, bi, bu, bo);
    tabprep_kernel<<<1, 256>>>(qpf, qpi, qpu, qpo);
    xproj_kernel<<<(T_ * B_) / 64, 128, XP3_SMEM>>>(inputs);
    qlstm_kernel<<<128, 256, SMEM_DYN>>>(pW1, pb1, pb2, out);
}

// round 11
// speedup vs baseline: 3.7326x; 1.1819x over previous
#include <cuda_runtime.h>
#include <cuda_bf16.h>
#include <cuda_fp16.h>
#include <math.h>
#include <stdint.h>

#define T_  64
#define B_  256
#define D_  512
#define H_  512

// ---------------- device scratch (allocation-free rule) ----------------
__device__ __half g_H1f[B_ * 4 * H_];          // fp16(H1), row = b*4 + gate
__device__ __half g_Bhf[H_ * H_];              // hi fp16(pW2^T), [n][k]
__device__ __half g_Blf[H_ * H_];              // lo fp16(pW2^T)
__device__ __nv_bfloat16 g_Wxh[32 * D_];       // hi(Wx^T) [o][k] for xproj
__device__ __nv_bfloat16 g_Wxl[32 * D_];       // lo(Wx^T)
__device__ float g_bx[32];                     // gate bias vector
__device__ float g_Xproj[T_ * B_ * 32];        // x_t @ W + b, [t*B+b][g*8+q]
__device__ float g_Zpart[8 * B_ * 32];         // per-n-tile partial h-projections
__device__ float g_Wh2t[H_ * 32];              // W[D+col][g*8+q] as [col][32]
__device__ float2 g_ry[4 * 2 * 8];             // (cy,sy) per (g,l,q)
__device__ float2 g_pl2[4 * 2 * 32];           // lane-deferred RZ phase per (g,l,lane)
__device__ float2 g_pr2[4 * 2 * 8];            // reg-deferred RZ phase per (g,l,r)
__device__ int g_gcnt[16 * 32];                // padded: one 128B line per group
__device__ volatile int g_ggen[16 * 32];

// ---------------- PTX helpers ----------------
__device__ __forceinline__ uint32_t smem_u32(const void* p) {
    uint32_t a;
    asm("{ .reg .u64 t; cvta.to.shared.u64 t, %1; cvt.u32.u64 %0, t; }" : "=r"(a) : "l"(p));
    return a;
}
__device__ __forceinline__ void cp16cg(uint32_t dst, const void* src) {
    asm volatile("cp.async.cg.shared.global [%0], [%1], 16;" :: "r"(dst), "l"(src) : "memory");
}
#define CP_COMMIT() asm volatile("cp.async.commit_group;" ::: "memory")
template<int N> __device__ __forceinline__ void cp_wait() {
    asm volatile("cp.async.wait_group %0;" :: "n"(N) : "memory");
}
__device__ __forceinline__ void ldm4(uint32_t addr, uint32_t* r) {
    asm volatile("ldmatrix.sync.aligned.m8n8.x4.shared.b16 {%0,%1,%2,%3}, [%4];"
        : "=r"(r[0]), "=r"(r[1]), "=r"(r[2]), "=r"(r[3]) : "r"(addr));
}
__device__ __forceinline__ void mma_bf16(float* c, const uint32_t* a, uint32_t b0, uint32_t b1) {
    asm volatile(
        "mma.sync.aligned.m16n8k16.row.col.f32.bf16.bf16.f32 "
        "{%0,%1,%2,%3}, {%4,%5,%6,%7}, {%8,%9}, {%0,%1,%2,%3};"
        : "+f"(c[0]), "+f"(c[1]), "+f"(c[2]), "+f"(c[3])
        : "r"(a[0]), "r"(a[1]), "r"(a[2]), "r"(a[3]), "r"(b0), "r"(b1));
}
__device__ __forceinline__ void mma_f16(float* c, const uint32_t* a, uint32_t b0, uint32_t b1) {
    asm volatile(
        "mma.sync.aligned.m16n8k16.row.col.f32.f16.f16.f32 "
        "{%0,%1,%2,%3}, {%4,%5,%6,%7}, {%8,%9}, {%0,%1,%2,%3};"
        : "+f"(c[0]), "+f"(c[1]), "+f"(c[2]), "+f"(c[3])
        : "r"(a[0]), "r"(a[1]), "r"(a[2]), "r"(a[3]), "r"(b0), "r"(b1));
}
__device__ __forceinline__ float sigmoidf_(float x) { return 1.f / (1.f + expf(-x)); }

// ---------------- group barrier: 8 blocks (one m-tile group), padded lines ---
__device__ __forceinline__ void groupbar(int grp) {
    __syncthreads();
    if (threadIdx.x == 0) {
        __threadfence();
        int gen = g_ggen[grp * 32];
        if (atomicAdd(&g_gcnt[grp * 32], 1) == 7) {
            g_gcnt[grp * 32] = 0;
            __threadfence();
            g_ggen[grp * 32] = gen + 1;
        } else {
            while (g_ggen[grp * 32] == gen) __nanosleep(20);
        }
    }
    __syncthreads();
}

// ---------------- prep kernels ----------------
// pW2 (K,N) -> transposed fp16 hi/lo [n][k]
__global__ void bprep_kernel(const float* __restrict__ pW2) {
    int i = blockIdx.x * blockDim.x + threadIdx.x;
    int n = i >> 9, k = i & 511;
    float v = pW2[k * H_ + n];
    __half hi = __float2half(v);
    __half lo = __float2half(v - __half2float(hi));
    g_Bhf[i] = hi; g_Blf[i] = lo;
}

__global__ void whprep_kernel(
    const float* __restrict__ Wf, const float* __restrict__ Wi,
    const float* __restrict__ Wu, const float* __restrict__ Wo,
    const float* __restrict__ bf, const float* __restrict__ bi,
    const float* __restrict__ bu, const float* __restrict__ bo)
{
    int i = blockIdx.x * blockDim.x + threadIdx.x;   // 0..16383
    {
        int col = i >> 5, o = i & 31, g = o >> 3, q = o & 7;
        const float* W = (g == 0) ? Wf : (g == 1) ? Wi : (g == 2) ? Wu : Wo;
        g_Wh2t[i] = W[(D_ + col) * 8 + q];
    }
    {
        int o = i >> 9, k = i & 511, g = o >> 3, q = o & 7;
        const float* W = (g == 0) ? Wf : (g == 1) ? Wi : (g == 2) ? Wu : Wo;
        float v = W[k * 8 + q];
        __nv_bfloat16 hi = __float2bfloat16(v);
        __nv_bfloat16 lo = __float2bfloat16(v - __bfloat162float(hi));
        g_Wxh[i] = hi; g_Wxl[i] = lo;
    }
    if (i < 32) {
        int g = i >> 3, q = i & 7;
        const float* bb = (g == 0) ? bf : (g == 1) ? bi : (g == 2) ? bu : bo;
        g_bx[i] = bb[q];
    }
}

__global__ void tabprep_kernel(
    const float* __restrict__ qpf, const float* __restrict__ qpi,
    const float* __restrict__ qpu, const float* __restrict__ qpo)
{
    int i = threadIdx.x;   // 0..255
    const float* qps[4] = {qpf, qpi, qpu, qpo};
    if (i < 64) {
        int g = i >> 4, l = (i >> 3) & 1, q = i & 7;
        const float* qp = qps[g];
        float th = qp[(l * 8 + q) * 3 + 0] * 0.5f;
        g_ry[i] = make_float2(cosf(th), sinf(th));
        int r = q;
        float prr = 1.f, pri = 0.f;
        #pragma unroll
        for (int qq = 5; qq < 8; qq++) {
            float tz = qp[(l * 8 + qq) * 3 + 1] * 0.5f;
            float cz = cosf(tz), sz = sinf(tz);
            float zn = ((r >> (7 - qq)) & 1) ? sz : -sz;
            float nr = prr * cz - pri * zn;
            float ni = prr * zn + pri * cz;
            prr = nr; pri = ni;
        }
        g_pr2[i] = make_float2(prr, pri);
    }
    {
        int g = i >> 6, l = (i >> 5) & 1, ln = i & 31;
        const float* qp = qps[g];
        float prr = 1.f, pri = 0.f;
        #pragma unroll
        for (int q = 0; q < 5; q++) {
            float tz = qp[(l * 8 + q) * 3 + 1] * 0.5f;
            float cz = cosf(tz), sz = sinf(tz);
            float zn = ((ln >> (4 - q)) & 1) ? sz : -sz;
            float nr = prr * cz - pri * zn;
            float ni = prr * zn + pri * cz;
            prr = nr; pri = ni;
        }
        g_pl2[i] = make_float2(prr, pri);
    }
}

// ---------------- xproj v3: HMMA GEMM (unchanged, known good) ---------------
#define XROWB 1040u
#define XA_H 0u
#define XA_L 66560u
#define XB_H 133120u
#define XB_L 166400u
#define XP3_SMEM 199680

__global__ __launch_bounds__(128, 1) void xproj_kernel(const float* __restrict__ inputs)
{
    extern __shared__ __align__(16) char xsm[];
    uint32_t s0 = smem_u32(xsm);
    int tid = threadIdx.x, wid = tid >> 5, lane = tid & 31;
    int m0 = blockIdx.x * 64;

    #pragma unroll
    for (int j = 0; j < 16; j++) {
        int u = tid + 128 * j;
        int row = u >> 6, ku = u & 63;
        uint32_t dst = (uint32_t)row * XROWB + (uint32_t)ku * 16u;
        cp16cg(s0 + XB_H + dst, g_Wxh + row * D_ + ku * 8);
        cp16cg(s0 + XB_L + dst, g_Wxl + row * D_ + ku * 8);
    }
    CP_COMMIT();

    #pragma unroll
    for (int j = 0; j < 64; j++) {
        int u = tid + 128 * j;
        int row = u >> 7, f4 = u & 127;
        float4 xv = *(const float4*)(inputs + (size_t)(m0 + row) * D_ + f4 * 4);
        __nv_bfloat16 h0 = __float2bfloat16(xv.x), h1 = __float2bfloat16(xv.y);
        __nv_bfloat16 h2 = __float2bfloat16(xv.z), h3 = __float2bfloat16(xv.w);
        __nv_bfloat16 l0 = __float2bfloat16(xv.x - __bfloat162float(h0));
        __nv_bfloat16 l1 = __float2bfloat16(xv.y - __bfloat162float(h1));
        __nv_bfloat16 l2 = __float2bfloat16(xv.z - __bfloat162float(h2));
        __nv_bfloat16 l3 = __float2bfloat16(xv.w - __bfloat162float(h3));
        uint2 ph, pl;
        ph.x = ((uint32_t)__bfloat16_as_ushort(h1) << 16) | __bfloat16_as_ushort(h0);
        ph.y = ((uint32_t)__bfloat16_as_ushort(h3) << 16) | __bfloat16_as_ushort(h2);
        pl.x = ((uint32_t)__bfloat16_as_ushort(l1) << 16) | __bfloat16_as_ushort(l0);
        pl.y = ((uint32_t)__bfloat16_as_ushort(l3) << 16) | __bfloat16_as_ushort(l2);
        uint32_t off = (uint32_t)row * XROWB + (uint32_t)f4 * 8u;
        *(uint2*)(xsm + XA_H + off) = ph;
        *(uint2*)(xsm + XA_L + off) = pl;
    }
    cp_wait<0>();
    __syncthreads();

    float acc[4][4];
    #pragma unroll
    for (int j = 0; j < 4; j++)
        #pragma unroll
        for (int r = 0; r < 4; r++) acc[j][r] = 0.f;

    uint32_t aOff = (uint32_t)(wid * 16 + (lane & 15)) * XROWB + (uint32_t)((lane >> 4) << 4);
    uint32_t bOff = (uint32_t)(lane & 15) * XROWB + (uint32_t)((lane >> 4) << 4);

    #pragma unroll 4
    for (int k16 = 0; k16 < 32; k16++) {
        uint32_t kb = (uint32_t)k16 * 32u;
        uint32_t ah[4], al[4], bh[2][4], bl[2][4];
        ldm4(s0 + XA_H + aOff + kb, ah);
        ldm4(s0 + XA_L + aOff + kb, al);
        ldm4(s0 + XB_H + bOff + kb, bh[0]);
        ldm4(s0 + XB_H + bOff + 16 * XROWB + kb, bh[1]);
        ldm4(s0 + XB_L + bOff + kb, bl[0]);
        ldm4(s0 + XB_L + bOff + 16 * XROWB + kb, bl[1]);
        #pragma unroll
        for (int j = 0; j < 4; j++) {
            int p = j >> 1, sb = j & 1;
            mma_bf16(acc[j], ah, bh[p][sb], bh[p][2 + sb]);
            mma_bf16(acc[j], ah, bl[p][sb], bl[p][2 + sb]);
            mma_bf16(acc[j], al, bh[p][sb], bh[p][2 + sb]);
        }
    }

    int r0 = m0 + wid * 16 + (lane >> 2);
    #pragma unroll
    for (int j = 0; j < 4; j++) {
        int col = j * 8 + (lane & 3) * 2;
        float b0 = g_bx[col], b1 = g_bx[col + 1];
        *(float2*)(g_Xproj + (size_t)r0 * 32 + col)       = make_float2(acc[j][0] + b0, acc[j][1] + b1);
        *(float2*)(g_Xproj + (size_t)(r0 + 8) * 32 + col) = make_float2(acc[j][2] + b0, acc[j][3] + b1);
    }
}

// ---------------- the persistent recurrence kernel ----------------
// smem: B resident fp16 hi/lo; A triple buffer (fp16 single); resident tables.
#define BROWB 1040u
#define PB_H  0u
#define PB_L  66560u
#define PA    133120u
#define PABUF 9216u
#define PW1S  160768u
#define WHS   177152u
#define PB1S  185344u
#define PB2S  187392u
#define CS    187648u
#define HSOFF 191744u
#define SMEM_DYN 195840
#define SROWB 144u
#define EPAD 68

__global__ __launch_bounds__(256, 1) void qlstm_kernel(
    const float* __restrict__ pW1, const float* __restrict__ pb1,
    const float* __restrict__ pb2, float* __restrict__ out)
{
    extern __shared__ __align__(16) char dsm[];
    const unsigned FULL = 0xffffffffu;
    uint32_t s0 = smem_u32(dsm);
    int tid = threadIdx.x, wid = tid >> 5, lane = tid & 31;
    int bid = blockIdx.x;
    int nt = bid & 7, mt = bid >> 3;
    int grp = mt;
    int n0 = nt * 64, m0 = mt * 64;

    int sidx = bid * 8 + wid;
    int qb = sidx >> 2, qg = sidx & 3;

    // ---- stage resident smem (one-time) ----
    #pragma unroll
    for (int j = 0; j < 16; j++) {              // B tiles (fp16 hi/lo)
        int u = tid + 256 * j;
        int row = u >> 6, ku = u & 63;
        uint32_t dst = (uint32_t)row * BROWB + (uint32_t)ku * 16u;
        cp16cg(s0 + PB_H + dst, g_Bhf + (size_t)(n0 + row) * H_ + ku * 8);
        cp16cg(s0 + PB_L + dst, g_Blf + (size_t)(n0 + row) * H_ + ku * 8);
    }
    #pragma unroll
    for (int j = 0; j < 4; j++) {               // pW1 (16KB)
        int u = tid + 256 * j;
        cp16cg(s0 + PW1S + (uint32_t)u * 16u, pW1 + u * 4);
    }
    #pragma unroll
    for (int j = 0; j < 2; j++) {               // Wh tile (8KB)
        int u = tid + 256 * j;
        cp16cg(s0 + WHS + (uint32_t)u * 16u, g_Wh2t + (size_t)n0 * 32 + u * 4);
    }
    if (tid < 128) cp16cg(s0 + PB1S + (uint32_t)tid * 16u, pb1 + tid * 4);
    if (tid < 16)  cp16cg(s0 + PB2S + (uint32_t)tid * 16u, pb2 + n0 + tid * 4);
    CP_COMMIT();

    float* cs = (float*)(dsm + CS);
    #pragma unroll
    for (int j = 0; j < 4; j++) cs[tid + 256 * j] = 0.f;
    if (tid < 64) {
        #pragma unroll
        for (int p = 0; p < 8; p++)
            __stcg(g_Zpart + p * (B_ * 32) + bid * 64 + tid, 0.f);
    }
    cp_wait<0>();
    groupbar(grp);

    // ---- hoisted constants ----
    const __half* Af = g_H1f + (size_t)m0 * H_;
    int wm = (wid >> 1) * 16, wn = (wid & 1) * 32;
    uint32_t aOff = (uint32_t)(wm + (lane & 15)) * SROWB + (uint32_t)((lane >> 4) << 4);
    uint32_t bOff = (uint32_t)(wn + (lane & 15)) * BROWB + (uint32_t)((lane >> 4) << 4);
    int lrow = tid >> 3, lun = tid & 7;
    int lrow2 = (tid + 256) >> 3, lun2 = (tid + 256) & 7;
    uint32_t ld0 = (uint32_t)lrow * SROWB + (uint32_t)lun * 16u;
    uint32_t ld1 = (uint32_t)lrow2 * SROWB + (uint32_t)lun2 * 16u;

    const float2* ryp = g_ry + qg * 16;
    const float2* prp = g_pr2 + qg * 16;
    const float* pw1s = (const float*)(dsm + PW1S);
    const float* pb1s = (const float*)(dsm + PB1S);
    const float* pb2s = (const float*)(dsm + PB2S);
    const float* whs  = (const float*)(dsm + WHS);

    for (int t = 0; t < T_; t++) {
        // ================= Q phase =================
        {
            float a = 0.f;
            if (lane < 8) {
                float zacc = 0.f;
                const float* zp = g_Zpart + qb * 32 + qg * 8 + lane;
                #pragma unroll
                for (int p = 0; p < 8; p++) zacc += __ldcg(zp + p * (B_ * 32));
                a = zacc + g_Xproj[((t * B_ + qb) * 4 + qg) * 8 + lane];
            }
            float sv, cv;
            __sincosf(a * 0.5f, &sv, &cv);

            float re[8], im[8];
            #pragma unroll
            for (int r = 0; r < 8; r++) { re[r] = 0.f; im[r] = 0.f; }
            if (lane == 0) re[0] = 1.f;

            #pragma unroll
            for (int q = 0; q < 5; q++) {
                int d = 16 >> q;
                float c = __shfl_sync(FULL, cv, q);
                float s = __shfl_sync(FULL, sv, q);
                #pragma unroll
                for (int r = 0; r < 8; r++) {
                    float pr = __shfl_xor_sync(FULL, re[r], d);
                    float pi = __shfl_xor_sync(FULL, im[r], d);
                    re[r] = c * re[r] + s * pi;
                    im[r] = c * im[r] - s * pr;
                }
            }
            #pragma unroll
            for (int q = 5; q < 8; q++) {
                int str = 1 << (7 - q);
                float c = __shfl_sync(FULL, cv, q);
                float s = __shfl_sync(FULL, sv, q);
                #pragma unroll
                for (int a0 = 0; a0 < 8; a0++) {
                    if (a0 & str) continue;
                    int b0 = a0 | str;
                    float tr0 = re[a0], ti0 = im[a0], tr1 = re[b0], ti1 = im[b0];
                    re[a0] = c * tr0 + s * ti1;
                    im[a0] = c * ti0 - s * tr1;
                    re[b0] = c * tr1 + s * ti0;
                    im[b0] = c * ti1 - s * tr0;
                }
            }

            #pragma unroll
            for (int l = 0; l < 2; l++) {
                #pragma unroll
                for (int q = 0; q < 5; q++) {
                    float2 ys = ryp[l * 8 + q];
                    int d = 16 >> q;
                    int hi = (lane >> (4 - q)) & 1;
                    float sgn = hi ? ys.y : -ys.y;
                    #pragma unroll
                    for (int r = 0; r < 8; r++) {
                        float pr = __shfl_xor_sync(FULL, re[r], d);
                        float pi = __shfl_xor_sync(FULL, im[r], d);
                        re[r] = ys.x * re[r] + sgn * pr;
                        im[r] = ys.x * im[r] + sgn * pi;
                    }
                }
                #pragma unroll
                for (int q = 5; q < 8; q++) {
                    float2 ys = ryp[l * 8 + q];
                    int str = 1 << (7 - q);
                    #pragma unroll
                    for (int a0 = 0; a0 < 8; a0++) {
                        if (a0 & str) continue;
                        int b0 = a0 | str;
                        float tr0 = re[a0], ti0 = im[a0], tr1 = re[b0], ti1 = im[b0];
                        re[a0] = ys.x * tr0 - ys.y * tr1;
                        im[a0] = ys.x * ti0 - ys.y * ti1;
                        re[b0] = ys.y * tr0 + ys.x * tr1;
                        im[b0] = ys.y * ti0 + ys.x * ti1;
                    }
                }
                if (l == 0) {
                    float2 pl = g_pl2[(qg * 2 + l) * 32 + lane];
                    #pragma unroll
                    for (int r = 0; r < 8; r++) {
                        float nr = pl.x * re[r] - pl.y * im[r];
                        im[r] = pl.x * im[r] + pl.y * re[r];
                        re[r] = nr;
                    }
                    #pragma unroll
                    for (int r = 0; r < 8; r++) {
                        float2 pq = prp[l * 8 + r];
                        float nr = pq.x * re[r] - pq.y * im[r];
                        im[r] = pq.x * im[r] + pq.y * re[r];
                        re[r] = nr;
                    }
                }
                #pragma unroll
                for (int ct = 0; ct < 4; ct++) {
                    int d = 8 >> ct, cb = 4 - ct;
                    int cbit = (lane >> cb) & 1;
                    #pragma unroll
                    for (int r = 0; r < 8; r++) {
                        float pr = __shfl_xor_sync(FULL, re[r], d);
                        float pi = __shfl_xor_sync(FULL, im[r], d);
                        re[r] = cbit ? pr : re[r];
                        im[r] = cbit ? pi : im[r];
                    }
                }
                {
                    int cbit = lane & 1;
                    #pragma unroll
                    for (int r = 0; r < 4; r++) {
                        float t1 = re[r], t2 = re[r + 4];
                        re[r]     = cbit ? t2 : t1;
                        re[r + 4] = cbit ? t1 : t2;
                        t1 = im[r]; t2 = im[r + 4];
                        im[r]     = cbit ? t2 : t1;
                        im[r + 4] = cbit ? t1 : t2;
                    }
                }
                {
                    float tt;
                    tt = re[4]; re[4] = re[6]; re[6] = tt;
                    tt = re[5]; re[5] = re[7]; re[7] = tt;
                    tt = im[4]; im[4] = im[6]; im[6] = tt;
                    tt = im[5]; im[5] = im[7]; im[7] = tt;
                }
                {
                    float tt;
                    tt = re[2]; re[2] = re[3]; re[3] = tt;
                    tt = re[6]; re[6] = re[7]; re[7] = tt;
                    tt = im[2]; im[2] = im[3]; im[3] = tt;
                    tt = im[6]; im[6] = im[7]; im[7] = tt;
                }
            }

            float p0 = re[0]*re[0]+im[0]*im[0], p1 = re[1]*re[1]+im[1]*im[1];
            float p2 = re[2]*re[2]+im[2]*im[2], p3 = re[3]*re[3]+im[3]*im[3];
            float p4 = re[4]*re[4]+im[4]*im[4], p5 = re[5]*re[5]+im[5]*im[5];
            float p6 = re[6]*re[6]+im[6]*im[6], p7 = re[7]*re[7]+im[7]*im[7];
            float S = p0+p1+p2+p3+p4+p5+p6+p7;
            float z[8];
            #pragma unroll
            for (int q = 0; q < 5; q++)
                z[q] = ((lane >> (4 - q)) & 1) ? -S : S;
            z[5] = (p0+p1+p2+p3) - (p4+p5+p6+p7);
            z[6] = (p0+p1+p4+p5) - (p2+p3+p6+p7);
            z[7] = (p0+p2+p4+p6) - (p1+p3+p5+p7);
            #pragma unroll
            for (int q = 0; q < 8; q++) {
                #pragma unroll
                for (int o = 16; o; o >>= 1) z[q] += __shfl_xor_sync(FULL, z[q], o);
            }

            int row = qb * 4 + qg;
            #pragma unroll
            for (int j = 0; j < 16; j++) {
                int col = j * 32 + lane;
                float a2 = pb1s[col];
                #pragma unroll
                for (int q = 0; q < 8; q++) a2 += z[q] * pw1s[q * H_ + col];
                a2 = fmaxf(a2, 0.f);
                g_H1f[row * H_ + col] = __float2half(a2);
            }
        }
        groupbar(grp);

        // ================= G phase: GEMM + LSTM + h-projection =================
        {
            float* outt = out + (size_t)t * (B_ * H_);
            // prefetch chunks 0,1
            #pragma unroll
            for (int pc = 0; pc < 2; pc++) {
                uint32_t sb = s0 + PA + pc * PABUF;
                int kb = pc * 64;
                cp16cg(sb + ld0, Af + (size_t)lrow * H_ + kb + lun * 8);
                cp16cg(sb + ld1, Af + (size_t)lrow2 * H_ + kb + lun2 * 8);
                CP_COMMIT();
            }
            float acc[4][4];
            #pragma unroll
            for (int j = 0; j < 4; j++)
                #pragma unroll
                for (int r = 0; r < 4; r++) acc[j][r] = 0.f;

            int bufidx = 0;
            for (int c = 0; c < 8; c++) {
                if (c + 2 < 8) {
                    int pbuf = (bufidx + 2) % 3;
                    uint32_t sb = s0 + PA + pbuf * PABUF;
                    int kb = (c + 2) * 64;
                    cp16cg(sb + ld0, Af + (size_t)lrow * H_ + kb + lun * 8);
                    cp16cg(sb + ld1, Af + (size_t)lrow2 * H_ + kb + lun2 * 8);
                    CP_COMMIT();
                    cp_wait<2>();
                } else if (c + 1 < 8) {
                    cp_wait<1>();
                } else {
                    cp_wait<0>();
                }
                __syncthreads();

                uint32_t abuf = s0 + PA + bufidx * PABUF;
                uint32_t bko = (uint32_t)c * 128u;
                #pragma unroll
                for (int kk = 0; kk < 4; kk++) {
                    uint32_t kb2 = kk * 32;
                    uint32_t af[4], bhf[2][4], blf[2][4];
                    ldm4(abuf + aOff + kb2, af);
                    ldm4(s0 + PB_H + bOff + bko + kb2, bhf[0]);
                    ldm4(s0 + PB_H + bOff + 16 * BROWB + bko + kb2, bhf[1]);
                    ldm4(s0 + PB_L + bOff + bko + kb2, blf[0]);
                    ldm4(s0 + PB_L + bOff + 16 * BROWB + bko + kb2, blf[1]);
                    #pragma unroll
                    for (int j = 0; j < 4; j++) {
                        int p = j >> 1, sb2 = j & 1;
                        mma_f16(acc[j], af, bhf[p][sb2], bhf[p][2 + sb2]);
                        mma_f16(acc[j], af, blf[p][sb2], blf[p][2 + sb2]);
                    }
                }
                __syncthreads();
                bufidx = (bufidx + 1) % 3;
            }

            // stage preact (aliases A buffers)
            float* sp = (float*)(dsm + PA);
            int r0 = wm + (lane >> 2);
            #pragma unroll
            for (int j = 0; j < 4; j++) {
                int cc = wn + j * 8 + (lane & 3) * 2;
                sp[r0 * EPAD + cc]           = acc[j][0];
                sp[r0 * EPAD + cc + 1]       = acc[j][1];
                sp[(r0 + 8) * EPAD + cc]     = acc[j][2];
                sp[(r0 + 8) * EPAD + cc + 1] = acc[j][3];
            }
            __syncthreads();

            float* hs = (float*)(dsm + HSOFF);
            bool last = (t == T_ - 1);
            #pragma unroll
            for (int jj = 0; jj < 4; jj++) {
                int e = tid + 256 * jj;
                int bi = e >> 6, col = e & 63;
                float bias = pb2s[col];
                float fv = sigmoidf_(sp[(bi * 4 + 0) * EPAD + col] + bias);
                float iv = sigmoidf_(sp[(bi * 4 + 1) * EPAD + col] + bias);
                float uv = tanhf   (sp[(bi * 4 + 2) * EPAD + col] + bias);
                float ov = sigmoidf_(sp[(bi * 4 + 3) * EPAD + col] + bias);
                float cc2 = fv * cs[e] + iv * uv;
                float hh2 = ov * tanhf(cc2);
                cs[e] = cc2;
                int batch = mt * 16 + bi;
                int idx = batch * H_ + n0 + col;
                outt[idx] = hh2;
                hs[bi * 64 + col] = hh2;
                if (last) {
                    out[(size_t)T_ * B_ * H_ + idx] = hh2;
                    out[(size_t)T_ * B_ * H_ + B_ * H_ + idx] = cc2;
                }
            }
            __syncthreads();

            #pragma unroll
            for (int jj = 0; jj < 2; jj++) {
                int idx2 = tid + 256 * jj;
                int bi = idx2 >> 5, o = idx2 & 31;
                const float* hh = hs + bi * 64;
                const float* wr = whs + o;
                float sacc = 0.f;
                #pragma unroll 16
                for (int c2 = 0; c2 < 64; c2++) sacc += hh[c2] * wr[c2 * 32];
                __stcg(g_Zpart + nt * (B_ * 32) + (mt * 16 + bi) * 32 + o, sacc);
            }
        }
        if (t < T_ - 1) groupbar(grp);
    }
}

// ---------------- host ----------------
extern "C" void kernel_launch(void* const* d_in, const int* in_sizes, int n_in,
                              void* d_out, int out_size) {
    const float* inputs = (const float*)d_in[0];
    const float* qpf = (const float*)d_in[1];
    const float* qpi = (const float*)d_in[2];
    const float* qpu = (const float*)d_in[3];
    const float* qpo = (const float*)d_in[4];
    const float* Wf  = (const float*)d_in[5];
    const float* bf  = (const float*)d_in[6];
    const float* Wi  = (const float*)d_in[7];
    const float* bi  = (const float*)d_in[8];
    const float* Wu  = (const float*)d_in[9];
    const float* bu  = (const float*)d_in[10];
    const float* Wo  = (const float*)d_in[11];
    const float* bo  = (const float*)d_in[12];
    const float* pW1 = (const float*)d_in[13];
    const float* pb1 = (const float*)d_in[14];
    const float* pW2 = (const float*)d_in[15];
    const float* pb2 = (const float*)d_in[16];
    float* out = (float*)d_out;

    cudaFuncSetAttribute(qlstm_kernel, cudaFuncAttributeMaxDynamicSharedMemorySize, SMEM_DYN);
    cudaFuncSetAttribute(xproj_kernel, cudaFuncAttributeMaxDynamicSharedMemorySize, XP3_SMEM);

    bprep_kernel<<<(H_ * H_) / 256, 256>>>(pW2);
    whprep_kernel<<<(H_ * 32) / 256, 256>>>(Wf, Wi, Wu, Wo, bf, bi, bu, bo);
    tabprep_kernel<<<1, 256>>>(qpf, qpi, qpu, qpo);
    xproj_kernel<<<(T_ * B_) / 64, 128, XP3_SMEM>>>(inputs);
    qlstm_kernel<<<128, 256, SMEM_DYN>>>(pW1, pb1, pb2, out);
}

// round 12
// speedup vs baseline: 4.0491x; 1.0848x over previous
#include <cuda_runtime.h>
#include <cuda_bf16.h>
#include <cuda_fp16.h>
#include <math.h>
#include <stdint.h>

#define T_  64
#define B_  256
#define D_  512
#define H_  512

// ---------------- device scratch (allocation-free rule) ----------------
__device__ __half g_H1f[B_ * 4 * H_];          // fp16(H1), row = b*4 + gate
__device__ __half g_Bf[H_ * H_];               // fp16(pW2^T), [n][k]
__device__ __nv_bfloat16 g_Wxh[32 * D_];       // hi(Wx^T) [o][k] for xproj
__device__ __nv_bfloat16 g_Wxl[32 * D_];       // lo(Wx^T)
__device__ float g_bx[32];                     // gate bias vector
__device__ float g_Xproj[T_ * B_ * 32];        // x_t @ W + b, [t*B+b][g*8+q]
__device__ float g_Zpart[8 * B_ * 32];         // per-n-tile partial h-projections
__device__ float g_Wh2t[H_ * 32];              // W[D+col][g*8+q] as [col][32]
__device__ float2 g_ry[4 * 2 * 8];             // (cy,sy) per (g,l,q)
__device__ float2 g_pl2[4 * 2 * 32];           // lane-deferred RZ phase per (g,l,lane)
__device__ float2 g_pr2[4 * 2 * 8];            // reg-deferred RZ phase per (g,l,r)
__device__ int g_gcnt[16 * 32];                // padded: one 128B line per group
__device__ volatile int g_ggen[16 * 32];

// ---------------- PTX helpers ----------------
__device__ __forceinline__ uint32_t smem_u32(const void* p) {
    uint32_t a;
    asm("{ .reg .u64 t; cvta.to.shared.u64 t, %1; cvt.u32.u64 %0, t; }" : "=r"(a) : "l"(p));
    return a;
}
__device__ __forceinline__ void cp16cg(uint32_t dst, const void* src) {
    asm volatile("cp.async.cg.shared.global [%0], [%1], 16;" :: "r"(dst), "l"(src) : "memory");
}
#define CP_COMMIT() asm volatile("cp.async.commit_group;" ::: "memory")
template<int N> __device__ __forceinline__ void cp_wait() {
    asm volatile("cp.async.wait_group %0;" :: "n"(N) : "memory");
}
__device__ __forceinline__ void ldm4(uint32_t addr, uint32_t* r) {
    asm volatile("ldmatrix.sync.aligned.m8n8.x4.shared.b16 {%0,%1,%2,%3}, [%4];"
        : "=r"(r[0]), "=r"(r[1]), "=r"(r[2]), "=r"(r[3]) : "r"(addr));
}
__device__ __forceinline__ void mma_bf16(float* c, const uint32_t* a, uint32_t b0, uint32_t b1) {
    asm volatile(
        "mma.sync.aligned.m16n8k16.row.col.f32.bf16.bf16.f32 "
        "{%0,%1,%2,%3}, {%4,%5,%6,%7}, {%8,%9}, {%0,%1,%2,%3};"
        : "+f"(c[0]), "+f"(c[1]), "+f"(c[2]), "+f"(c[3])
        : "r"(a[0]), "r"(a[1]), "r"(a[2]), "r"(a[3]), "r"(b0), "r"(b1));
}
__device__ __forceinline__ void mma_f16(float* c, const uint32_t* a, uint32_t b0, uint32_t b1) {
    asm volatile(
        "mma.sync.aligned.m16n8k16.row.col.f32.f16.f16.f32 "
        "{%0,%1,%2,%3}, {%4,%5,%6,%7}, {%8,%9}, {%0,%1,%2,%3};"
        : "+f"(c[0]), "+f"(c[1]), "+f"(c[2]), "+f"(c[3])
        : "r"(a[0]), "r"(a[1]), "r"(a[2]), "r"(a[3]), "r"(b0), "r"(b1));
}
__device__ __forceinline__ float sigmoidf_(float x) { return 1.f / (1.f + expf(-x)); }

// ---------------- group barrier: 8 blocks (one m-tile group), padded lines ---
__device__ __forceinline__ void groupbar(int grp) {
    __syncthreads();
    if (threadIdx.x == 0) {
        __threadfence();
        int gen = g_ggen[grp * 32];
        if (atomicAdd(&g_gcnt[grp * 32], 1) == 7) {
            g_gcnt[grp * 32] = 0;
            __threadfence();
            g_ggen[grp * 32] = gen + 1;
        } else {
            while (g_ggen[grp * 32] == gen) __nanosleep(20);
        }
    }
    __syncthreads();
}

// ---------------- prep kernels ----------------
// pW2 (K,N) -> transposed single fp16 [n][k]
__global__ void bprep_kernel(const float* __restrict__ pW2) {
    int i = blockIdx.x * blockDim.x + threadIdx.x;
    int n = i >> 9, k = i & 511;
    g_Bf[i] = __float2half(pW2[k * H_ + n]);
}

__global__ void whprep_kernel(
    const float* __restrict__ Wf, const float* __restrict__ Wi,
    const float* __restrict__ Wu, const float* __restrict__ Wo,
    const float* __restrict__ bf, const float* __restrict__ bi,
    const float* __restrict__ bu, const float* __restrict__ bo)
{
    int i = blockIdx.x * blockDim.x + threadIdx.x;   // 0..16383
    {
        int col = i >> 5, o = i & 31, g = o >> 3, q = o & 7;
        const float* W = (g == 0) ? Wf : (g == 1) ? Wi : (g == 2) ? Wu : Wo;
        g_Wh2t[i] = W[(D_ + col) * 8 + q];
    }
    {
        int o = i >> 9, k = i & 511, g = o >> 3, q = o & 7;
        const float* W = (g == 0) ? Wf : (g == 1) ? Wi : (g == 2) ? Wu : Wo;
        float v = W[k * 8 + q];
        __nv_bfloat16 hi = __float2bfloat16(v);
        __nv_bfloat16 lo = __float2bfloat16(v - __bfloat162float(hi));
        g_Wxh[i] = hi; g_Wxl[i] = lo;
    }
    if (i < 32) {
        int g = i >> 3, q = i & 7;
        const float* bb = (g == 0) ? bf : (g == 1) ? bi : (g == 2) ? bu : bo;
        g_bx[i] = bb[q];
    }
}

__global__ void tabprep_kernel(
    const float* __restrict__ qpf, const float* __restrict__ qpi,
    const float* __restrict__ qpu, const float* __restrict__ qpo)
{
    int i = threadIdx.x;   // 0..255
    const float* qps[4] = {qpf, qpi, qpu, qpo};
    if (i < 64) {
        int g = i >> 4, l = (i >> 3) & 1, q = i & 7;
        const float* qp = qps[g];
        float th = qp[(l * 8 + q) * 3 + 0] * 0.5f;
        g_ry[i] = make_float2(cosf(th), sinf(th));
        int r = q;
        float prr = 1.f, pri = 0.f;
        #pragma unroll
        for (int qq = 5; qq < 8; qq++) {
            float tz = qp[(l * 8 + qq) * 3 + 1] * 0.5f;
            float cz = cosf(tz), sz = sinf(tz);
            float zn = ((r >> (7 - qq)) & 1) ? sz : -sz;
            float nr = prr * cz - pri * zn;
            float ni = prr * zn + pri * cz;
            prr = nr; pri = ni;
        }
        g_pr2[i] = make_float2(prr, pri);
    }
    {
        int g = i >> 6, l = (i >> 5) & 1, ln = i & 31;
        const float* qp = qps[g];
        float prr = 1.f, pri = 0.f;
        #pragma unroll
        for (int q = 0; q < 5; q++) {
            float tz = qp[(l * 8 + q) * 3 + 1] * 0.5f;
            float cz = cosf(tz), sz = sinf(tz);
            float zn = ((ln >> (4 - q)) & 1) ? sz : -sz;
            float nr = prr * cz - pri * zn;
            float ni = prr * zn + pri * cz;
            prr = nr; pri = ni;
        }
        g_pl2[i] = make_float2(prr, pri);
    }
}

// ---------------- xproj v3: HMMA GEMM (unchanged, known good) ---------------
#define XROWB 1040u
#define XA_H 0u
#define XA_L 66560u
#define XB_H 133120u
#define XB_L 166400u
#define XP3_SMEM 199680

__global__ __launch_bounds__(128, 1) void xproj_kernel(const float* __restrict__ inputs)
{
    extern __shared__ __align__(16) char xsm[];
    uint32_t s0 = smem_u32(xsm);
    int tid = threadIdx.x, wid = tid >> 5, lane = tid & 31;
    int m0 = blockIdx.x * 64;

    #pragma unroll
    for (int j = 0; j < 16; j++) {
        int u = tid + 128 * j;
        int row = u >> 6, ku = u & 63;
        uint32_t dst = (uint32_t)row * XROWB + (uint32_t)ku * 16u;
        cp16cg(s0 + XB_H + dst, g_Wxh + row * D_ + ku * 8);
        cp16cg(s0 + XB_L + dst, g_Wxl + row * D_ + ku * 8);
    }
    CP_COMMIT();

    #pragma unroll
    for (int j = 0; j < 64; j++) {
        int u = tid + 128 * j;
        int row = u >> 7, f4 = u & 127;
        float4 xv = *(const float4*)(inputs + (size_t)(m0 + row) * D_ + f4 * 4);
        __nv_bfloat16 h0 = __float2bfloat16(xv.x), h1 = __float2bfloat16(xv.y);
        __nv_bfloat16 h2 = __float2bfloat16(xv.z), h3 = __float2bfloat16(xv.w);
        __nv_bfloat16 l0 = __float2bfloat16(xv.x - __bfloat162float(h0));
        __nv_bfloat16 l1 = __float2bfloat16(xv.y - __bfloat162float(h1));
        __nv_bfloat16 l2 = __float2bfloat16(xv.z - __bfloat162float(h2));
        __nv_bfloat16 l3 = __float2bfloat16(xv.w - __bfloat162float(h3));
        uint2 ph, pl;
        ph.x = ((uint32_t)__bfloat16_as_ushort(h1) << 16) | __bfloat16_as_ushort(h0);
        ph.y = ((uint32_t)__bfloat16_as_ushort(h3) << 16) | __bfloat16_as_ushort(h2);
        pl.x = ((uint32_t)__bfloat16_as_ushort(l1) << 16) | __bfloat16_as_ushort(l0);
        pl.y = ((uint32_t)__bfloat16_as_ushort(l3) << 16) | __bfloat16_as_ushort(l2);
        uint32_t off = (uint32_t)row * XROWB + (uint32_t)f4 * 8u;
        *(uint2*)(xsm + XA_H + off) = ph;
        *(uint2*)(xsm + XA_L + off) = pl;
    }
    cp_wait<0>();
    __syncthreads();

    float acc[4][4];
    #pragma unroll
    for (int j = 0; j < 4; j++)
        #pragma unroll
        for (int r = 0; r < 4; r++) acc[j][r] = 0.f;

    uint32_t aOff = (uint32_t)(wid * 16 + (lane & 15)) * XROWB + (uint32_t)((lane >> 4) << 4);
    uint32_t bOff = (uint32_t)(lane & 15) * XROWB + (uint32_t)((lane >> 4) << 4);

    #pragma unroll 4
    for (int k16 = 0; k16 < 32; k16++) {
        uint32_t kb = (uint32_t)k16 * 32u;
        uint32_t ah[4], al[4], bh[2][4], bl[2][4];
        ldm4(s0 + XA_H + aOff + kb, ah);
        ldm4(s0 + XA_L + aOff + kb, al);
        ldm4(s0 + XB_H + bOff + kb, bh[0]);
        ldm4(s0 + XB_H + bOff + 16 * XROWB + kb, bh[1]);
        ldm4(s0 + XB_L + bOff + kb, bl[0]);
        ldm4(s0 + XB_L + bOff + 16 * XROWB + kb, bl[1]);
        #pragma unroll
        for (int j = 0; j < 4; j++) {
            int p = j >> 1, sb = j & 1;
            mma_bf16(acc[j], ah, bh[p][sb], bh[p][2 + sb]);
            mma_bf16(acc[j], ah, bl[p][sb], bl[p][2 + sb]);
            mma_bf16(acc[j], al, bh[p][sb], bh[p][2 + sb]);
        }
    }

    int r0 = m0 + wid * 16 + (lane >> 2);
    #pragma unroll
    for (int j = 0; j < 4; j++) {
        int col = j * 8 + (lane & 3) * 2;
        float b0 = g_bx[col], b1 = g_bx[col + 1];
        *(float2*)(g_Xproj + (size_t)r0 * 32 + col)       = make_float2(acc[j][0] + b0, acc[j][1] + b1);
        *(float2*)(g_Xproj + (size_t)(r0 + 8) * 32 + col) = make_float2(acc[j][2] + b0, acc[j][3] + b1);
    }
}

// ---------------- the persistent recurrence kernel ----------------
// smem: B resident fp16 single; A 8 fully-issued chunks; resident tables.
#define BROWB 1040u
#define PB    0u
#define PA    66560u
#define PABUF 9216u
#define PW1S  140288u
#define WHS   156672u
#define PB1S  164864u
#define PB2S  166912u
#define CS    167168u
#define HSOFF 171264u
#define SMEM_DYN 175360
#define SROWB 144u
#define EPAD 68

__global__ __launch_bounds__(256, 1) void qlstm_kernel(
    const float* __restrict__ pW1, const float* __restrict__ pb1,
    const float* __restrict__ pb2, float* __restrict__ out)
{
    extern __shared__ __align__(16) char dsm[];
    const unsigned FULL = 0xffffffffu;
    uint32_t s0 = smem_u32(dsm);
    int tid = threadIdx.x, wid = tid >> 5, lane = tid & 31;
    int bid = blockIdx.x;
    int nt = bid & 7, mt = bid >> 3;
    int grp = mt;
    int n0 = nt * 64, m0 = mt * 64;

    int sidx = bid * 8 + wid;
    int qb = sidx >> 2, qg = sidx & 3;

    // ---- stage resident smem (one-time) ----
    #pragma unroll
    for (int j = 0; j < 16; j++) {              // B tile (single fp16)
        int u = tid + 256 * j;                  // 4096 16B units
        int row = u >> 6, ku = u & 63;
        cp16cg(s0 + PB + (uint32_t)row * BROWB + (uint32_t)ku * 16u,
               g_Bf + (size_t)(n0 + row) * H_ + ku * 8);
    }
    #pragma unroll
    for (int j = 0; j < 4; j++) {               // pW1 (16KB)
        int u = tid + 256 * j;
        cp16cg(s0 + PW1S + (uint32_t)u * 16u, pW1 + u * 4);
    }
    #pragma unroll
    for (int j = 0; j < 2; j++) {               // Wh tile (8KB)
        int u = tid + 256 * j;
        cp16cg(s0 + WHS + (uint32_t)u * 16u, g_Wh2t + (size_t)n0 * 32 + u * 4);
    }
    if (tid < 128) cp16cg(s0 + PB1S + (uint32_t)tid * 16u, pb1 + tid * 4);
    if (tid < 16)  cp16cg(s0 + PB2S + (uint32_t)tid * 16u, pb2 + n0 + tid * 4);
    CP_COMMIT();

    float* cs = (float*)(dsm + CS);
    #pragma unroll
    for (int j = 0; j < 4; j++) cs[tid + 256 * j] = 0.f;
    if (tid < 64) {
        #pragma unroll
        for (int p = 0; p < 8; p++)
            __stcg(g_Zpart + p * (B_ * 32) + bid * 64 + tid, 0.f);
    }
    cp_wait<0>();
    groupbar(grp);

    // ---- hoisted constants ----
    const __half* Af = g_H1f + (size_t)m0 * H_;
    int wm = (wid >> 1) * 16, wn = (wid & 1) * 32;
    uint32_t aOff = (uint32_t)(wm + (lane & 15)) * SROWB + (uint32_t)((lane >> 4) << 4);
    uint32_t bOff = (uint32_t)(wn + (lane & 15)) * BROWB + (uint32_t)((lane >> 4) << 4);
    int lrow = tid >> 3, lun = tid & 7;
    int lrow2 = (tid + 256) >> 3, lun2 = (tid + 256) & 7;
    uint32_t ld0 = (uint32_t)lrow * SROWB + (uint32_t)lun * 16u;
    uint32_t ld1 = (uint32_t)lrow2 * SROWB + (uint32_t)lun2 * 16u;

    const float2* ryp = g_ry + qg * 16;
    const float2* prp = g_pr2 + qg * 16;
    const float* pw1s = (const float*)(dsm + PW1S);
    const float* pb1s = (const float*)(dsm + PB1S);
    const float* pb2s = (const float*)(dsm + PB2S);
    const float* whs  = (const float*)(dsm + WHS);

    for (int t = 0; t < T_; t++) {
        // ================= Q phase =================
        {
            float a = 0.f;
            if (lane < 8) {
                float zacc = 0.f;
                const float* zp = g_Zpart + qb * 32 + qg * 8 + lane;
                #pragma unroll
                for (int p = 0; p < 8; p++) zacc += __ldcg(zp + p * (B_ * 32));
                a = zacc + g_Xproj[((t * B_ + qb) * 4 + qg) * 8 + lane];
            }
            float sv, cv;
            __sincosf(a * 0.5f, &sv, &cv);

            float re[8], im[8];
            #pragma unroll
            for (int r = 0; r < 8; r++) { re[r] = 0.f; im[r] = 0.f; }
            if (lane == 0) re[0] = 1.f;

            #pragma unroll
            for (int q = 0; q < 5; q++) {
                int d = 16 >> q;
                float c = __shfl_sync(FULL, cv, q);
                float s = __shfl_sync(FULL, sv, q);
                #pragma unroll
                for (int r = 0; r < 8; r++) {
                    float pr = __shfl_xor_sync(FULL, re[r], d);
                    float pi = __shfl_xor_sync(FULL, im[r], d);
                    re[r] = c * re[r] + s * pi;
                    im[r] = c * im[r] - s * pr;
                }
            }
            #pragma unroll
            for (int q = 5; q < 8; q++) {
                int str = 1 << (7 - q);
                float c = __shfl_sync(FULL, cv, q);
                float s = __shfl_sync(FULL, sv, q);
                #pragma unroll
                for (int a0 = 0; a0 < 8; a0++) {
                    if (a0 & str) continue;
                    int b0 = a0 | str;
                    float tr0 = re[a0], ti0 = im[a0], tr1 = re[b0], ti1 = im[b0];
                    re[a0] = c * tr0 + s * ti1;
                    im[a0] = c * ti0 - s * tr1;
                    re[b0] = c * tr1 + s * ti0;
                    im[b0] = c * ti1 - s * tr0;
                }
            }

            #pragma unroll
            for (int l = 0; l < 2; l++) {
                #pragma unroll
                for (int q = 0; q < 5; q++) {
                    float2 ys = ryp[l * 8 + q];
                    int d = 16 >> q;
                    int hi = (lane >> (4 - q)) & 1;
                    float sgn = hi ? ys.y : -ys.y;
                    #pragma unroll
                    for (int r = 0; r < 8; r++) {
                        float pr = __shfl_xor_sync(FULL, re[r], d);
                        float pi = __shfl_xor_sync(FULL, im[r], d);
                        re[r] = ys.x * re[r] + sgn * pr;
                        im[r] = ys.x * im[r] + sgn * pi;
                    }
                }
                #pragma unroll
                for (int q = 5; q < 8; q++) {
                    float2 ys = ryp[l * 8 + q];
                    int str = 1 << (7 - q);
                    #pragma unroll
                    for (int a0 = 0; a0 < 8; a0++) {
                        if (a0 & str) continue;
                        int b0 = a0 | str;
                        float tr0 = re[a0], ti0 = im[a0], tr1 = re[b0], ti1 = im[b0];
                        re[a0] = ys.x * tr0 - ys.y * tr1;
                        im[a0] = ys.x * ti0 - ys.y * ti1;
                        re[b0] = ys.y * tr0 + ys.x * tr1;
                        im[b0] = ys.y * ti0 + ys.x * ti1;
                    }
                }
                if (l == 0) {
                    float2 pl = g_pl2[(qg * 2 + l) * 32 + lane];
                    #pragma unroll
                    for (int r = 0; r < 8; r++) {
                        float nr = pl.x * re[r] - pl.y * im[r];
                        im[r] = pl.x * im[r] + pl.y * re[r];
                        re[r] = nr;
                    }
                    #pragma unroll
                    for (int r = 0; r < 8; r++) {
                        float2 pq = prp[l * 8 + r];
                        float nr = pq.x * re[r] - pq.y * im[r];
                        im[r] = pq.x * im[r] + pq.y * re[r];
                        re[r] = nr;
                    }
                }
                #pragma unroll
                for (int ct = 0; ct < 4; ct++) {
                    int d = 8 >> ct, cb = 4 - ct;
                    int cbit = (lane >> cb) & 1;
                    #pragma unroll
                    for (int r = 0; r < 8; r++) {
                        float pr = __shfl_xor_sync(FULL, re[r], d);
                        float pi = __shfl_xor_sync(FULL, im[r], d);
                        re[r] = cbit ? pr : re[r];
                        im[r] = cbit ? pi : im[r];
                    }
                }
                {
                    int cbit = lane & 1;
                    #pragma unroll
                    for (int r = 0; r < 4; r++) {
                        float t1 = re[r], t2 = re[r + 4];
                        re[r]     = cbit ? t2 : t1;
                        re[r + 4] = cbit ? t1 : t2;
                        t1 = im[r]; t2 = im[r + 4];
                        im[r]     = cbit ? t2 : t1;
                        im[r + 4] = cbit ? t1 : t2;
                    }
                }
                {
                    float tt;
                    tt = re[4]; re[4] = re[6]; re[6] = tt;
                    tt = re[5]; re[5] = re[7]; re[7] = tt;
                    tt = im[4]; im[4] = im[6]; im[6] = tt;
                    tt = im[5]; im[5] = im[7]; im[7] = tt;
                }
                {
                    float tt;
                    tt = re[2]; re[2] = re[3]; re[3] = tt;
                    tt = re[6]; re[6] = re[7]; re[7] = tt;
                    tt = im[2]; im[2] = im[3]; im[3] = tt;
                    tt = im[6]; im[6] = im[7]; im[7] = tt;
                }
            }

            float p0 = re[0]*re[0]+im[0]*im[0], p1 = re[1]*re[1]+im[1]*im[1];
            float p2 = re[2]*re[2]+im[2]*im[2], p3 = re[3]*re[3]+im[3]*im[3];
            float p4 = re[4]*re[4]+im[4]*im[4], p5 = re[5]*re[5]+im[5]*im[5];
            float p6 = re[6]*re[6]+im[6]*im[6], p7 = re[7]*re[7]+im[7]*im[7];
            float S = p0+p1+p2+p3+p4+p5+p6+p7;
            float z[8];
            #pragma unroll
            for (int q = 0; q < 5; q++)
                z[q] = ((lane >> (4 - q)) & 1) ? -S : S;
            z[5] = (p0+p1+p2+p3) - (p4+p5+p6+p7);
            z[6] = (p0+p1+p4+p5) - (p2+p3+p6+p7);
            z[7] = (p0+p2+p4+p6) - (p1+p3+p5+p7);
            #pragma unroll
            for (int q = 0; q < 8; q++) {
                #pragma unroll
                for (int o = 16; o; o >>= 1) z[q] += __shfl_xor_sync(FULL, z[q], o);
            }

            int row = qb * 4 + qg;
            #pragma unroll
            for (int j = 0; j < 16; j++) {
                int col = j * 32 + lane;
                float a2 = pb1s[col];
                #pragma unroll
                for (int q = 0; q < 8; q++) a2 += z[q] * pw1s[q * H_ + col];
                a2 = fmaxf(a2, 0.f);
                g_H1f[row * H_ + col] = __float2half(a2);
            }
        }
        groupbar(grp);

        // ================= G phase: GEMM + LSTM + h-projection =================
        {
            float* outt = out + (size_t)t * (B_ * H_);
            // issue all 8 A-chunk loads as separate groups
            #pragma unroll
            for (int c = 0; c < 8; c++) {
                uint32_t sb = s0 + PA + c * PABUF;
                int kb = c * 64;
                cp16cg(sb + ld0, Af + (size_t)lrow * H_ + kb + lun * 8);
                cp16cg(sb + ld1, Af + (size_t)lrow2 * H_ + kb + lun2 * 8);
                CP_COMMIT();
            }
            float acc[4][4];
            #pragma unroll
            for (int j = 0; j < 4; j++)
                #pragma unroll
                for (int r = 0; r < 4; r++) acc[j][r] = 0.f;

            #define GSTEP(CC, NW) { \
                cp_wait<NW>(); \
                __syncthreads(); \
                uint32_t abuf = s0 + PA + (CC) * PABUF; \
                uint32_t bko = (uint32_t)(CC) * 128u; \
                _Pragma("unroll") \
                for (int kk = 0; kk < 4; kk++) { \
                    uint32_t kb2 = kk * 32; \
                    uint32_t af[4], bf2[2][4]; \
                    ldm4(abuf + aOff + kb2, af); \
                    ldm4(s0 + PB + bOff + bko + kb2, bf2[0]); \
                    ldm4(s0 + PB + bOff + 16 * BROWB + bko + kb2, bf2[1]); \
                    _Pragma("unroll") \
                    for (int j = 0; j < 4; j++) { \
                        int p = j >> 1, sb2 = j & 1; \
                        mma_f16(acc[j], af, bf2[p][sb2], bf2[p][2 + sb2]); \
                    } \
                } }
            GSTEP(0, 7) GSTEP(1, 6) GSTEP(2, 5) GSTEP(3, 4)
            GSTEP(4, 3) GSTEP(5, 2) GSTEP(6, 1) GSTEP(7, 0)
            #undef GSTEP
            __syncthreads();   // all A buffers consumed before aliasing as sp

            // stage preact (aliases A chunk buffers 0/1)
            float* sp = (float*)(dsm + PA);
            int r0 = wm + (lane >> 2);
            #pragma unroll
            for (int j = 0; j < 4; j++) {
                int cc = wn + j * 8 + (lane & 3) * 2;
                sp[r0 * EPAD + cc]           = acc[j][0];
                sp[r0 * EPAD + cc + 1]       = acc[j][1];
                sp[(r0 + 8) * EPAD + cc]     = acc[j][2];
                sp[(r0 + 8) * EPAD + cc + 1] = acc[j][3];
            }
            __syncthreads();

            float* hs = (float*)(dsm + HSOFF);
            bool last = (t == T_ - 1);
            #pragma unroll
            for (int jj = 0; jj < 4; jj++) {
                int e = tid + 256 * jj;
                int bi = e >> 6, col = e & 63;
                float bias = pb2s[col];
                float fv = sigmoidf_(sp[(bi * 4 + 0) * EPAD + col] + bias);
                float iv = sigmoidf_(sp[(bi * 4 + 1) * EPAD + col] + bias);
                float uv = tanhf   (sp[(bi * 4 + 2) * EPAD + col] + bias);
                float ov = sigmoidf_(sp[(bi * 4 + 3) * EPAD + col] + bias);
                float cc2 = fv * cs[e] + iv * uv;
                float hh2 = ov * tanhf(cc2);
                cs[e] = cc2;
                int batch = mt * 16 + bi;
                int idx = batch * H_ + n0 + col;
                outt[idx] = hh2;
                hs[bi * 64 + col] = hh2;
                if (last) {
                    out[(size_t)T_ * B_ * H_ + idx] = hh2;
                    out[(size_t)T_ * B_ * H_ + B_ * H_ + idx] = cc2;
                }
            }
            __syncthreads();

            #pragma unroll
            for (int jj = 0; jj < 2; jj++) {
                int idx2 = tid + 256 * jj;
                int bi = idx2 >> 5, o = idx2 & 31;
                const float* hh = hs + bi * 64;
                const float* wr = whs + o;
                float sacc = 0.f;
                #pragma unroll 16
                for (int c2 = 0; c2 < 64; c2++) sacc += hh[c2] * wr[c2 * 32];
                __stcg(g_Zpart + nt * (B_ * 32) + (mt * 16 + bi) * 32 + o, sacc);
            }
        }
        if (t < T_ - 1) groupbar(grp);
    }
}

// ---------------- host ----------------
extern "C" void kernel_launch(void* const* d_in, const int* in_sizes, int n_in,
                              void* d_out, int out_size) {
    const float* inputs = (const float*)d_in[0];
    const float* qpf = (const float*)d_in[1];
    const float* qpi = (const float*)d_in[2];
    const float* qpu = (const float*)d_in[3];
    const float* qpo = (const float*)d_in[4];
    const float* Wf  = (const float*)d_in[5];
    const float* bf  = (const float*)d_in[6];
    const float* Wi  = (const float*)d_in[7];
    const float* bi  = (const float*)d_in[8];
    const float* Wu  = (const float*)d_in[9];
    const float* bu  = (const float*)d_in[10];
    const float* Wo  = (const float*)d_in[11];
    const float* bo  = (const float*)d_in[12];
    const float* pW1 = (const float*)d_in[13];
    const float* pb1 = (const float*)d_in[14];
    const float* pW2 = (const float*)d_in[15];
    const float* pb2 = (const float*)d_in[16];
    float* out = (float*)d_out;

    cudaFuncSetAttribute(qlstm_kernel, cudaFuncAttributeMaxDynamicSharedMemorySize, SMEM_DYN);
    cudaFuncSetAttribute(xproj_kernel, cudaFuncAttributeMaxDynamicSharedMemorySize, XP3_SMEM);

    bprep_kernel<<<(H_ * H_) / 256, 256>>>(pW2);
    whprep_kernel<<<(H_ * 32) / 256, 256>>>(Wf, Wi, Wu, Wo, bf, bi, bu, bo);
    tabprep_kernel<<<1, 256>>>(qpf, qpi, qpu, qpo);
    xproj_kernel<<<(T_ * B_) / 64, 128, XP3_SMEM>>>(inputs);
    qlstm_kernel<<<128, 256, SMEM_DYN>>>(pW1, pb1, pb2, out);
}